// round 2
// baseline (speedup 1.0000x reference)
#include <cuda_runtime.h>
#include <math.h>

#define B_ 16
#define D_ 256
#define M_ 2048
#define N_ 2048
#define SLICES_ 64           // rows-per-slice = M_/SLICES_ = 32
#define ROWS_PER_SLICE_ 32

// ---------------- scratch (static device arrays; no allocation) ----------------
__device__ float g_R[B_ * M_];                 // row scale factors
__device__ float g_C[B_ * N_];                 // col scale factors
__device__ float g_rowtmp[B_ * M_];            // per-row K0 sums (for initial g)
__device__ float g_colpart[B_ * SLICES_ * N_]; // deterministic column partial sums (8MB)
__device__ float g_g[B_];                      // global scalar per batch
__device__ float g_w[B_ * M_];                 // final row sums (weights)
__device__ float g_numer[B_ * M_ * 3];         // matches @ t^T numerators

// ---------------- block reductions (deterministic) ----------------
__device__ __forceinline__ float blockReduceSum(float v) {
    __shared__ float sh[33];
    int lane = threadIdx.x & 31, w = threadIdx.x >> 5;
#pragma unroll
    for (int o = 16; o; o >>= 1) v += __shfl_down_sync(0xffffffffu, v, o);
    if (lane == 0) sh[w] = v;
    __syncthreads();
    if (w == 0) {
        v = (lane < (int)(blockDim.x >> 5)) ? sh[lane] : 0.f;
#pragma unroll
        for (int o = 16; o; o >>= 1) v += __shfl_down_sync(0xffffffffu, v, o);
        if (lane == 0) sh[32] = v;
    }
    __syncthreads();
    float r = sh[32];
    __syncthreads();
    return r;
}

__device__ __forceinline__ float blockReduceMax(float v) {
    __shared__ float shm[33];
    int lane = threadIdx.x & 31, w = threadIdx.x >> 5;
#pragma unroll
    for (int o = 16; o; o >>= 1) v = fmaxf(v, __shfl_down_sync(0xffffffffu, v, o));
    if (lane == 0) shm[w] = v;
    __syncthreads();
    if (w == 0) {
        v = (lane < (int)(blockDim.x >> 5)) ? shm[lane] : -3.4e38f;
#pragma unroll
        for (int o = 16; o; o >>= 1) v = fmaxf(v, __shfl_down_sync(0xffffffffu, v, o));
        if (lane == 0) shm[32] = v;
    }
    __syncthreads();
    float r = shm[32];
    __syncthreads();
    return r;
}

// ---------------- init: C = 1 ----------------
__global__ void init_kernel() {
    int i = blockIdx.x * blockDim.x + threadIdx.x;
    if (i < B_ * N_) g_C[i] = 1.0f;
}

// ---------------- GEMM: scores[b] = se[b]^T @ te[b] / 16  (written into matches region) ----------------
__global__ __launch_bounds__(256) void gemm_kernel(const float* __restrict__ SE,
                                                   const float* __restrict__ TE,
                                                   float* __restrict__ OUT) {
    __shared__ __align__(16) float As[8][128];
    __shared__ __align__(16) float Bs[8][128];
    int b = blockIdx.z;
    int m0 = blockIdx.y * 128, n0 = blockIdx.x * 128;
    const float* A = SE + (size_t)b * D_ * M_;
    const float* Bm = TE + (size_t)b * D_ * N_;
    int tid = threadIdx.x;
    int lrow = tid >> 5, lcol = (tid & 31) << 2;
    int ty = tid >> 4, tx = tid & 15;
    float acc[8][8];
#pragma unroll
    for (int i = 0; i < 8; i++)
#pragma unroll
        for (int j = 0; j < 8; j++) acc[i][j] = 0.f;

    for (int k0 = 0; k0 < D_; k0 += 8) {
        *(float4*)&As[lrow][lcol] = *(const float4*)&A[(size_t)(k0 + lrow) * M_ + m0 + lcol];
        *(float4*)&Bs[lrow][lcol] = *(const float4*)&Bm[(size_t)(k0 + lrow) * N_ + n0 + lcol];
        __syncthreads();
#pragma unroll
        for (int k = 0; k < 8; k++) {
            float a[8], bb[8];
            *(float4*)&a[0] = *(float4*)&As[k][ty * 8];
            *(float4*)&a[4] = *(float4*)&As[k][ty * 8 + 4];
            *(float4*)&bb[0] = *(float4*)&Bs[k][tx * 8];
            *(float4*)&bb[4] = *(float4*)&Bs[k][tx * 8 + 4];
#pragma unroll
            for (int i = 0; i < 8; i++)
#pragma unroll
                for (int j = 0; j < 8; j++) acc[i][j] += a[i] * bb[j];
        }
        __syncthreads();
    }
    float* O = OUT + (size_t)b * M_ * N_;
#pragma unroll
    for (int i = 0; i < 8; i++) {
        size_t ro = (size_t)(m0 + ty * 8 + i) * N_ + n0 + tx * 8;
#pragma unroll
        for (int j = 0; j < 8; j += 4) {
            float4 v;
            v.x = acc[i][j] * 0.0625f;
            v.y = acc[i][j + 1] * 0.0625f;
            v.z = acc[i][j + 2] * 0.0625f;
            v.w = acc[i][j + 3] * 0.0625f;
            *(float4*)&O[ro + j] = v;
        }
    }
}

// ---------------- softmax: K0 = exp(log_softmax(scores)/rho) in place; row sums; R=1 ----------------
__global__ __launch_bounds__(256) void softmax_kernel(float* __restrict__ K,
                                                      const float* __restrict__ rho_p) {
    int row = blockIdx.x;  // 0..B*M-1
    float* P = K + (size_t)row * N_;
    int tid = threadIdx.x;
    float v[8];
#pragma unroll
    for (int k = 0; k < 8; k++) v[k] = P[tid + k * 256];
    float mx = -3.4e38f;
#pragma unroll
    for (int k = 0; k < 8; k++) mx = fmaxf(mx, v[k]);
    mx = blockReduceMax(mx);
    float z = 0.f;
#pragma unroll
    for (int k = 0; k < 8; k++) z += __expf(v[k] - mx);
    z = blockReduceSum(z);
    float rho = fmaxf(rho_p[0], 1e-8f);
    float invrho = 1.0f / rho;
    float lz = __logf(z);
    float rs = 0.f;
#pragma unroll
    for (int k = 0; k < 8; k++) {
        float e = __expf((v[k] - mx - lz) * invrho);
        P[tid + k * 256] = e;
        rs += e;
    }
    rs = blockReduceSum(rs);
    if (tid == 0) {
        g_rowtmp[row] = rs;
        g_R[row] = 1.0f;
    }
}

// ---------------- initial global normalization: g = m / clip(sum K0, EPS), m = 1 ----------------
__global__ __launch_bounds__(256) void initg_kernel() {
    int b = blockIdx.x;
    float s = 0.f;
    for (int i = threadIdx.x; i < M_; i += 256) s += g_rowtmp[b * M_ + i];
    s = blockReduceSum(s);
    if (threadIdx.x == 0) g_g[b] = 1.0f / fmaxf(s, 1e-8f);
}

// ---------------- iteration: row scaling r_i = min(a/rowsum, 1) ----------------
__global__ __launch_bounds__(256) void rowscale_kernel(const float* __restrict__ K) {
    int row = blockIdx.x;
    int b = row >> 11;
    const float* P = K + (size_t)row * N_;
    const float* C = g_C + (b << 11);
    int tid = threadIdx.x;
    float d = 0.f;
#pragma unroll
    for (int k = 0; k < 8; k++) {
        int j = tid + k * 256;
        d += P[j] * C[j];
    }
    d = blockReduceSum(d);
    if (tid == 0) {
        float rowsum = g_g[b] * g_R[row] * d;
        float r = fminf((1.0f / 2048.0f) / fmaxf(rowsum, 1e-8f), 1.0f);
        g_R[row] *= r;
    }
}

// ---------------- iteration: column partial sums sum_i K0_ij * R_i (deterministic slices) ----------------
__global__ __launch_bounds__(256) void colsum_kernel(const float* __restrict__ K) {
    int b = blockIdx.x >> 6;
    int slice = blockIdx.x & 63;
    int i0 = slice * ROWS_PER_SLICE_;
    int tid = threadIdx.x;
    const float* base = K + ((size_t)(b << 11) + i0) * N_;
    float acc[8] = {0, 0, 0, 0, 0, 0, 0, 0};
    for (int r = 0; r < ROWS_PER_SLICE_; r++) {
        float Rv = g_R[(b << 11) + i0 + r];
        const float* P = base + (size_t)r * N_;
#pragma unroll
        for (int k = 0; k < 8; k++) acc[k] += P[tid + k * 256] * Rv;
    }
    float* out = g_colpart + (size_t)blockIdx.x * N_;
#pragma unroll
    for (int k = 0; k < 8; k++) out[tid + k * 256] = acc[k];
}

// ---------------- iteration: col scaling + global renorm ----------------
__global__ __launch_bounds__(256) void colscale_kernel() {
    int b = blockIdx.x;
    int tid = threadIdx.x;
    float g = g_g[b];
    float tp = 0.f;
#pragma unroll
    for (int k = 0; k < 8; k++) {
        int j = tid + k * 256;
        float acc = 0.f;
        const float* cp = g_colpart + (size_t)(b << 6) * N_ + j;
        for (int s = 0; s < SLICES_; s++) acc += cp[(size_t)s * N_];
        int cj = (b << 11) + j;
        float colsum = g * g_C[cj] * acc;
        float c = fminf((1.0f / 2048.0f) / fmaxf(colsum, 1e-8f), 1.0f);
        g_C[cj] *= c;
        tp += colsum * c;
    }
    tp = blockReduceSum(tp);
    if (tid == 0) g_g[b] = g * (1.0f / fmaxf(tp, 1e-8f));
}

// ---------------- final: matches = K0*g*R*C written in place; rowsum + matches@t^T ----------------
__global__ __launch_bounds__(256) void final_kernel(float* __restrict__ K,
                                                    const float* __restrict__ tgt) {
    int row = blockIdx.x;
    int b = row >> 11;
    int tid = threadIdx.x;
    float* P = K + (size_t)row * N_;
    const float* C = g_C + (b << 11);
    const float* t0 = tgt + (size_t)b * 3 * N_;
    const float* t1 = t0 + N_;
    const float* t2 = t0 + 2 * N_;
    float gR = g_g[b] * g_R[row];
    float s = 0.f, sx = 0.f, sy = 0.f, sz = 0.f;
#pragma unroll
    for (int k = 0; k < 8; k++) {
        int j = tid + k * 256;
        float val = P[j] * gR * C[j];
        P[j] = val;
        s += val;
        sx += val * t0[j];
        sy += val * t1[j];
        sz += val * t2[j];
    }
    s = blockReduceSum(s);
    sx = blockReduceSum(sx);
    sy = blockReduceSum(sy);
    sz = blockReduceSum(sz);
    if (tid == 0) {
        g_w[row] = s;
        g_numer[row * 3 + 0] = sx;
        g_numer[row * 3 + 1] = sy;
        g_numer[row * 3 + 2] = sz;
    }
}

// ---------------- rigid transform: weighted Kabsch + 3x3 SVD (fp64), per batch ----------------
__global__ __launch_bounds__(256) void rigid_kernel(const float* __restrict__ src,
                                                    float* __restrict__ out) {
    int b = blockIdx.x;
    int tid = threadIdx.x;
    const float* s0 = src + (size_t)b * 3 * M_;
    const float* s1 = s0 + M_;
    const float* s2 = s0 + 2 * M_;
    double acc[16];
#pragma unroll
    for (int q = 0; q < 16; q++) acc[q] = 0.0;
    for (int i = tid; i < M_; i += 256) {
        int row = (b << 11) + i;
        double w = (double)g_w[row];
        double dn = w + 1e-6;
        double bx = (double)g_numer[row * 3 + 0] / dn;
        double by = (double)g_numer[row * 3 + 1] / dn;
        double bz = (double)g_numer[row * 3 + 2] / dn;
        double ax = (double)s0[i], ay = (double)s1[i], az = (double)s2[i];
        acc[0] += w;
        acc[1] += w * ax; acc[2] += w * ay; acc[3] += w * az;
        acc[4] += w * bx; acc[5] += w * by; acc[6] += w * bz;
        acc[7]  += w * ax * bx; acc[8]  += w * ax * by; acc[9]  += w * ax * bz;
        acc[10] += w * ay * bx; acc[11] += w * ay * by; acc[12] += w * ay * bz;
        acc[13] += w * az * bx; acc[14] += w * az * by; acc[15] += w * az * bz;
    }
    __shared__ double sh[256];
    __shared__ double res[16];
    for (int q = 0; q < 16; q++) {
        sh[tid] = acc[q];
        __syncthreads();
        for (int off = 128; off > 0; off >>= 1) {
            if (tid < off) sh[tid] += sh[tid + off];
            __syncthreads();
        }
        if (tid == 0) res[q] = sh[0];
        __syncthreads();
    }
    if (tid != 0) return;

    double W2 = res[0] + 1e-6;
    double ca[3], cb[3];
#pragma unroll
    for (int i = 0; i < 3; i++) {
        ca[i] = res[1 + i] / W2;
        cb[i] = res[4 + i] / W2;
    }
    double sfac = 2.0 - res[0] / W2;
    double Cv[3][3];
#pragma unroll
    for (int i = 0; i < 3; i++)
#pragma unroll
        for (int j = 0; j < 3; j++)
            Cv[i][j] = res[7 + i * 3 + j] / W2 - sfac * ca[i] * cb[j];

    // A = Cv^T Cv, Jacobi eigendecomposition -> V (right singular vectors)
    double A[3][3];
#pragma unroll
    for (int i = 0; i < 3; i++)
#pragma unroll
        for (int j = 0; j < 3; j++)
            A[i][j] = Cv[0][i] * Cv[0][j] + Cv[1][i] * Cv[1][j] + Cv[2][i] * Cv[2][j];
    double V[3][3] = {{1, 0, 0}, {0, 1, 0}, {0, 0, 1}};
    const int PP[3] = {0, 0, 1}, QQ[3] = {1, 2, 2};
    for (int sweep = 0; sweep < 30; sweep++) {
        double off = fabs(A[0][1]) + fabs(A[0][2]) + fabs(A[1][2]);
        if (off < 1e-28) break;
        for (int r = 0; r < 3; r++) {
            int p = PP[r], q = QQ[r];
            double apq = A[p][q];
            if (apq == 0.0) continue;
            double theta = (A[q][q] - A[p][p]) / (2.0 * apq);
            double t = ((theta >= 0.0) ? 1.0 : -1.0) / (fabs(theta) + sqrt(1.0 + theta * theta));
            double c = 1.0 / sqrt(1.0 + t * t);
            double s = t * c;
            for (int k = 0; k < 3; k++) {
                double akp = A[k][p], akq = A[k][q];
                A[k][p] = c * akp - s * akq;
                A[k][q] = s * akp + c * akq;
            }
            for (int k = 0; k < 3; k++) {
                double apk = A[p][k], aqk = A[q][k];
                A[p][k] = c * apk - s * aqk;
                A[q][k] = s * apk + c * aqk;
            }
            for (int k = 0; k < 3; k++) {
                double vkp = V[k][p], vkq = V[k][q];
                V[k][p] = c * vkp - s * vkq;
                V[k][q] = s * vkp + c * vkq;
            }
        }
    }
    double d[3] = {A[0][0], A[1][1], A[2][2]};
    // sort eigenpairs descending (swap V columns)
    for (int i = 0; i < 2; i++)
        for (int j = i + 1; j < 3; j++)
            if (d[j] > d[i]) {
                double tmp = d[i]; d[i] = d[j]; d[j] = tmp;
                for (int k = 0; k < 3; k++) {
                    double tv = V[k][i]; V[k][i] = V[k][j]; V[k][j] = tv;
                }
            }
    // U columns = Cv * v_k normalized
    double U[3][3];
    double nrm[3];
#pragma unroll
    for (int k = 0; k < 3; k++) {
        double u0 = Cv[0][0] * V[0][k] + Cv[0][1] * V[1][k] + Cv[0][2] * V[2][k];
        double u1 = Cv[1][0] * V[0][k] + Cv[1][1] * V[1][k] + Cv[1][2] * V[2][k];
        double u2 = Cv[2][0] * V[0][k] + Cv[2][1] * V[1][k] + Cv[2][2] * V[2][k];
        double n = sqrt(u0 * u0 + u1 * u1 + u2 * u2);
        nrm[k] = n;
        if (n > 1e-30) {
            U[0][k] = u0 / n; U[1][k] = u1 / n; U[2][k] = u2 / n;
        } else {
            U[0][k] = 0.0; U[1][k] = 0.0; U[2][k] = 0.0;
        }
    }
    if (nrm[2] <= 1e-12 * fmax(nrm[0], 1e-30)) {
        double cx = U[1][0] * U[2][1] - U[2][0] * U[1][1];
        double cy = U[2][0] * U[0][1] - U[0][0] * U[2][1];
        double cz = U[0][0] * U[1][1] - U[1][0] * U[0][1];
        double n = sqrt(cx * cx + cy * cy + cz * cz);
        if (n > 1e-30) { U[0][2] = cx / n; U[1][2] = cy / n; U[2][2] = cz / n; }
    }
    // rot = V U^T (with det fix: negate V[:,2] if det <= 0)
    double R[3][3];
#pragma unroll
    for (int i = 0; i < 3; i++)
#pragma unroll
        for (int j = 0; j < 3; j++)
            R[i][j] = V[i][0] * U[j][0] + V[i][1] * U[j][1] + V[i][2] * U[j][2];
    double det = R[0][0] * (R[1][1] * R[2][2] - R[1][2] * R[2][1])
               - R[0][1] * (R[1][0] * R[2][2] - R[1][2] * R[2][0])
               + R[0][2] * (R[1][0] * R[2][1] - R[1][1] * R[2][0]);
    if (!(det > 0.0)) {
#pragma unroll
        for (int i = 0; i < 3; i++)
#pragma unroll
            for (int j = 0; j < 3; j++)
                R[i][j] -= 2.0 * V[i][2] * U[j][2];
    }
    double tr[3];
#pragma unroll
    for (int i = 0; i < 3; i++)
        tr[i] = cb[i] - (R[i][0] * ca[0] + R[i][1] * ca[1] + R[i][2] * ca[2]);

    // outputs: R at out[b*9], t at out[144 + b*3]
#pragma unroll
    for (int i = 0; i < 3; i++)
#pragma unroll
        for (int j = 0; j < 3; j++)
            out[b * 9 + i * 3 + j] = (float)R[i][j];
#pragma unroll
    for (int i = 0; i < 3; i++) out[144 + b * 3 + i] = (float)tr[i];
}

// ---------------- launch ----------------
extern "C" void kernel_launch(void* const* d_in, const int* in_sizes, int n_in,
                              void* d_out, int out_size) {
    (void)in_sizes; (void)n_in; (void)out_size;
    const float* se  = (const float*)d_in[0];
    const float* te  = (const float*)d_in[1];
    const float* src = (const float*)d_in[2];
    const float* tgt = (const float*)d_in[3];
    const float* rho = (const float*)d_in[4];
    float* out = (float*)d_out;
    float* Kmat = out + 192;  // matches region doubles as K0 scratch

    init_kernel<<<(B_ * N_ + 255) / 256, 256>>>();
    gemm_kernel<<<dim3(N_ / 128, M_ / 128, B_), 256>>>(se, te, Kmat);
    softmax_kernel<<<B_ * M_, 256>>>(Kmat, rho);
    initg_kernel<<<B_, 256>>>();
    for (int it = 0; it < 5; it++) {
        rowscale_kernel<<<B_ * M_, 256>>>(Kmat);
        colsum_kernel<<<B_ * SLICES_, 256>>>(Kmat);
        colscale_kernel<<<B_, 256>>>();
    }
    final_kernel<<<B_ * M_, 256>>>(Kmat, tgt);
    rigid_kernel<<<B_, 256>>>(src, out);
}

// round 4
// speedup vs baseline: 1.3294x; 1.3294x over previous
#include <cuda_runtime.h>
#include <cuda_bf16.h>
#include <math.h>
#include <stdint.h>

#define B_ 16
#define D_ 256
#define M_ 2048
#define N_ 2048
#define SLICES_ 64
#define ROWS_PER_SLICE_ 32

// ---------------- scratch (static device arrays; no allocation) ----------------
__device__ float g_R[B_ * M_];
__device__ float g_C[B_ * N_];
__device__ float g_rowtmp[B_ * M_];
__device__ float g_colpart[B_ * SLICES_ * N_];
__device__ float g_g[B_];
__device__ float g_w[B_ * M_];
__device__ float g_numer[B_ * M_ * 3];
// bf16 split operands, K-major (B, M/N, D)
__device__ __nv_bfloat16 g_AH[B_ * M_ * D_];
__device__ __nv_bfloat16 g_AL[B_ * M_ * D_];
__device__ __nv_bfloat16 g_BH[B_ * N_ * D_];
__device__ __nv_bfloat16 g_BL[B_ * N_ * D_];

// ---------------- helpers ----------------
__device__ __forceinline__ uint32_t smem_u32(const void* p) {
    uint32_t a;
    asm("{ .reg .u64 t; cvta.to.shared.u64 t, %1; cvt.u32.u64 %0, t; }" : "=r"(a) : "l"(p));
    return a;
}

#define LDSM_X4(r0, r1, r2, r3, addr) \
    asm volatile("ldmatrix.sync.aligned.m8n8.x4.shared.b16 {%0,%1,%2,%3}, [%4];" \
                 : "=r"(r0), "=r"(r1), "=r"(r2), "=r"(r3) : "r"(addr))

#define MMA16816(d, a, bq) \
    asm volatile( \
        "mma.sync.aligned.m16n8k16.row.col.f32.bf16.bf16.f32 " \
        "{%0,%1,%2,%3}, {%4,%5,%6,%7}, {%8,%9}, {%0,%1,%2,%3};" \
        : "+f"((d)[0]), "+f"((d)[1]), "+f"((d)[2]), "+f"((d)[3]) \
        : "r"((a)[0]), "r"((a)[1]), "r"((a)[2]), "r"((a)[3]), \
          "r"((bq)[0]), "r"((bq)[1]))

#define CP_ASYNC16(sa, ga) \
    asm volatile("cp.async.cg.shared.global [%0], [%1], 16;" :: "r"(sa), "l"(ga))

// ---------------- block reductions ----------------
__device__ __forceinline__ float blockReduceSum(float v) {
    __shared__ float sh[33];
    int lane = threadIdx.x & 31, w = threadIdx.x >> 5;
#pragma unroll
    for (int o = 16; o; o >>= 1) v += __shfl_down_sync(0xffffffffu, v, o);
    if (lane == 0) sh[w] = v;
    __syncthreads();
    if (w == 0) {
        v = (lane < (int)(blockDim.x >> 5)) ? sh[lane] : 0.f;
#pragma unroll
        for (int o = 16; o; o >>= 1) v += __shfl_down_sync(0xffffffffu, v, o);
        if (lane == 0) sh[32] = v;
    }
    __syncthreads();
    float r = sh[32];
    __syncthreads();
    return r;
}

__device__ __forceinline__ float blockReduceMax(float v) {
    __shared__ float shm[33];
    int lane = threadIdx.x & 31, w = threadIdx.x >> 5;
#pragma unroll
    for (int o = 16; o; o >>= 1) v = fmaxf(v, __shfl_down_sync(0xffffffffu, v, o));
    if (lane == 0) shm[w] = v;
    __syncthreads();
    if (w == 0) {
        v = (lane < (int)(blockDim.x >> 5)) ? shm[lane] : -3.4e38f;
#pragma unroll
        for (int o = 16; o; o >>= 1) v = fmaxf(v, __shfl_down_sync(0xffffffffu, v, o));
        if (lane == 0) shm[32] = v;
    }
    __syncthreads();
    float r = shm[32];
    __syncthreads();
    return r;
}

// ---------------- init: C = 1 ----------------
__global__ void init_kernel() {
    int i = blockIdx.x * blockDim.x + threadIdx.x;
    if (i < B_ * N_) g_C[i] = 1.0f;
}

// ---------------- transpose + bf16 hi/lo split: X(B,D,M) -> H/L (B,M,D) ----------------
__global__ __launch_bounds__(256) void split_transpose_kernel(const float* __restrict__ X,
                                                              __nv_bfloat16* __restrict__ H,
                                                              __nv_bfloat16* __restrict__ L) {
    __shared__ float t[32][33];
    int b = blockIdx.z;
    int m0 = blockIdx.x * 32, d0 = blockIdx.y * 32;
    const float* Xb = X + (size_t)b * D_ * M_;
    int tx = threadIdx.x & 31, ty = threadIdx.x >> 5;  // 32x8
#pragma unroll
    for (int i = 0; i < 4; i++) {
        int d = d0 + ty + i * 8;
        t[ty + i * 8][tx] = Xb[(size_t)d * M_ + m0 + tx];
    }
    __syncthreads();
#pragma unroll
    for (int i = 0; i < 4; i++) {
        int m = m0 + ty + i * 8;
        float v = t[tx][ty + i * 8];
        __nv_bfloat16 h = __float2bfloat16(v);
        __nv_bfloat16 l = __float2bfloat16(v - __bfloat162float(h));
        size_t o = ((size_t)b * M_ + m) * D_ + d0 + tx;
        H[o] = h;
        L[o] = l;
    }
}

// ---------------- HMMA GEMM: scores = (A@B^T)/16, bf16 hi/lo split, fp32 accum ----------------
// CTA tile 128x128, 8 warps (2x4), warp tile 64x32. K staged in chunks of 32.
#define SMS_ 40  // padded smem row stride in bf16 elems (80B -> conflict-free ldmatrix)

__global__ __launch_bounds__(256) void gemm_mma_kernel(float* __restrict__ OUT) {
    __shared__ __align__(16) __nv_bfloat16 sm[4 * 128 * SMS_];
    __nv_bfloat16* sAh = sm;
    __nv_bfloat16* sAl = sm + 128 * SMS_;
    __nv_bfloat16* sBh = sm + 2 * 128 * SMS_;
    __nv_bfloat16* sBl = sm + 3 * 128 * SMS_;

    int tid = threadIdx.x, wid = tid >> 5, lane = tid & 31;
    int b = blockIdx.z, m0 = blockIdx.y * 128, n0 = blockIdx.x * 128;
    int wr = wid >> 2, wc = wid & 3;

    const __nv_bfloat16* Ah = g_AH + ((size_t)b * M_ + m0) * D_;
    const __nv_bfloat16* Al = g_AL + ((size_t)b * M_ + m0) * D_;
    const __nv_bfloat16* Bh = g_BH + ((size_t)b * N_ + n0) * D_;
    const __nv_bfloat16* Bl = g_BL + ((size_t)b * N_ + n0) * D_;

    float acc[4][4][4];
#pragma unroll
    for (int mi = 0; mi < 4; mi++)
#pragma unroll
        for (int ni = 0; ni < 4; ni++)
#pragma unroll
            for (int r = 0; r < 4; r++) acc[mi][ni][r] = 0.f;

    // per-thread cp.async indices: idx = tid*2+i over 512 16B-vectors per matrix
    int i0 = tid * 2, i1 = tid * 2 + 1;
    int r0_ = i0 >> 2, s0_ = i0 & 3;
    int r1_ = i1 >> 2, s1_ = i1 & 3;

    uint32_t sAh_u = smem_u32(sAh), sAl_u = smem_u32(sAl);
    uint32_t sBh_u = smem_u32(sBh), sBl_u = smem_u32(sBl);

    // ldmatrix lane addressing (element offsets within a tile)
    int a_row = (lane & 15), a_colh = (lane >> 4) * 8;       // A frag
    int b_tile = lane >> 3, b_r8 = lane & 7;
    int b_n = ((b_tile >> 1) * 8) + b_r8;                    // B frag n offset
    int b_k = (b_tile & 1) * 8;                              // B frag k offset

    for (int c = 0; c < 8; c++) {
        // ---- stage K-chunk of 32 into smem via cp.async ----
        {
            uint32_t d00 = (uint32_t)(r0_ * SMS_ + s0_ * 8) * 2;
            uint32_t d01 = (uint32_t)(r1_ * SMS_ + s1_ * 8) * 2;
            size_t g00 = (size_t)r0_ * D_ + c * 32 + s0_ * 8;
            size_t g01 = (size_t)r1_ * D_ + c * 32 + s1_ * 8;
            CP_ASYNC16(sAh_u + d00, Ah + g00);
            CP_ASYNC16(sAh_u + d01, Ah + g01);
            CP_ASYNC16(sAl_u + d00, Al + g00);
            CP_ASYNC16(sAl_u + d01, Al + g01);
            CP_ASYNC16(sBh_u + d00, Bh + g00);
            CP_ASYNC16(sBh_u + d01, Bh + g01);
            CP_ASYNC16(sBl_u + d00, Bl + g00);
            CP_ASYNC16(sBl_u + d01, Bl + g01);
        }
        asm volatile("cp.async.commit_group;" ::: "memory");
        asm volatile("cp.async.wait_group 0;" ::: "memory");
        __syncthreads();

#pragma unroll
        for (int ks = 0; ks < 2; ks++) {
            // ---- B fragments: 4 n-frags x {b0,b1}, hi and lo ----
            uint32_t bh[4][2], bl[4][2];
#pragma unroll
            for (int np = 0; np < 2; np++) {
                uint32_t off = (uint32_t)((wc * 32 + np * 16 + b_n) * SMS_ + ks * 16 + b_k) * 2;
                LDSM_X4(bh[np * 2][0], bh[np * 2][1], bh[np * 2 + 1][0], bh[np * 2 + 1][1],
                        sBh_u + off);
                LDSM_X4(bl[np * 2][0], bl[np * 2][1], bl[np * 2 + 1][0], bl[np * 2 + 1][1],
                        sBl_u + off);
            }
#pragma unroll
            for (int mi = 0; mi < 4; mi++) {
                uint32_t ah[4], al[4];
                uint32_t aoff = (uint32_t)((wr * 64 + mi * 16 + a_row) * SMS_ + ks * 16 + a_colh) * 2;
                LDSM_X4(ah[0], ah[1], ah[2], ah[3], sAh_u + aoff);
                LDSM_X4(al[0], al[1], al[2], al[3], sAl_u + aoff);
#pragma unroll
                for (int ni = 0; ni < 4; ni++) {
                    MMA16816(acc[mi][ni], ah, bh[ni]);
                    MMA16816(acc[mi][ni], ah, bl[ni]);
                    MMA16816(acc[mi][ni], al, bh[ni]);
                }
            }
        }
        __syncthreads();
    }

    // ---- epilogue: write scores/16 ----
    int gid = lane >> 2, tig = lane & 3;
    float* O = OUT + (size_t)b * M_ * N_;
#pragma unroll
    for (int mi = 0; mi < 4; mi++) {
        int row = m0 + wr * 64 + mi * 16 + gid;
#pragma unroll
        for (int ni = 0; ni < 4; ni++) {
            int col = n0 + wc * 32 + ni * 8 + tig * 2;
            float2 v0, v1;
            v0.x = acc[mi][ni][0] * 0.0625f;
            v0.y = acc[mi][ni][1] * 0.0625f;
            v1.x = acc[mi][ni][2] * 0.0625f;
            v1.y = acc[mi][ni][3] * 0.0625f;
            *(float2*)(O + (size_t)row * N_ + col) = v0;
            *(float2*)(O + (size_t)(row + 8) * N_ + col) = v1;
        }
    }
}

// ---------------- softmax: K0 = exp(log_softmax(scores)/rho) in place; row sums ----------------
__global__ __launch_bounds__(256) void softmax_kernel(float* __restrict__ K,
                                                      const float* __restrict__ rho_p) {
    int row = blockIdx.x;
    float* P = K + (size_t)row * N_;
    int tid = threadIdx.x;
    float v[8];
#pragma unroll
    for (int k = 0; k < 8; k++) v[k] = P[tid + k * 256];
    float mx = -3.4e38f;
#pragma unroll
    for (int k = 0; k < 8; k++) mx = fmaxf(mx, v[k]);
    mx = blockReduceMax(mx);
    float z = 0.f;
#pragma unroll
    for (int k = 0; k < 8; k++) z += __expf(v[k] - mx);
    z = blockReduceSum(z);
    float rho = fmaxf(rho_p[0], 1e-8f);
    float invrho = 1.0f / rho;
    float lz = __logf(z);
    float rs = 0.f;
#pragma unroll
    for (int k = 0; k < 8; k++) {
        float e = __expf((v[k] - mx - lz) * invrho);
        P[tid + k * 256] = e;
        rs += e;
    }
    rs = blockReduceSum(rs);
    if (tid == 0) g_rowtmp[row] = rs;
}

// ---------------- initial global normalization ----------------
__global__ __launch_bounds__(256) void initg_kernel() {
    int b = blockIdx.x;
    float s = 0.f;
    for (int i = threadIdx.x; i < M_; i += 256) s += g_rowtmp[b * M_ + i];
    s = blockReduceSum(s);
    if (threadIdx.x == 0) g_g[b] = 1.0f / fmaxf(s, 1e-8f);
}

// ---------------- iteration 1 row scaling (free — uses softmax rowsums) ----------------
__global__ void initR_kernel() {
    int i = blockIdx.x * blockDim.x + threadIdx.x;
    if (i < B_ * M_) {
        int b = i >> 11;
        float rowsum = g_g[b] * g_rowtmp[i];
        g_R[i] = fminf((1.0f / 2048.0f) / fmaxf(rowsum, 1e-8f), 1.0f);
    }
}

// ---------------- iteration 1 column partial sums ----------------
__global__ __launch_bounds__(256) void colsum_kernel(const float* __restrict__ K) {
    int b = blockIdx.x >> 6;
    int slice = blockIdx.x & 63;
    int i0 = slice * ROWS_PER_SLICE_;
    int tid = threadIdx.x;
    const float* base = K + ((size_t)(b << 11) + i0) * N_;
    float acc[8] = {0, 0, 0, 0, 0, 0, 0, 0};
    for (int r = 0; r < ROWS_PER_SLICE_; r++) {
        float Rv = g_R[(b << 11) + i0 + r];
        const float* P = base + (size_t)r * N_;
#pragma unroll
        for (int k = 0; k < 8; k++) acc[k] += P[tid + k * 256] * Rv;
    }
    float* out = g_colpart + (size_t)blockIdx.x * N_;
#pragma unroll
    for (int k = 0; k < 8; k++) out[tid + k * 256] = acc[k];
}

// ---------------- iterations 2-5: fused rowscale + colsum (one K read) ----------------
__global__ __launch_bounds__(256) void fused_iter_kernel(const float* __restrict__ K) {
    int b = blockIdx.x >> 6;
    int slice = blockIdx.x & 63;
    int i0 = slice * ROWS_PER_SLICE_;
    int tid = threadIdx.x;
    const float* Cp = g_C + (b << 11);
    float c[8];
#pragma unroll
    for (int k = 0; k < 8; k++) c[k] = Cp[tid + k * 256];
    float g = g_g[b];
    float acc[8] = {0, 0, 0, 0, 0, 0, 0, 0};
    const float* base = K + ((size_t)(b << 11) + i0) * N_;
    for (int r = 0; r < ROWS_PER_SLICE_; r++) {
        const float* P = base + (size_t)r * N_;
        float v[8];
#pragma unroll
        for (int k = 0; k < 8; k++) v[k] = P[tid + k * 256];
        float d = 0.f;
#pragma unroll
        for (int k = 0; k < 8; k++) d += v[k] * c[k];
        d = blockReduceSum(d);
        float Rold = g_R[(b << 11) + i0 + r];
        float rowsum = g * Rold * d;
        float Rnew = Rold * fminf((1.0f / 2048.0f) / fmaxf(rowsum, 1e-8f), 1.0f);
        if (tid == 0) g_R[(b << 11) + i0 + r] = Rnew;
#pragma unroll
        for (int k = 0; k < 8; k++) acc[k] += v[k] * Rnew;
    }
    float* outp = g_colpart + (size_t)blockIdx.x * N_;
#pragma unroll
    for (int k = 0; k < 8; k++) outp[tid + k * 256] = acc[k];
}

// ---------------- col scaling + global renorm ----------------
__global__ __launch_bounds__(256) void colscale_kernel() {
    int b = blockIdx.x;
    int tid = threadIdx.x;
    float g = g_g[b];
    float tp = 0.f;
#pragma unroll
    for (int k = 0; k < 8; k++) {
        int j = tid + k * 256;
        float acc = 0.f;
        const float* cp = g_colpart + (size_t)(b << 6) * N_ + j;
        for (int s = 0; s < SLICES_; s++) acc += cp[(size_t)s * N_];
        int cj = (b << 11) + j;
        float colsum = g * g_C[cj] * acc;
        float cc = fminf((1.0f / 2048.0f) / fmaxf(colsum, 1e-8f), 1.0f);
        g_C[cj] *= cc;
        tp += colsum * cc;
    }
    tp = blockReduceSum(tp);
    if (tid == 0) g_g[b] = g * (1.0f / fmaxf(tp, 1e-8f));
}

// ---------------- final: matches written in place; rowsum + matches@t^T ----------------
__global__ __launch_bounds__(256) void final_kernel(float* __restrict__ K,
                                                    const float* __restrict__ tgt) {
    int row = blockIdx.x;
    int b = row >> 11;
    int tid = threadIdx.x;
    float* P = K + (size_t)row * N_;
    const float* C = g_C + (b << 11);
    const float* t0 = tgt + (size_t)b * 3 * N_;
    const float* t1 = t0 + N_;
    const float* t2 = t0 + 2 * N_;
    float gR = g_g[b] * g_R[row];
    float s = 0.f, sx = 0.f, sy = 0.f, sz = 0.f;
#pragma unroll
    for (int k = 0; k < 8; k++) {
        int j = tid + k * 256;
        float val = P[j] * gR * C[j];
        P[j] = val;
        s += val;
        sx += val * t0[j];
        sy += val * t1[j];
        sz += val * t2[j];
    }
    s = blockReduceSum(s);
    sx = blockReduceSum(sx);
    sy = blockReduceSum(sy);
    sz = blockReduceSum(sz);
    if (tid == 0) {
        g_w[row] = s;
        g_numer[row * 3 + 0] = sx;
        g_numer[row * 3 + 1] = sy;
        g_numer[row * 3 + 2] = sz;
    }
}

// ---------------- rigid transform: weighted Kabsch + 3x3 SVD (fp64) ----------------
__global__ __launch_bounds__(256) void rigid_kernel(const float* __restrict__ src,
                                                    float* __restrict__ out) {
    int b = blockIdx.x;
    int tid = threadIdx.x;
    const float* s0 = src + (size_t)b * 3 * M_;
    const float* s1 = s0 + M_;
    const float* s2 = s0 + 2 * M_;
    double acc[16];
#pragma unroll
    for (int q = 0; q < 16; q++) acc[q] = 0.0;
    for (int i = tid; i < M_; i += 256) {
        int row = (b << 11) + i;
        double w = (double)g_w[row];
        double dn = w + 1e-6;
        double bx = (double)g_numer[row * 3 + 0] / dn;
        double by = (double)g_numer[row * 3 + 1] / dn;
        double bz = (double)g_numer[row * 3 + 2] / dn;
        double ax = (double)s0[i], ay = (double)s1[i], az = (double)s2[i];
        acc[0] += w;
        acc[1] += w * ax; acc[2] += w * ay; acc[3] += w * az;
        acc[4] += w * bx; acc[5] += w * by; acc[6] += w * bz;
        acc[7]  += w * ax * bx; acc[8]  += w * ax * by; acc[9]  += w * ax * bz;
        acc[10] += w * ay * bx; acc[11] += w * ay * by; acc[12] += w * ay * bz;
        acc[13] += w * az * bx; acc[14] += w * az * by; acc[15] += w * az * bz;
    }
    __shared__ double sh[256];
    __shared__ double res[16];
    for (int q = 0; q < 16; q++) {
        sh[tid] = acc[q];
        __syncthreads();
        for (int off = 128; off > 0; off >>= 1) {
            if (tid < off) sh[tid] += sh[tid + off];
            __syncthreads();
        }
        if (tid == 0) res[q] = sh[0];
        __syncthreads();
    }
    if (tid != 0) return;

    double W2 = res[0] + 1e-6;
    double ca[3], cb[3];
#pragma unroll
    for (int i = 0; i < 3; i++) {
        ca[i] = res[1 + i] / W2;
        cb[i] = res[4 + i] / W2;
    }
    double sfac = 2.0 - res[0] / W2;
    double Cv[3][3];
#pragma unroll
    for (int i = 0; i < 3; i++)
#pragma unroll
        for (int j = 0; j < 3; j++)
            Cv[i][j] = res[7 + i * 3 + j] / W2 - sfac * ca[i] * cb[j];

    double A[3][3];
#pragma unroll
    for (int i = 0; i < 3; i++)
#pragma unroll
        for (int j = 0; j < 3; j++)
            A[i][j] = Cv[0][i] * Cv[0][j] + Cv[1][i] * Cv[1][j] + Cv[2][i] * Cv[2][j];
    double V[3][3] = {{1, 0, 0}, {0, 1, 0}, {0, 0, 1}};
    const int PP[3] = {0, 0, 1}, QQ[3] = {1, 2, 2};
    for (int sweep = 0; sweep < 30; sweep++) {
        double off = fabs(A[0][1]) + fabs(A[0][2]) + fabs(A[1][2]);
        if (off < 1e-28) break;
        for (int r = 0; r < 3; r++) {
            int p = PP[r], q = QQ[r];
            double apq = A[p][q];
            if (apq == 0.0) continue;
            double theta = (A[q][q] - A[p][p]) / (2.0 * apq);
            double t = ((theta >= 0.0) ? 1.0 : -1.0) / (fabs(theta) + sqrt(1.0 + theta * theta));
            double c = 1.0 / sqrt(1.0 + t * t);
            double s = t * c;
            for (int k = 0; k < 3; k++) {
                double akp = A[k][p], akq = A[k][q];
                A[k][p] = c * akp - s * akq;
                A[k][q] = s * akp + c * akq;
            }
            for (int k = 0; k < 3; k++) {
                double apk = A[p][k], aqk = A[q][k];
                A[p][k] = c * apk - s * aqk;
                A[q][k] = s * apk + c * aqk;
            }
            for (int k = 0; k < 3; k++) {
                double vkp = V[k][p], vkq = V[k][q];
                V[k][p] = c * vkp - s * vkq;
                V[k][q] = s * vkp + c * vkq;
            }
        }
    }
    double d[3] = {A[0][0], A[1][1], A[2][2]};
    for (int i = 0; i < 2; i++)
        for (int j = i + 1; j < 3; j++)
            if (d[j] > d[i]) {
                double tmp = d[i]; d[i] = d[j]; d[j] = tmp;
                for (int k = 0; k < 3; k++) {
                    double tv = V[k][i]; V[k][i] = V[k][j]; V[k][j] = tv;
                }
            }
    double U[3][3];
    double nrm[3];
#pragma unroll
    for (int k = 0; k < 3; k++) {
        double u0 = Cv[0][0] * V[0][k] + Cv[0][1] * V[1][k] + Cv[0][2] * V[2][k];
        double u1 = Cv[1][0] * V[0][k] + Cv[1][1] * V[1][k] + Cv[1][2] * V[2][k];
        double u2 = Cv[2][0] * V[0][k] + Cv[2][1] * V[1][k] + Cv[2][2] * V[2][k];
        double n = sqrt(u0 * u0 + u1 * u1 + u2 * u2);
        nrm[k] = n;
        if (n > 1e-30) {
            U[0][k] = u0 / n; U[1][k] = u1 / n; U[2][k] = u2 / n;
        } else {
            U[0][k] = 0.0; U[1][k] = 0.0; U[2][k] = 0.0;
        }
    }
    if (nrm[2] <= 1e-12 * fmax(nrm[0], 1e-30)) {
        double cx = U[1][0] * U[2][1] - U[2][0] * U[1][1];
        double cy = U[2][0] * U[0][1] - U[0][0] * U[2][1];
        double cz = U[0][0] * U[1][1] - U[1][0] * U[0][1];
        double n = sqrt(cx * cx + cy * cy + cz * cz);
        if (n > 1e-30) { U[0][2] = cx / n; U[1][2] = cy / n; U[2][2] = cz / n; }
    }
    double R[3][3];
#pragma unroll
    for (int i = 0; i < 3; i++)
#pragma unroll
        for (int j = 0; j < 3; j++)
            R[i][j] = V[i][0] * U[j][0] + V[i][1] * U[j][1] + V[i][2] * U[j][2];
    double det = R[0][0] * (R[1][1] * R[2][2] - R[1][2] * R[2][1])
               - R[0][1] * (R[1][0] * R[2][2] - R[1][2] * R[2][0])
               + R[0][2] * (R[1][0] * R[2][1] - R[1][1] * R[2][0]);
    if (!(det > 0.0)) {
#pragma unroll
        for (int i = 0; i < 3; i++)
#pragma unroll
            for (int j = 0; j < 3; j++)
                R[i][j] -= 2.0 * V[i][2] * U[j][2];
    }
    double tr[3];
#pragma unroll
    for (int i = 0; i < 3; i++)
        tr[i] = cb[i] - (R[i][0] * ca[0] + R[i][1] * ca[1] + R[i][2] * ca[2]);

#pragma unroll
    for (int i = 0; i < 3; i++)
#pragma unroll
        for (int j = 0; j < 3; j++)
            out[b * 9 + i * 3 + j] = (float)R[i][j];
#pragma unroll
    for (int i = 0; i < 3; i++) out[144 + b * 3 + i] = (float)tr[i];
}

// ---------------- launch ----------------
extern "C" void kernel_launch(void* const* d_in, const int* in_sizes, int n_in,
                              void* d_out, int out_size) {
    (void)in_sizes; (void)n_in; (void)out_size;
    const float* se  = (const float*)d_in[0];
    const float* te  = (const float*)d_in[1];
    const float* src = (const float*)d_in[2];
    const float* tgt = (const float*)d_in[3];
    const float* rho = (const float*)d_in[4];
    float* out = (float*)d_out;
    float* Kmat = out + 192;  // matches region doubles as scores/K0 scratch

    init_kernel<<<(B_ * N_ + 255) / 256, 256>>>();
    __nv_bfloat16 *ah, *al, *bh, *bl;
    cudaGetSymbolAddress((void**)&ah, g_AH);
    cudaGetSymbolAddress((void**)&al, g_AL);
    cudaGetSymbolAddress((void**)&bh, g_BH);
    cudaGetSymbolAddress((void**)&bl, g_BL);
    split_transpose_kernel<<<dim3(M_ / 32, D_ / 32, B_), 256>>>(se, ah, al);
    split_transpose_kernel<<<dim3(N_ / 32, D_ / 32, B_), 256>>>(te, bh, bl);
    gemm_mma_kernel<<<dim3(N_ / 128, M_ / 128, B_), 256>>>(Kmat);
    softmax_kernel<<<B_ * M_, 256>>>(Kmat, rho);
    initg_kernel<<<B_, 256>>>();
    initR_kernel<<<(B_ * M_ + 255) / 256, 256>>>();
    colsum_kernel<<<B_ * SLICES_, 256>>>(Kmat);
    colscale_kernel<<<B_, 256>>>();
    for (int it = 0; it < 4; it++) {
        fused_iter_kernel<<<B_ * SLICES_, 256>>>(Kmat);
        colscale_kernel<<<B_, 256>>>();
    }
    final_kernel<<<B_ * M_, 256>>>(Kmat, tgt);
    rigid_kernel<<<B_, 256>>>(src, out);
}

// round 5
// speedup vs baseline: 1.5798x; 1.1884x over previous
#include <cuda_runtime.h>
#include <cuda_bf16.h>
#include <math.h>
#include <stdint.h>

#define B_ 16
#define D_ 256
#define M_ 2048
#define N_ 2048
#define SLICES_ 64
#define ROWS_PER_SLICE_ 32

// ---------------- scratch (static device arrays; no allocation) ----------------
__device__ float g_R[B_ * M_];
__device__ float g_C[B_ * N_];
__device__ float g_rowtmp[B_ * M_];
__device__ float g_colpart[B_ * SLICES_ * N_];
__device__ float g_g[B_];
__device__ float g_tppart[B_ * 8];
__device__ float g_w[B_ * M_];
__device__ float g_numer[B_ * M_ * 3];
__device__ __nv_bfloat16 g_AH[B_ * M_ * D_];
__device__ __nv_bfloat16 g_AL[B_ * M_ * D_];
__device__ __nv_bfloat16 g_BH[B_ * N_ * D_];
__device__ __nv_bfloat16 g_BL[B_ * N_ * D_];

// ---------------- helpers ----------------
__device__ __forceinline__ uint32_t smem_u32(const void* p) {
    uint32_t a;
    asm("{ .reg .u64 t; cvta.to.shared.u64 t, %1; cvt.u32.u64 %0, t; }" : "=r"(a) : "l"(p));
    return a;
}

#define LDSM_X4(r0, r1, r2, r3, addr) \
    asm volatile("ldmatrix.sync.aligned.m8n8.x4.shared.b16 {%0,%1,%2,%3}, [%4];" \
                 : "=r"(r0), "=r"(r1), "=r"(r2), "=r"(r3) : "r"(addr))

#define MMA16816(d, a, bq) \
    asm volatile( \
        "mma.sync.aligned.m16n8k16.row.col.f32.bf16.bf16.f32 " \
        "{%0,%1,%2,%3}, {%4,%5,%6,%7}, {%8,%9}, {%0,%1,%2,%3};" \
        : "+f"((d)[0]), "+f"((d)[1]), "+f"((d)[2]), "+f"((d)[3]) \
        : "r"((a)[0]), "r"((a)[1]), "r"((a)[2]), "r"((a)[3]), \
          "r"((bq)[0]), "r"((bq)[1]))

#define CP_ASYNC16(sa, ga) \
    asm volatile("cp.async.cg.shared.global [%0], [%1], 16;" :: "r"(sa), "l"(ga))

// ---------------- block reductions ----------------
__device__ __forceinline__ float blockReduceSum(float v) {
    __shared__ float sh[33];
    int lane = threadIdx.x & 31, w = threadIdx.x >> 5;
#pragma unroll
    for (int o = 16; o; o >>= 1) v += __shfl_down_sync(0xffffffffu, v, o);
    if (lane == 0) sh[w] = v;
    __syncthreads();
    if (w == 0) {
        v = (lane < (int)(blockDim.x >> 5)) ? sh[lane] : 0.f;
#pragma unroll
        for (int o = 16; o; o >>= 1) v += __shfl_down_sync(0xffffffffu, v, o);
        if (lane == 0) sh[32] = v;
    }
    __syncthreads();
    float r = sh[32];
    __syncthreads();
    return r;
}

__device__ __forceinline__ float blockReduceMax(float v) {
    __shared__ float shm[33];
    int lane = threadIdx.x & 31, w = threadIdx.x >> 5;
#pragma unroll
    for (int o = 16; o; o >>= 1) v = fmaxf(v, __shfl_down_sync(0xffffffffu, v, o));
    if (lane == 0) shm[w] = v;
    __syncthreads();
    if (w == 0) {
        v = (lane < (int)(blockDim.x >> 5)) ? shm[lane] : -3.4e38f;
#pragma unroll
        for (int o = 16; o; o >>= 1) v = fmaxf(v, __shfl_down_sync(0xffffffffu, v, o));
        if (lane == 0) shm[32] = v;
    }
    __syncthreads();
    float r = shm[32];
    __syncthreads();
    return r;
}

// ---------------- init: C = 1 ----------------
__global__ void init_kernel() {
    int i = blockIdx.x * blockDim.x + threadIdx.x;
    if (i < B_ * N_) g_C[i] = 1.0f;
}

// ---------------- transpose + bf16 hi/lo split ----------------
__global__ __launch_bounds__(256) void split_transpose_kernel(const float* __restrict__ X,
                                                              __nv_bfloat16* __restrict__ H,
                                                              __nv_bfloat16* __restrict__ L) {
    __shared__ float t[32][33];
    int b = blockIdx.z;
    int m0 = blockIdx.x * 32, d0 = blockIdx.y * 32;
    const float* Xb = X + (size_t)b * D_ * M_;
    int tx = threadIdx.x & 31, ty = threadIdx.x >> 5;
#pragma unroll
    for (int i = 0; i < 4; i++) {
        int d = d0 + ty + i * 8;
        t[ty + i * 8][tx] = Xb[(size_t)d * M_ + m0 + tx];
    }
    __syncthreads();
#pragma unroll
    for (int i = 0; i < 4; i++) {
        int m = m0 + ty + i * 8;
        float v = t[tx][ty + i * 8];
        __nv_bfloat16 h = __float2bfloat16(v);
        __nv_bfloat16 l = __float2bfloat16(v - __bfloat162float(h));
        size_t o = ((size_t)b * M_ + m) * D_ + d0 + tx;
        H[o] = h;
        L[o] = l;
    }
}

// ---------------- HMMA GEMM, 2-stage cp.async pipeline ----------------
#define SMS_ 40
#define STG_ (128 * SMS_)                 // elems per matrix per stage
#define GEMM_SMEM_BYTES (2 * 4 * STG_ * 2)

__global__ __launch_bounds__(256) void gemm_mma_kernel(float* __restrict__ OUT) {
    extern __shared__ __align__(16) __nv_bfloat16 sm[];

    int tid = threadIdx.x, wid = tid >> 5, lane = tid & 31;
    int b = blockIdx.z, m0 = blockIdx.y * 128, n0 = blockIdx.x * 128;
    int wr = wid >> 2, wc = wid & 3;

    const __nv_bfloat16* Ah = g_AH + ((size_t)b * M_ + m0) * D_;
    const __nv_bfloat16* Al = g_AL + ((size_t)b * M_ + m0) * D_;
    const __nv_bfloat16* Bh = g_BH + ((size_t)b * N_ + n0) * D_;
    const __nv_bfloat16* Bl = g_BL + ((size_t)b * N_ + n0) * D_;

    float acc[4][4][4];
#pragma unroll
    for (int mi = 0; mi < 4; mi++)
#pragma unroll
        for (int ni = 0; ni < 4; ni++)
#pragma unroll
            for (int r = 0; r < 4; r++) acc[mi][ni][r] = 0.f;

    int i0 = tid * 2, i1 = tid * 2 + 1;
    int r0_ = i0 >> 2, s0_ = i0 & 3;
    int r1_ = i1 >> 2, s1_ = i1 & 3;
    uint32_t d00 = (uint32_t)(r0_ * SMS_ + s0_ * 8) * 2;
    uint32_t d01 = (uint32_t)(r1_ * SMS_ + s1_ * 8) * 2;

    uint32_t smb = smem_u32(sm);
    uint32_t stg_bytes = 4 * STG_ * 2;
    uint32_t mat_bytes = STG_ * 2;

    int a_row = (lane & 15), a_colh = (lane >> 4) * 8;
    int b_tile = lane >> 3, b_r8 = lane & 7;
    int b_n = ((b_tile >> 1) * 8) + b_r8;
    int b_k = (b_tile & 1) * 8;

    // ---- stage loader ----
    auto load_chunk = [&](int c, int s) {
        uint32_t base = smb + (uint32_t)s * stg_bytes;
        size_t g00 = (size_t)r0_ * D_ + c * 32 + s0_ * 8;
        size_t g01 = (size_t)r1_ * D_ + c * 32 + s1_ * 8;
        CP_ASYNC16(base + d00, Ah + g00);
        CP_ASYNC16(base + d01, Ah + g01);
        CP_ASYNC16(base + mat_bytes + d00, Al + g00);
        CP_ASYNC16(base + mat_bytes + d01, Al + g01);
        CP_ASYNC16(base + 2 * mat_bytes + d00, Bh + g00);
        CP_ASYNC16(base + 2 * mat_bytes + d01, Bh + g01);
        CP_ASYNC16(base + 3 * mat_bytes + d00, Bl + g00);
        CP_ASYNC16(base + 3 * mat_bytes + d01, Bl + g01);
        asm volatile("cp.async.commit_group;" ::: "memory");
    };

    load_chunk(0, 0);

    for (int c = 0; c < 8; c++) {
        if (c < 7) load_chunk(c + 1, (c + 1) & 1);
        if (c < 7)
            asm volatile("cp.async.wait_group 1;" ::: "memory");
        else
            asm volatile("cp.async.wait_group 0;" ::: "memory");
        __syncthreads();

        uint32_t base = smb + (uint32_t)(c & 1) * stg_bytes;
        uint32_t sAh_u = base, sAl_u = base + mat_bytes;
        uint32_t sBh_u = base + 2 * mat_bytes, sBl_u = base + 3 * mat_bytes;

#pragma unroll
        for (int ks = 0; ks < 2; ks++) {
            uint32_t bh[4][2], bl[4][2];
#pragma unroll
            for (int np = 0; np < 2; np++) {
                uint32_t off = (uint32_t)((wc * 32 + np * 16 + b_n) * SMS_ + ks * 16 + b_k) * 2;
                LDSM_X4(bh[np * 2][0], bh[np * 2][1], bh[np * 2 + 1][0], bh[np * 2 + 1][1],
                        sBh_u + off);
                LDSM_X4(bl[np * 2][0], bl[np * 2][1], bl[np * 2 + 1][0], bl[np * 2 + 1][1],
                        sBl_u + off);
            }
#pragma unroll
            for (int mi = 0; mi < 4; mi++) {
                uint32_t ah[4], al[4];
                uint32_t aoff = (uint32_t)((wr * 64 + mi * 16 + a_row) * SMS_ + ks * 16 + a_colh) * 2;
                LDSM_X4(ah[0], ah[1], ah[2], ah[3], sAh_u + aoff);
                LDSM_X4(al[0], al[1], al[2], al[3], sAl_u + aoff);
#pragma unroll
                for (int ni = 0; ni < 4; ni++) {
                    MMA16816(acc[mi][ni], ah, bh[ni]);
                    MMA16816(acc[mi][ni], ah, bl[ni]);
                    MMA16816(acc[mi][ni], al, bh[ni]);
                }
            }
        }
        __syncthreads();
    }

    int gid = lane >> 2, tig = lane & 3;
    float* O = OUT + (size_t)b * M_ * N_;
#pragma unroll
    for (int mi = 0; mi < 4; mi++) {
        int row = m0 + wr * 64 + mi * 16 + gid;
#pragma unroll
        for (int ni = 0; ni < 4; ni++) {
            int col = n0 + wc * 32 + ni * 8 + tig * 2;
            float2 v0, v1;
            v0.x = acc[mi][ni][0] * 0.0625f;
            v0.y = acc[mi][ni][1] * 0.0625f;
            v1.x = acc[mi][ni][2] * 0.0625f;
            v1.y = acc[mi][ni][3] * 0.0625f;
            *(float2*)(O + (size_t)row * N_ + col) = v0;
            *(float2*)(O + (size_t)(row + 8) * N_ + col) = v1;
        }
    }
}

// ---------------- softmax ----------------
__global__ __launch_bounds__(256) void softmax_kernel(float* __restrict__ K,
                                                      const float* __restrict__ rho_p) {
    int row = blockIdx.x;
    float* P = K + (size_t)row * N_;
    int tid = threadIdx.x;
    float v[8];
#pragma unroll
    for (int k = 0; k < 8; k++) v[k] = P[tid + k * 256];
    float mx = -3.4e38f;
#pragma unroll
    for (int k = 0; k < 8; k++) mx = fmaxf(mx, v[k]);
    mx = blockReduceMax(mx);
    float z = 0.f;
#pragma unroll
    for (int k = 0; k < 8; k++) z += __expf(v[k] - mx);
    z = blockReduceSum(z);
    float rho = fmaxf(rho_p[0], 1e-8f);
    float invrho = 1.0f / rho;
    float lz = __logf(z);
    float rs = 0.f;
#pragma unroll
    for (int k = 0; k < 8; k++) {
        float e = __expf((v[k] - mx - lz) * invrho);
        P[tid + k * 256] = e;
        rs += e;
    }
    rs = blockReduceSum(rs);
    if (tid == 0) g_rowtmp[row] = rs;
}

// ---------------- initial global normalization ----------------
__global__ __launch_bounds__(256) void initg_kernel() {
    int b = blockIdx.x;
    float s = 0.f;
    for (int i = threadIdx.x; i < M_; i += 256) s += g_rowtmp[b * M_ + i];
    s = blockReduceSum(s);
    if (threadIdx.x == 0) g_g[b] = 1.0f / fmaxf(s, 1e-8f);
}

// ---------------- iteration 1 row scaling ----------------
__global__ void initR_kernel() {
    int i = blockIdx.x * blockDim.x + threadIdx.x;
    if (i < B_ * M_) {
        int b = i >> 11;
        float rowsum = g_g[b] * g_rowtmp[i];
        g_R[i] = fminf((1.0f / 2048.0f) / fmaxf(rowsum, 1e-8f), 1.0f);
    }
}

// ---------------- iteration 1 column partial sums ----------------
__global__ __launch_bounds__(256) void colsum_kernel(const float* __restrict__ K) {
    int b = blockIdx.x >> 6;
    int slice = blockIdx.x & 63;
    int i0 = slice * ROWS_PER_SLICE_;
    int tid = threadIdx.x;
    const float* base = K + ((size_t)(b << 11) + i0) * N_;
    float acc[8] = {0, 0, 0, 0, 0, 0, 0, 0};
    for (int r = 0; r < ROWS_PER_SLICE_; r++) {
        float Rv = g_R[(b << 11) + i0 + r];
        const float* P = base + (size_t)r * N_;
#pragma unroll
        for (int k = 0; k < 8; k++) acc[k] += P[tid + k * 256] * Rv;
    }
    float* out = g_colpart + (size_t)blockIdx.x * N_;
#pragma unroll
    for (int k = 0; k < 8; k++) out[tid + k * 256] = acc[k];
}

// ---------------- iterations 2-5: fused rowscale + colsum, warp-per-rows ----------------
#define FUSED_SMEM_BYTES (8 * N_ * 4)
__global__ __launch_bounds__(256) void fused_iter_kernel(const float* __restrict__ K) {
    extern __shared__ float ssum[];  // 8 warps x 2048
    int b = blockIdx.x >> 6;
    int slice = blockIdx.x & 63;
    int i0 = slice * ROWS_PER_SLICE_;
    int wid = threadIdx.x >> 5, lane = threadIdx.x & 31;
    const float* Cp = g_C + (b << 11);
    float g = g_g[b];
    float acc[64];
#pragma unroll
    for (int q = 0; q < 64; q++) acc[q] = 0.f;

    for (int r = 0; r < 4; r++) {
        int row = (b << 11) + i0 + wid * 4 + r;
        const float* P = K + (size_t)row * N_;
        float d = 0.f;
#pragma unroll
        for (int q = 0; q < 64; q++) d += P[lane + 32 * q] * Cp[lane + 32 * q];
#pragma unroll
        for (int o = 16; o; o >>= 1) d += __shfl_xor_sync(0xffffffffu, d, o);
        float Rold = g_R[row];
        float rowsum = g * Rold * d;
        float Rnew = Rold * fminf((1.0f / 2048.0f) / fmaxf(rowsum, 1e-8f), 1.0f);
        if (lane == 0) g_R[row] = Rnew;
        // second read is an L2 hit (row just streamed)
#pragma unroll
        for (int q = 0; q < 64; q++) acc[q] += P[lane + 32 * q] * Rnew;
    }
    float* myrow = ssum + wid * N_;
#pragma unroll
    for (int q = 0; q < 64; q++) myrow[lane + 32 * q] = acc[q];
    __syncthreads();
    float* outp = g_colpart + (size_t)blockIdx.x * N_;
    for (int j = threadIdx.x; j < N_; j += 256) {
        float t = 0.f;
#pragma unroll
        for (int w = 0; w < 8; w++) t += ssum[w * N_ + j];
        outp[j] = t;
    }
}

// ---------------- col scaling (parallel) + g update ----------------
__global__ __launch_bounds__(256) void colscale_part_kernel() {
    int b = blockIdx.x >> 3;
    int part = blockIdx.x & 7;
    int j = part * 256 + threadIdx.x;
    float g = g_g[b];
    float acc = 0.f;
    const float* cp = g_colpart + (size_t)(b << 6) * N_ + j;
#pragma unroll 8
    for (int s = 0; s < SLICES_; s++) acc += cp[(size_t)s * N_];
    int cj = (b << 11) + j;
    float colsum = g * g_C[cj] * acc;
    float cc = fminf((1.0f / 2048.0f) / fmaxf(colsum, 1e-8f), 1.0f);
    g_C[cj] *= cc;
    float tp = blockReduceSum(colsum * cc);
    if (threadIdx.x == 0) g_tppart[blockIdx.x] = tp;
}

__global__ void gfix_kernel() {
    int b = threadIdx.x;
    if (b < B_) {
        float tp = 0.f;
#pragma unroll
        for (int p = 0; p < 8; p++) tp += g_tppart[b * 8 + p];
        g_g[b] *= 1.0f / fmaxf(tp, 1e-8f);
    }
}

// ---------------- final ----------------
__global__ __launch_bounds__(256) void final_kernel(float* __restrict__ K,
                                                    const float* __restrict__ tgt) {
    int row = blockIdx.x;
    int b = row >> 11;
    int tid = threadIdx.x;
    float* P = K + (size_t)row * N_;
    const float* C = g_C + (b << 11);
    const float* t0 = tgt + (size_t)b * 3 * N_;
    const float* t1 = t0 + N_;
    const float* t2 = t0 + 2 * N_;
    float gR = g_g[b] * g_R[row];
    float s = 0.f, sx = 0.f, sy = 0.f, sz = 0.f;
#pragma unroll
    for (int k = 0; k < 8; k++) {
        int j = tid + k * 256;
        float val = P[j] * gR * C[j];
        P[j] = val;
        s += val;
        sx += val * t0[j];
        sy += val * t1[j];
        sz += val * t2[j];
    }
    s = blockReduceSum(s);
    sx = blockReduceSum(sx);
    sy = blockReduceSum(sy);
    sz = blockReduceSum(sz);
    if (tid == 0) {
        g_w[row] = s;
        g_numer[row * 3 + 0] = sx;
        g_numer[row * 3 + 1] = sy;
        g_numer[row * 3 + 2] = sz;
    }
}

// ---------------- rigid transform (fp64 Kabsch + Jacobi SVD) ----------------
__global__ __launch_bounds__(256) void rigid_kernel(const float* __restrict__ src,
                                                    float* __restrict__ out) {
    int b = blockIdx.x;
    int tid = threadIdx.x;
    const float* s0 = src + (size_t)b * 3 * M_;
    const float* s1 = s0 + M_;
    const float* s2 = s0 + 2 * M_;
    double acc[16];
#pragma unroll
    for (int q = 0; q < 16; q++) acc[q] = 0.0;
    for (int i = tid; i < M_; i += 256) {
        int row = (b << 11) + i;
        double w = (double)g_w[row];
        double dn = w + 1e-6;
        double bx = (double)g_numer[row * 3 + 0] / dn;
        double by = (double)g_numer[row * 3 + 1] / dn;
        double bz = (double)g_numer[row * 3 + 2] / dn;
        double ax = (double)s0[i], ay = (double)s1[i], az = (double)s2[i];
        acc[0] += w;
        acc[1] += w * ax; acc[2] += w * ay; acc[3] += w * az;
        acc[4] += w * bx; acc[5] += w * by; acc[6] += w * bz;
        acc[7]  += w * ax * bx; acc[8]  += w * ax * by; acc[9]  += w * ax * bz;
        acc[10] += w * ay * bx; acc[11] += w * ay * by; acc[12] += w * ay * bz;
        acc[13] += w * az * bx; acc[14] += w * az * by; acc[15] += w * az * bz;
    }
    __shared__ double sh[256];
    __shared__ double res[16];
    for (int q = 0; q < 16; q++) {
        sh[tid] = acc[q];
        __syncthreads();
        for (int off = 128; off > 0; off >>= 1) {
            if (tid < off) sh[tid] += sh[tid + off];
            __syncthreads();
        }
        if (tid == 0) res[q] = sh[0];
        __syncthreads();
    }
    if (tid != 0) return;

    double W2 = res[0] + 1e-6;
    double ca[3], cb[3];
#pragma unroll
    for (int i = 0; i < 3; i++) {
        ca[i] = res[1 + i] / W2;
        cb[i] = res[4 + i] / W2;
    }
    double sfac = 2.0 - res[0] / W2;
    double Cv[3][3];
#pragma unroll
    for (int i = 0; i < 3; i++)
#pragma unroll
        for (int j = 0; j < 3; j++)
            Cv[i][j] = res[7 + i * 3 + j] / W2 - sfac * ca[i] * cb[j];

    double A[3][3];
#pragma unroll
    for (int i = 0; i < 3; i++)
#pragma unroll
        for (int j = 0; j < 3; j++)
            A[i][j] = Cv[0][i] * Cv[0][j] + Cv[1][i] * Cv[1][j] + Cv[2][i] * Cv[2][j];
    double V[3][3] = {{1, 0, 0}, {0, 1, 0}, {0, 0, 1}};
    const int PP[3] = {0, 0, 1}, QQ[3] = {1, 2, 2};
    for (int sweep = 0; sweep < 30; sweep++) {
        double off = fabs(A[0][1]) + fabs(A[0][2]) + fabs(A[1][2]);
        if (off < 1e-28) break;
        for (int r = 0; r < 3; r++) {
            int p = PP[r], q = QQ[r];
            double apq = A[p][q];
            if (apq == 0.0) continue;
            double theta = (A[q][q] - A[p][p]) / (2.0 * apq);
            double t = ((theta >= 0.0) ? 1.0 : -1.0) / (fabs(theta) + sqrt(1.0 + theta * theta));
            double c = 1.0 / sqrt(1.0 + t * t);
            double s = t * c;
            for (int k = 0; k < 3; k++) {
                double akp = A[k][p], akq = A[k][q];
                A[k][p] = c * akp - s * akq;
                A[k][q] = s * akp + c * akq;
            }
            for (int k = 0; k < 3; k++) {
                double apk = A[p][k], aqk = A[q][k];
                A[p][k] = c * apk - s * aqk;
                A[q][k] = s * apk + c * aqk;
            }
            for (int k = 0; k < 3; k++) {
                double vkp = V[k][p], vkq = V[k][q];
                V[k][p] = c * vkp - s * vkq;
                V[k][q] = s * vkp + c * vkq;
            }
        }
    }
    double d[3] = {A[0][0], A[1][1], A[2][2]};
    for (int i = 0; i < 2; i++)
        for (int j = i + 1; j < 3; j++)
            if (d[j] > d[i]) {
                double tmp = d[i]; d[i] = d[j]; d[j] = tmp;
                for (int k = 0; k < 3; k++) {
                    double tv = V[k][i]; V[k][i] = V[k][j]; V[k][j] = tv;
                }
            }
    double U[3][3];
    double nrm[3];
#pragma unroll
    for (int k = 0; k < 3; k++) {
        double u0 = Cv[0][0] * V[0][k] + Cv[0][1] * V[1][k] + Cv[0][2] * V[2][k];
        double u1 = Cv[1][0] * V[0][k] + Cv[1][1] * V[1][k] + Cv[1][2] * V[2][k];
        double u2 = Cv[2][0] * V[0][k] + Cv[2][1] * V[1][k] + Cv[2][2] * V[2][k];
        double n = sqrt(u0 * u0 + u1 * u1 + u2 * u2);
        nrm[k] = n;
        if (n > 1e-30) {
            U[0][k] = u0 / n; U[1][k] = u1 / n; U[2][k] = u2 / n;
        } else {
            U[0][k] = 0.0; U[1][k] = 0.0; U[2][k] = 0.0;
        }
    }
    if (nrm[2] <= 1e-12 * fmax(nrm[0], 1e-30)) {
        double cx = U[1][0] * U[2][1] - U[2][0] * U[1][1];
        double cy = U[2][0] * U[0][1] - U[0][0] * U[2][1];
        double cz = U[0][0] * U[1][1] - U[1][0] * U[0][1];
        double n = sqrt(cx * cx + cy * cy + cz * cz);
        if (n > 1e-30) { U[0][2] = cx / n; U[1][2] = cy / n; U[2][2] = cz / n; }
    }
    double R[3][3];
#pragma unroll
    for (int i = 0; i < 3; i++)
#pragma unroll
        for (int j = 0; j < 3; j++)
            R[i][j] = V[i][0] * U[j][0] + V[i][1] * U[j][1] + V[i][2] * U[j][2];
    double det = R[0][0] * (R[1][1] * R[2][2] - R[1][2] * R[2][1])
               - R[0][1] * (R[1][0] * R[2][2] - R[1][2] * R[2][0])
               + R[0][2] * (R[1][0] * R[2][1] - R[1][1] * R[2][0]);
    if (!(det > 0.0)) {
#pragma unroll
        for (int i = 0; i < 3; i++)
#pragma unroll
            for (int j = 0; j < 3; j++)
                R[i][j] -= 2.0 * V[i][2] * U[j][2];
    }
    double tr[3];
#pragma unroll
    for (int i = 0; i < 3; i++)
        tr[i] = cb[i] - (R[i][0] * ca[0] + R[i][1] * ca[1] + R[i][2] * ca[2]);

#pragma unroll
    for (int i = 0; i < 3; i++)
#pragma unroll
        for (int j = 0; j < 3; j++)
            out[b * 9 + i * 3 + j] = (float)R[i][j];
#pragma unroll
    for (int i = 0; i < 3; i++) out[144 + b * 3 + i] = (float)tr[i];
}

// ---------------- launch ----------------
extern "C" void kernel_launch(void* const* d_in, const int* in_sizes, int n_in,
                              void* d_out, int out_size) {
    (void)in_sizes; (void)n_in; (void)out_size;
    const float* se  = (const float*)d_in[0];
    const float* te  = (const float*)d_in[1];
    const float* src = (const float*)d_in[2];
    const float* tgt = (const float*)d_in[3];
    const float* rho = (const float*)d_in[4];
    float* out = (float*)d_out;
    float* Kmat = out + 192;

    static int attr_done = 0;
    if (!attr_done) {
        cudaFuncSetAttribute(gemm_mma_kernel, cudaFuncAttributeMaxDynamicSharedMemorySize,
                             GEMM_SMEM_BYTES);
        cudaFuncSetAttribute(fused_iter_kernel, cudaFuncAttributeMaxDynamicSharedMemorySize,
                             FUSED_SMEM_BYTES);
        attr_done = 1;
    }

    init_kernel<<<(B_ * N_ + 255) / 256, 256>>>();
    __nv_bfloat16 *ah, *al, *bh, *bl;
    cudaGetSymbolAddress((void**)&ah, g_AH);
    cudaGetSymbolAddress((void**)&al, g_AL);
    cudaGetSymbolAddress((void**)&bh, g_BH);
    cudaGetSymbolAddress((void**)&bl, g_BL);
    split_transpose_kernel<<<dim3(M_ / 32, D_ / 32, B_), 256>>>(se, ah, al);
    split_transpose_kernel<<<dim3(N_ / 32, D_ / 32, B_), 256>>>(te, bh, bl);
    gemm_mma_kernel<<<dim3(N_ / 128, M_ / 128, B_), 256, GEMM_SMEM_BYTES>>>(Kmat);
    softmax_kernel<<<B_ * M_, 256>>>(Kmat, rho);
    initg_kernel<<<B_, 256>>>();
    initR_kernel<<<(B_ * M_ + 255) / 256, 256>>>();
    colsum_kernel<<<B_ * SLICES_, 256>>>(Kmat);
    colscale_part_kernel<<<B_ * 8, 256>>>();
    gfix_kernel<<<1, 32>>>();
    for (int it = 0; it < 4; it++) {
        fused_iter_kernel<<<B_ * SLICES_, 256, FUSED_SMEM_BYTES>>>(Kmat);
        colscale_part_kernel<<<B_ * 8, 256>>>();
        gfix_kernel<<<1, 32>>>();
    }
    final_kernel<<<B_ * M_, 256>>>(Kmat, tgt);
    rigid_kernel<<<B_, 256>>>(src, out);
}

// round 8
// speedup vs baseline: 1.6090x; 1.0185x over previous
#include <cuda_runtime.h>
#include <cuda_bf16.h>
#include <math.h>
#include <stdint.h>

#define B_ 16
#define D_ 256
#define M_ 2048
#define N_ 2048
#define SLICES_ 64
#define ROWS_PER_SLICE_ 32

// ---------------- scratch (static device arrays; no allocation) ----------------
__device__ float g_R[B_ * M_];
__device__ float g_C[B_ * N_];
__device__ float g_rowtmp[B_ * M_];
__device__ float g_colpart[B_ * SLICES_ * N_];
__device__ float g_g[B_];
__device__ float g_tppart[B_ * 8];
__device__ float g_w[B_ * M_];
__device__ float g_numer[B_ * M_ * 3];
__device__ __nv_bfloat16 g_BH[B_ * N_ * D_];
__device__ __nv_bfloat16 g_BL[B_ * N_ * D_];

// ---------------- helpers ----------------
__device__ __forceinline__ uint32_t smem_u32(const void* p) {
    uint32_t a;
    asm("{ .reg .u64 t; cvta.to.shared.u64 t, %1; cvt.u32.u64 %0, t; }" : "=r"(a) : "l"(p));
    return a;
}

#define LDSM_X4(r0, r1, r2, r3, addr) \
    asm volatile("ldmatrix.sync.aligned.m8n8.x4.shared.b16 {%0,%1,%2,%3}, [%4];" \
                 : "=r"(r0), "=r"(r1), "=r"(r2), "=r"(r3) : "r"(addr))

#define MMA16816(d, a, bq) \
    asm volatile( \
        "mma.sync.aligned.m16n8k16.row.col.f32.bf16.bf16.f32 " \
        "{%0,%1,%2,%3}, {%4,%5,%6,%7}, {%8,%9}, {%0,%1,%2,%3};" \
        : "+f"((d)[0]), "+f"((d)[1]), "+f"((d)[2]), "+f"((d)[3]) \
        : "r"((a)[0]), "r"((a)[1]), "r"((a)[2]), "r"((a)[3]), \
          "r"((bq)[0]), "r"((bq)[1]))

#define CP_ASYNC16(sa, ga) \
    asm volatile("cp.async.cg.shared.global [%0], [%1], 16;" :: "r"(sa), "l"(ga))

// ---------------- block reductions ----------------
__device__ __forceinline__ float blockReduceSum(float v) {
    __shared__ float sh[33];
    int lane = threadIdx.x & 31, w = threadIdx.x >> 5;
#pragma unroll
    for (int o = 16; o; o >>= 1) v += __shfl_down_sync(0xffffffffu, v, o);
    if (lane == 0) sh[w] = v;
    __syncthreads();
    if (w == 0) {
        v = (lane < (int)(blockDim.x >> 5)) ? sh[lane] : 0.f;
#pragma unroll
        for (int o = 16; o; o >>= 1) v += __shfl_down_sync(0xffffffffu, v, o);
        if (lane == 0) sh[32] = v;
    }
    __syncthreads();
    float r = sh[32];
    __syncthreads();
    return r;
}

// ---------------- init: C = 1 ----------------
__global__ void init_kernel() {
    int i = blockIdx.x * blockDim.x + threadIdx.x;
    if (i < B_ * N_) g_C[i] = 1.0f;
}

// ---------------- transpose + bf16 hi/lo split for B (te) only ----------------
__global__ __launch_bounds__(256) void split_transpose_kernel(const float* __restrict__ X,
                                                              __nv_bfloat16* __restrict__ H,
                                                              __nv_bfloat16* __restrict__ L) {
    __shared__ float t[32][33];
    int b = blockIdx.z;
    int m0 = blockIdx.x * 32, d0 = blockIdx.y * 32;
    const float* Xb = X + (size_t)b * D_ * M_;
    int tx = threadIdx.x & 31, ty = threadIdx.x >> 5;
#pragma unroll
    for (int i = 0; i < 4; i++) {
        int d = d0 + ty + i * 8;
        t[ty + i * 8][tx] = Xb[(size_t)d * M_ + m0 + tx];
    }
    __syncthreads();
#pragma unroll
    for (int i = 0; i < 4; i++) {
        int m = m0 + ty + i * 8;
        float v = t[tx][ty + i * 8];
        __nv_bfloat16 h = __float2bfloat16(v);
        __nv_bfloat16 l = __float2bfloat16(v - __bfloat162float(h));
        size_t o = ((size_t)b * M_ + m) * D_ + d0 + tx;
        H[o] = h;
        L[o] = l;
    }
}

// ---------------- fused GEMM + exp + row stats ----------------
// CTA: 64-row strip x full N=2048. A (hi/lo) resident in smem (stride 264 elems =
// 528B, 16B-aligned, conflict-free). B double-buffered with stride 40 (80B rows).
// Writes K0' = exp(scores/rho); g_R = cr_i = (sum exp v)^(-1/rho); g_rowtmp = cr_i*s_i.
#define ASTR_ 264
#define SMS_ 40
#define A_H_OFF 0
#define A_L_OFF (64 * ASTR_ * 2)                  // 33792
#define B_OFF (2 * 64 * ASTR_ * 2)                // 67584
#define B_MAT_BYTES (128 * SMS_ * 2)              // 10240
#define B_STAGE_BYTES (2 * B_MAT_BYTES)           // 20480 (Bh+Bl)
#define GEMM_SMEM_BYTES (B_OFF + 2 * B_STAGE_BYTES)  // 108544

__global__ __launch_bounds__(256, 2) void gemm_fused_kernel(float* __restrict__ OUT,
                                                            const float* __restrict__ SE,
                                                            const float* __restrict__ rho_p) {
    extern __shared__ __align__(16) char smem[];
    uint32_t smb = smem_u32(smem);
    int tid = threadIdx.x, wid = tid >> 5, lane = tid & 31;
    int mt = blockIdx.x, b = blockIdx.y;
    int m0 = mt * 64;
    int wr = wid >> 2, wc = wid & 3;
    int gid = lane >> 2, tig = lane & 3;

    float rho = fmaxf(rho_p[0], 1e-8f);
    float invr = 1.0f / rho;

    // ---- prologue: load A strip (64 rows x 256 k) from se (D, M) layout, split bf16 ----
    {
        const float* Ab = SE + (size_t)b * D_ * M_ + m0;
        int dd = tid >> 6, j = tid & 63;
        __nv_bfloat16* aH = (__nv_bfloat16*)(smem + A_H_OFF);
        __nv_bfloat16* aL = (__nv_bfloat16*)(smem + A_L_OFF);
        for (int d0 = 0; d0 < D_; d0 += 4) {
            int d = d0 + dd;
            float v = Ab[(size_t)d * M_ + j];
            __nv_bfloat16 h = __float2bfloat16(v);
            __nv_bfloat16 l = __float2bfloat16(v - __bfloat162float(h));
            int off = j * ASTR_ + d;
            aH[off] = h;
            aL[off] = l;
        }
    }
    __syncthreads();

    float acc[2][4][4];
#pragma unroll
    for (int mi = 0; mi < 2; mi++)
#pragma unroll
        for (int ni = 0; ni < 4; ni++)
#pragma unroll
            for (int r = 0; r < 4; r++) acc[mi][ni][r] = 0.f;

    float s_part[2][2] = {{0, 0}, {0, 0}};
    float z_part[2][2] = {{0, 0}, {0, 0}};

    // cp.async thread mapping for one 128x32 bf16 matrix (512 16B vectors)
    int i0 = tid * 2, i1 = tid * 2 + 1;
    int r0_ = i0 >> 2, s0_ = i0 & 3;
    int r1_ = i1 >> 2, s1_ = i1 & 3;
    uint32_t d00 = (uint32_t)(r0_ * SMS_ + s0_ * 8) * 2;
    uint32_t d01 = (uint32_t)(r1_ * SMS_ + s1_ * 8) * 2;

    const __nv_bfloat16* BHb = g_BH + (size_t)b * N_ * D_;
    const __nv_bfloat16* BLb = g_BL + (size_t)b * N_ * D_;

    int a_row = (lane & 15), a_colh = (lane >> 4) * 8;
    int b_tile = lane >> 3, b_r8 = lane & 7;
    int b_n = ((b_tile >> 1) * 8) + b_r8;
    int b_k = (b_tile & 1) * 8;

    auto load_chunk = [&](int cc) {
        int nt = cc >> 3, c = cc & 7;
        uint32_t base = smb + B_OFF + (uint32_t)(cc & 1) * B_STAGE_BYTES;
        const __nv_bfloat16* Bh = BHb + (size_t)(nt * 128) * D_ + c * 32;
        const __nv_bfloat16* Bl = BLb + (size_t)(nt * 128) * D_ + c * 32;
        size_t g00 = (size_t)r0_ * D_ + s0_ * 8;
        size_t g01 = (size_t)r1_ * D_ + s1_ * 8;
        CP_ASYNC16(base + d00, Bh + g00);
        CP_ASYNC16(base + d01, Bh + g01);
        CP_ASYNC16(base + B_MAT_BYTES + d00, Bl + g00);
        CP_ASYNC16(base + B_MAT_BYTES + d01, Bl + g01);
        asm volatile("cp.async.commit_group;" ::: "memory");
    };

    load_chunk(0);
    float* Ob = OUT + (size_t)b * M_ * N_;

    for (int cc = 0; cc < 128; cc++) {
        if (cc < 127) load_chunk(cc + 1);
        if (cc < 127)
            asm volatile("cp.async.wait_group 1;" ::: "memory");
        else
            asm volatile("cp.async.wait_group 0;" ::: "memory");
        __syncthreads();

        int c = cc & 7;
        uint32_t bbase = smb + B_OFF + (uint32_t)(cc & 1) * B_STAGE_BYTES;
        uint32_t sBh_u = bbase, sBl_u = bbase + B_MAT_BYTES;
        uint32_t aH_u = smb + A_H_OFF;
        uint32_t aL_u = smb + A_L_OFF;

#pragma unroll
        for (int ks = 0; ks < 2; ks++) {
            uint32_t bh[4][2], bl[4][2];
#pragma unroll
            for (int np = 0; np < 2; np++) {
                uint32_t off = (uint32_t)((wc * 32 + np * 16 + b_n) * SMS_ + ks * 16 + b_k) * 2;
                LDSM_X4(bh[np * 2][0], bh[np * 2][1], bh[np * 2 + 1][0], bh[np * 2 + 1][1],
                        sBh_u + off);
                LDSM_X4(bl[np * 2][0], bl[np * 2][1], bl[np * 2 + 1][0], bl[np * 2 + 1][1],
                        sBl_u + off);
            }
#pragma unroll
            for (int mi = 0; mi < 2; mi++) {
                uint32_t ah[4], al[4];
                uint32_t aoff = (uint32_t)((wr * 32 + mi * 16 + a_row) * ASTR_ +
                                           c * 32 + ks * 16 + a_colh) * 2;
                LDSM_X4(ah[0], ah[1], ah[2], ah[3], aH_u + aoff);
                LDSM_X4(al[0], al[1], al[2], al[3], aL_u + aoff);
#pragma unroll
                for (int ni = 0; ni < 4; ni++) {
                    MMA16816(acc[mi][ni], ah, bh[ni]);
                    MMA16816(acc[mi][ni], ah, bl[ni]);
                    MMA16816(acc[mi][ni], al, bh[ni]);
                }
            }
        }

        if ((cc & 7) == 7) {
            // tile epilogue: e = exp(v/rho), z = exp(v); write e; accumulate row stats
            int nt = cc >> 3;
            int n_base = nt * 128 + wc * 32 + tig * 2;
#pragma unroll
            for (int mi = 0; mi < 2; mi++) {
                int row0 = m0 + wr * 32 + mi * 16 + gid;
#pragma unroll
                for (int ni = 0; ni < 4; ni++) {
                    float v00 = acc[mi][ni][0] * 0.0625f;
                    float v01 = acc[mi][ni][1] * 0.0625f;
                    float v10 = acc[mi][ni][2] * 0.0625f;
                    float v11 = acc[mi][ni][3] * 0.0625f;
                    float e00 = __expf(fminf(fmaxf(v00 * invr, -60.f), 60.f));
                    float e01 = __expf(fminf(fmaxf(v01 * invr, -60.f), 60.f));
                    float e10 = __expf(fminf(fmaxf(v10 * invr, -60.f), 60.f));
                    float e11 = __expf(fminf(fmaxf(v11 * invr, -60.f), 60.f));
                    float z00 = __expf(fminf(fmaxf(v00, -60.f), 60.f));
                    float z01 = __expf(fminf(fmaxf(v01, -60.f), 60.f));
                    float z10 = __expf(fminf(fmaxf(v10, -60.f), 60.f));
                    float z11 = __expf(fminf(fmaxf(v11, -60.f), 60.f));
                    int col = n_base + ni * 8;
                    float2 w0 = {e00, e01}, w1 = {e10, e11};
                    *(float2*)(Ob + (size_t)row0 * N_ + col) = w0;
                    *(float2*)(Ob + (size_t)(row0 + 8) * N_ + col) = w1;
                    s_part[mi][0] += e00 + e01;
                    s_part[mi][1] += e10 + e11;
                    z_part[mi][0] += z00 + z01;
                    z_part[mi][1] += z10 + z11;
                    acc[mi][ni][0] = 0.f; acc[mi][ni][1] = 0.f;
                    acc[mi][ni][2] = 0.f; acc[mi][ni][3] = 0.f;
                }
            }
        }
        __syncthreads();
    }

    // ---- row stats reduction: quad shfl, then across wc warps via smem ----
    float* sred = (float*)(smem + B_OFF);
    float* zred = sred + 4 * 64;
#pragma unroll
    for (int mi = 0; mi < 2; mi++)
#pragma unroll
        for (int h = 0; h < 2; h++) {
            float s = s_part[mi][h];
            float z = z_part[mi][h];
            s += __shfl_down_sync(0xffffffffu, s, 1);
            s += __shfl_down_sync(0xffffffffu, s, 2);
            z += __shfl_down_sync(0xffffffffu, z, 1);
            z += __shfl_down_sync(0xffffffffu, z, 2);
            if (tig == 0) {
                int rl = wr * 32 + mi * 16 + h * 8 + gid;
                sred[wc * 64 + rl] = s;
                zred[wc * 64 + rl] = z;
            }
        }
    __syncthreads();
    if (tid < 64) {
        float s = sred[tid] + sred[64 + tid] + sred[128 + tid] + sred[192 + tid];
        float z = zred[tid] + zred[64 + tid] + zred[128 + tid] + zred[192 + tid];
        float cr = __expf(-invr * __logf(fmaxf(z, 1e-30f)));
        int grow = b * M_ + m0 + tid;
        g_R[grow] = cr;
        g_rowtmp[grow] = cr * s;
    }
}

// ---------------- initial global normalization ----------------
__global__ __launch_bounds__(256) void initg_kernel() {
    int b = blockIdx.x;
    float s = 0.f;
    for (int i = threadIdx.x; i < M_; i += 256) s += g_rowtmp[b * M_ + i];
    s = blockReduceSum(s);
    if (threadIdx.x == 0) g_g[b] = 1.0f / fmaxf(s, 1e-8f);
}

// ---------------- iteration 1 row scaling (multiplies cr already in g_R) ----------------
__global__ void initR_kernel() {
    int i = blockIdx.x * blockDim.x + threadIdx.x;
    if (i < B_ * M_) {
        int b = i >> 11;
        float rowsum = g_g[b] * g_rowtmp[i];
        g_R[i] *= fminf((1.0f / 2048.0f) / fmaxf(rowsum, 1e-8f), 1.0f);
    }
}

// ---------------- iteration 1 column partial sums ----------------
__global__ __launch_bounds__(256) void colsum_kernel(const float* __restrict__ K) {
    int b = blockIdx.x >> 6;
    int slice = blockIdx.x & 63;
    int i0 = slice * ROWS_PER_SLICE_;
    int tid = threadIdx.x;
    const float* base = K + ((size_t)(b << 11) + i0) * N_;
    float acc[8] = {0, 0, 0, 0, 0, 0, 0, 0};
    for (int r = 0; r < ROWS_PER_SLICE_; r++) {
        float Rv = g_R[(b << 11) + i0 + r];
        const float* P = base + (size_t)r * N_;
#pragma unroll
        for (int k = 0; k < 8; k++) acc[k] += P[tid + k * 256] * Rv;
    }
    float* out = g_colpart + (size_t)blockIdx.x * N_;
#pragma unroll
    for (int k = 0; k < 8; k++) out[tid + k * 256] = acc[k];
}

// ---------------- iterations 2-5: fused rowscale + colsum ----------------
#define FUSED_SMEM_BYTES (8 * N_ * 4)
__global__ __launch_bounds__(256) void fused_iter_kernel(const float* __restrict__ K) {
    extern __shared__ float ssum[];
    int b = blockIdx.x >> 6;
    int slice = blockIdx.x & 63;
    int i0 = slice * ROWS_PER_SLICE_;
    int wid = threadIdx.x >> 5, lane = threadIdx.x & 31;
    const float* Cp = g_C + (b << 11);
    float g = g_g[b];
    float acc[64];
#pragma unroll
    for (int q = 0; q < 64; q++) acc[q] = 0.f;

    for (int r = 0; r < 4; r++) {
        int row = (b << 11) + i0 + wid * 4 + r;
        const float* P = K + (size_t)row * N_;
        float d = 0.f;
#pragma unroll
        for (int q = 0; q < 64; q++) d += P[lane + 32 * q] * Cp[lane + 32 * q];
#pragma unroll
        for (int o = 16; o; o >>= 1) d += __shfl_xor_sync(0xffffffffu, d, o);
        float Rold = g_R[row];
        float rowsum = g * Rold * d;
        float Rnew = Rold * fminf((1.0f / 2048.0f) / fmaxf(rowsum, 1e-8f), 1.0f);
        if (lane == 0) g_R[row] = Rnew;
#pragma unroll
        for (int q = 0; q < 64; q++) acc[q] += P[lane + 32 * q] * Rnew;
    }
    float* myrow = ssum + wid * N_;
#pragma unroll
    for (int q = 0; q < 64; q++) myrow[lane + 32 * q] = acc[q];
    __syncthreads();
    float* outp = g_colpart + (size_t)blockIdx.x * N_;
    for (int j = threadIdx.x; j < N_; j += 256) {
        float t = 0.f;
#pragma unroll
        for (int w = 0; w < 8; w++) t += ssum[w * N_ + j];
        outp[j] = t;
    }
}

// ---------------- col scaling (parallel) + g update ----------------
__global__ __launch_bounds__(256) void colscale_part_kernel() {
    int b = blockIdx.x >> 3;
    int part = blockIdx.x & 7;
    int j = part * 256 + threadIdx.x;
    float g = g_g[b];
    float acc = 0.f;
    const float* cp = g_colpart + (size_t)(b << 6) * N_ + j;
#pragma unroll 8
    for (int s = 0; s < SLICES_; s++) acc += cp[(size_t)s * N_];
    int cj = (b << 11) + j;
    float colsum = g * g_C[cj] * acc;
    float cc = fminf((1.0f / 2048.0f) / fmaxf(colsum, 1e-8f), 1.0f);
    g_C[cj] *= cc;
    float tp = blockReduceSum(colsum * cc);
    if (threadIdx.x == 0) g_tppart[blockIdx.x] = tp;
}

__global__ void gfix_kernel() {
    int b = threadIdx.x;
    if (b < B_) {
        float tp = 0.f;
#pragma unroll
        for (int p = 0; p < 8; p++) tp += g_tppart[b * 8 + p];
        g_g[b] *= 1.0f / fmaxf(tp, 1e-8f);
    }
}

// ---------------- final ----------------
__global__ __launch_bounds__(256) void final_kernel(float* __restrict__ K,
                                                    const float* __restrict__ tgt) {
    int row = blockIdx.x;
    int b = row >> 11;
    int tid = threadIdx.x;
    float* P = K + (size_t)row * N_;
    const float* C = g_C + (b << 11);
    const float* t0 = tgt + (size_t)b * 3 * N_;
    const float* t1 = t0 + N_;
    const float* t2 = t0 + 2 * N_;
    float gR = g_g[b] * g_R[row];
    float s = 0.f, sx = 0.f, sy = 0.f, sz = 0.f;
#pragma unroll
    for (int k = 0; k < 8; k++) {
        int j = tid + k * 256;
        float val = P[j] * gR * C[j];
        P[j] = val;
        s += val;
        sx += val * t0[j];
        sy += val * t1[j];
        sz += val * t2[j];
    }
    s = blockReduceSum(s);
    sx = blockReduceSum(sx);
    sy = blockReduceSum(sy);
    sz = blockReduceSum(sz);
    if (tid == 0) {
        g_w[row] = s;
        g_numer[row * 3 + 0] = sx;
        g_numer[row * 3 + 1] = sy;
        g_numer[row * 3 + 2] = sz;
    }
}

// ---------------- rigid transform (fp64 Kabsch + Jacobi SVD) ----------------
__global__ __launch_bounds__(256) void rigid_kernel(const float* __restrict__ src,
                                                    float* __restrict__ out) {
    int b = blockIdx.x;
    int tid = threadIdx.x;
    const float* s0 = src + (size_t)b * 3 * M_;
    const float* s1 = s0 + M_;
    const float* s2 = s0 + 2 * M_;
    double acc[16];
#pragma unroll
    for (int q = 0; q < 16; q++) acc[q] = 0.0;
    for (int i = tid; i < M_; i += 256) {
        int row = (b << 11) + i;
        double w = (double)g_w[row];
        double dn = w + 1e-6;
        double bx = (double)g_numer[row * 3 + 0] / dn;
        double by = (double)g_numer[row * 3 + 1] / dn;
        double bz = (double)g_numer[row * 3 + 2] / dn;
        double ax = (double)s0[i], ay = (double)s1[i], az = (double)s2[i];
        acc[0] += w;
        acc[1] += w * ax; acc[2] += w * ay; acc[3] += w * az;
        acc[4] += w * bx; acc[5] += w * by; acc[6] += w * bz;
        acc[7]  += w * ax * bx; acc[8]  += w * ax * by; acc[9]  += w * ax * bz;
        acc[10] += w * ay * bx; acc[11] += w * ay * by; acc[12] += w * ay * bz;
        acc[13] += w * az * bx; acc[14] += w * az * by; acc[15] += w * az * bz;
    }
    __shared__ double sh[256];
    __shared__ double res[16];
    for (int q = 0; q < 16; q++) {
        sh[tid] = acc[q];
        __syncthreads();
        for (int off = 128; off > 0; off >>= 1) {
            if (tid < off) sh[tid] += sh[tid + off];
            __syncthreads();
        }
        if (tid == 0) res[q] = sh[0];
        __syncthreads();
    }
    if (tid != 0) return;

    double W2 = res[0] + 1e-6;
    double ca[3], cb[3];
#pragma unroll
    for (int i = 0; i < 3; i++) {
        ca[i] = res[1 + i] / W2;
        cb[i] = res[4 + i] / W2;
    }
    double sfac = 2.0 - res[0] / W2;
    double Cv[3][3];
#pragma unroll
    for (int i = 0; i < 3; i++)
#pragma unroll
        for (int j = 0; j < 3; j++)
            Cv[i][j] = res[7 + i * 3 + j] / W2 - sfac * ca[i] * cb[j];

    double A[3][3];
#pragma unroll
    for (int i = 0; i < 3; i++)
#pragma unroll
        for (int j = 0; j < 3; j++)
            A[i][j] = Cv[0][i] * Cv[0][j] + Cv[1][i] * Cv[1][j] + Cv[2][i] * Cv[2][j];
    double V[3][3] = {{1, 0, 0}, {0, 1, 0}, {0, 0, 1}};
    const int PP[3] = {0, 0, 1}, QQ[3] = {1, 2, 2};
    for (int sweep = 0; sweep < 30; sweep++) {
        double off = fabs(A[0][1]) + fabs(A[0][2]) + fabs(A[1][2]);
        if (off < 1e-28) break;
        for (int r = 0; r < 3; r++) {
            int p = PP[r], q = QQ[r];
            double apq = A[p][q];
            if (apq == 0.0) continue;
            double theta = (A[q][q] - A[p][p]) / (2.0 * apq);
            double t = ((theta >= 0.0) ? 1.0 : -1.0) / (fabs(theta) + sqrt(1.0 + theta * theta));
            double c = 1.0 / sqrt(1.0 + t * t);
            double s = t * c;
            for (int k = 0; k < 3; k++) {
                double akp = A[k][p], akq = A[k][q];
                A[k][p] = c * akp - s * akq;
                A[k][q] = s * akp + c * akq;
            }
            for (int k = 0; k < 3; k++) {
                double apk = A[p][k], aqk = A[q][k];
                A[p][k] = c * apk - s * aqk;
                A[q][k] = s * apk + c * aqk;
            }
            for (int k = 0; k < 3; k++) {
                double vkp = V[k][p], vkq = V[k][q];
                V[k][p] = c * vkp - s * vkq;
                V[k][q] = s * vkp + c * vkq;
            }
        }
    }
    double d[3] = {A[0][0], A[1][1], A[2][2]};
    for (int i = 0; i < 2; i++)
        for (int j = i + 1; j < 3; j++)
            if (d[j] > d[i]) {
                double tmp = d[i]; d[i] = d[j]; d[j] = tmp;
                for (int k = 0; k < 3; k++) {
                    double tv = V[k][i]; V[k][i] = V[k][j]; V[k][j] = tv;
                }
            }
    double U[3][3];
    double nrm[3];
#pragma unroll
    for (int k = 0; k < 3; k++) {
        double u0 = Cv[0][0] * V[0][k] + Cv[0][1] * V[1][k] + Cv[0][2] * V[2][k];
        double u1 = Cv[1][0] * V[0][k] + Cv[1][1] * V[1][k] + Cv[1][2] * V[2][k];
        double u2 = Cv[2][0] * V[0][k] + Cv[2][1] * V[1][k] + Cv[2][2] * V[2][k];
        double n = sqrt(u0 * u0 + u1 * u1 + u2 * u2);
        nrm[k] = n;
        if (n > 1e-30) {
            U[0][k] = u0 / n; U[1][k] = u1 / n; U[2][k] = u2 / n;
        } else {
            U[0][k] = 0.0; U[1][k] = 0.0; U[2][k] = 0.0;
        }
    }
    if (nrm[2] <= 1e-12 * fmax(nrm[0], 1e-30)) {
        double cx = U[1][0] * U[2][1] - U[2][0] * U[1][1];
        double cy = U[2][0] * U[0][1] - U[0][0] * U[2][1];
        double cz = U[0][0] * U[1][1] - U[1][0] * U[0][1];
        double n = sqrt(cx * cx + cy * cy + cz * cz);
        if (n > 1e-30) { U[0][2] = cx / n; U[1][2] = cy / n; U[2][2] = cz / n; }
    }
    double R[3][3];
#pragma unroll
    for (int i = 0; i < 3; i++)
#pragma unroll
        for (int j = 0; j < 3; j++)
            R[i][j] = V[i][0] * U[j][0] + V[i][1] * U[j][1] + V[i][2] * U[j][2];
    double det = R[0][0] * (R[1][1] * R[2][2] - R[1][2] * R[2][1])
               - R[0][1] * (R[1][0] * R[2][2] - R[1][2] * R[2][0])
               + R[0][2] * (R[1][0] * R[2][1] - R[1][1] * R[2][0]);
    if (!(det > 0.0)) {
#pragma unroll
        for (int i = 0; i < 3; i++)
#pragma unroll
            for (int j = 0; j < 3; j++)
                R[i][j] -= 2.0 * V[i][2] * U[j][2];
    }
    double tr[3];
#pragma unroll
    for (int i = 0; i < 3; i++)
        tr[i] = cb[i] - (R[i][0] * ca[0] + R[i][1] * ca[1] + R[i][2] * ca[2]);

#pragma unroll
    for (int i = 0; i < 3; i++)
#pragma unroll
        for (int j = 0; j < 3; j++)
            out[b * 9 + i * 3 + j] = (float)R[i][j];
#pragma unroll
    for (int i = 0; i < 3; i++) out[144 + b * 3 + i] = (float)tr[i];
}

// ---------------- launch ----------------
extern "C" void kernel_launch(void* const* d_in, const int* in_sizes, int n_in,
                              void* d_out, int out_size) {
    (void)in_sizes; (void)n_in; (void)out_size;
    const float* se  = (const float*)d_in[0];
    const float* te  = (const float*)d_in[1];
    const float* src = (const float*)d_in[2];
    const float* tgt = (const float*)d_in[3];
    const float* rho = (const float*)d_in[4];
    float* out = (float*)d_out;
    float* Kmat = out + 192;

    static int attr_done = 0;
    if (!attr_done) {
        cudaFuncSetAttribute(gemm_fused_kernel, cudaFuncAttributeMaxDynamicSharedMemorySize,
                             GEMM_SMEM_BYTES);
        cudaFuncSetAttribute(fused_iter_kernel, cudaFuncAttributeMaxDynamicSharedMemorySize,
                             FUSED_SMEM_BYTES);
        attr_done = 1;
    }

    init_kernel<<<(B_ * N_ + 255) / 256, 256>>>();
    __nv_bfloat16 *bh, *bl;
    cudaGetSymbolAddress((void**)&bh, g_BH);
    cudaGetSymbolAddress((void**)&bl, g_BL);
    split_transpose_kernel<<<dim3(N_ / 32, D_ / 32, B_), 256>>>(te, bh, bl);
    gemm_fused_kernel<<<dim3(M_ / 64, B_), 256, GEMM_SMEM_BYTES>>>(Kmat, se, rho);
    initg_kernel<<<B_, 256>>>();
    initR_kernel<<<(B_ * M_ + 255) / 256, 256>>>();
    colsum_kernel<<<B_ * SLICES_, 256>>>(Kmat);
    colscale_part_kernel<<<B_ * 8, 256>>>();
    gfix_kernel<<<1, 32>>>();
    for (int it = 0; it < 4; it++) {
        fused_iter_kernel<<<B_ * SLICES_, 256, FUSED_SMEM_BYTES>>>(Kmat);
        colscale_part_kernel<<<B_ * 8, 256>>>();
        gfix_kernel<<<1, 32>>>();
    }
    final_kernel<<<B_ * M_, 256>>>(Kmat, tgt);
    rigid_kernel<<<B_, 256>>>(src, out);
}

// round 9
// speedup vs baseline: 1.7038x; 1.0589x over previous
#include <cuda_runtime.h>
#include <cuda_bf16.h>
#include <math.h>
#include <stdint.h>

#define B_ 16
#define D_ 256
#define M_ 2048
#define N_ 2048
#define SLICES_ 64
#define ROWS_PER_SLICE_ 32

// ---------------- scratch (static device arrays; no allocation) ----------------
__device__ float g_R[B_ * M_];
__device__ float g_C[B_ * N_];
__device__ float g_rowtmp[B_ * M_];
__device__ float g_colpart[B_ * SLICES_ * N_];
__device__ float g_g[B_];
__device__ float g_tppart[B_ * 8];
__device__ float g_w[B_ * M_];
__device__ float g_numer[B_ * M_ * 3];
__device__ __nv_bfloat16 g_BH[B_ * N_ * D_];
__device__ __nv_bfloat16 g_BL[B_ * N_ * D_];
__device__ __nv_bfloat16 g_Kb[(size_t)B_ * M_ * N_];  // bf16 shadow of K0' (128 MB)

// ---------------- helpers ----------------
__device__ __forceinline__ uint32_t smem_u32(const void* p) {
    uint32_t a;
    asm("{ .reg .u64 t; cvta.to.shared.u64 t, %1; cvt.u32.u64 %0, t; }" : "=r"(a) : "l"(p));
    return a;
}

#define LDSM_X4(r0, r1, r2, r3, addr) \
    asm volatile("ldmatrix.sync.aligned.m8n8.x4.shared.b16 {%0,%1,%2,%3}, [%4];" \
                 : "=r"(r0), "=r"(r1), "=r"(r2), "=r"(r3) : "r"(addr))

#define MMA16816(d, a, bq) \
    asm volatile( \
        "mma.sync.aligned.m16n8k16.row.col.f32.bf16.bf16.f32 " \
        "{%0,%1,%2,%3}, {%4,%5,%6,%7}, {%8,%9}, {%0,%1,%2,%3};" \
        : "+f"((d)[0]), "+f"((d)[1]), "+f"((d)[2]), "+f"((d)[3]) \
        : "r"((a)[0]), "r"((a)[1]), "r"((a)[2]), "r"((a)[3]), \
          "r"((bq)[0]), "r"((bq)[1]))

#define CP_ASYNC16(sa, ga) \
    asm volatile("cp.async.cg.shared.global [%0], [%1], 16;" :: "r"(sa), "l"(ga))

#define PACK_BF16X2(r, lo, hi) \
    asm("cvt.rn.bf16x2.f32 %0, %1, %2;" : "=r"(r) : "f"(hi), "f"(lo))

__device__ __forceinline__ float bf_lo(uint32_t x) { return __uint_as_float(x << 16); }
__device__ __forceinline__ float bf_hi(uint32_t x) { return __uint_as_float(x & 0xffff0000u); }

// ---------------- block reductions ----------------
__device__ __forceinline__ float blockReduceSum(float v) {
    __shared__ float sh[33];
    int lane = threadIdx.x & 31, w = threadIdx.x >> 5;
#pragma unroll
    for (int o = 16; o; o >>= 1) v += __shfl_down_sync(0xffffffffu, v, o);
    if (lane == 0) sh[w] = v;
    __syncthreads();
    if (w == 0) {
        v = (lane < (int)(blockDim.x >> 5)) ? sh[lane] : 0.f;
#pragma unroll
        for (int o = 16; o; o >>= 1) v += __shfl_down_sync(0xffffffffu, v, o);
        if (lane == 0) sh[32] = v;
    }
    __syncthreads();
    float r = sh[32];
    __syncthreads();
    return r;
}

// ---------------- init: C = 1 ----------------
__global__ void init_kernel() {
    int i = blockIdx.x * blockDim.x + threadIdx.x;
    if (i < B_ * N_) g_C[i] = 1.0f;
}

// ---------------- transpose + bf16 hi/lo split for B (te) only ----------------
__global__ __launch_bounds__(256) void split_transpose_kernel(const float* __restrict__ X,
                                                              __nv_bfloat16* __restrict__ H,
                                                              __nv_bfloat16* __restrict__ L) {
    __shared__ float t[32][33];
    int b = blockIdx.z;
    int m0 = blockIdx.x * 32, d0 = blockIdx.y * 32;
    const float* Xb = X + (size_t)b * D_ * M_;
    int tx = threadIdx.x & 31, ty = threadIdx.x >> 5;
#pragma unroll
    for (int i = 0; i < 4; i++) {
        int d = d0 + ty + i * 8;
        t[ty + i * 8][tx] = Xb[(size_t)d * M_ + m0 + tx];
    }
    __syncthreads();
#pragma unroll
    for (int i = 0; i < 4; i++) {
        int m = m0 + ty + i * 8;
        float v = t[tx][ty + i * 8];
        __nv_bfloat16 h = __float2bfloat16(v);
        __nv_bfloat16 l = __float2bfloat16(v - __bfloat162float(h));
        size_t o = ((size_t)b * M_ + m) * D_ + d0 + tx;
        H[o] = h;
        L[o] = l;
    }
}

// ---------------- fused GEMM + exp + row stats (+ bf16 shadow write) ----------------
#define ASTR_ 264
#define SMS_ 40
#define A_H_OFF 0
#define A_L_OFF (64 * ASTR_ * 2)
#define B_OFF (2 * 64 * ASTR_ * 2)
#define B_MAT_BYTES (128 * SMS_ * 2)
#define B_STAGE_BYTES (2 * B_MAT_BYTES)
#define GEMM_SMEM_BYTES (B_OFF + 2 * B_STAGE_BYTES)

__global__ __launch_bounds__(256, 2) void gemm_fused_kernel(float* __restrict__ OUT,
                                                            const float* __restrict__ SE,
                                                            const float* __restrict__ rho_p) {
    extern __shared__ __align__(16) char smem[];
    uint32_t smb = smem_u32(smem);
    int tid = threadIdx.x, wid = tid >> 5, lane = tid & 31;
    int mt = blockIdx.x, b = blockIdx.y;
    int m0 = mt * 64;
    int wr = wid >> 2, wc = wid & 3;
    int gid = lane >> 2, tig = lane & 3;

    float rho = fmaxf(rho_p[0], 1e-8f);
    float invr = 1.0f / rho;

    {
        const float* Ab = SE + (size_t)b * D_ * M_ + m0;
        int dd = tid >> 6, j = tid & 63;
        __nv_bfloat16* aH = (__nv_bfloat16*)(smem + A_H_OFF);
        __nv_bfloat16* aL = (__nv_bfloat16*)(smem + A_L_OFF);
        for (int d0 = 0; d0 < D_; d0 += 4) {
            int d = d0 + dd;
            float v = Ab[(size_t)d * M_ + j];
            __nv_bfloat16 h = __float2bfloat16(v);
            __nv_bfloat16 l = __float2bfloat16(v - __bfloat162float(h));
            int off = j * ASTR_ + d;
            aH[off] = h;
            aL[off] = l;
        }
    }
    __syncthreads();

    float acc[2][4][4];
#pragma unroll
    for (int mi = 0; mi < 2; mi++)
#pragma unroll
        for (int ni = 0; ni < 4; ni++)
#pragma unroll
            for (int r = 0; r < 4; r++) acc[mi][ni][r] = 0.f;

    float s_part[2][2] = {{0, 0}, {0, 0}};
    float z_part[2][2] = {{0, 0}, {0, 0}};

    int i0 = tid * 2, i1 = tid * 2 + 1;
    int r0_ = i0 >> 2, s0_ = i0 & 3;
    int r1_ = i1 >> 2, s1_ = i1 & 3;
    uint32_t d00 = (uint32_t)(r0_ * SMS_ + s0_ * 8) * 2;
    uint32_t d01 = (uint32_t)(r1_ * SMS_ + s1_ * 8) * 2;

    const __nv_bfloat16* BHb = g_BH + (size_t)b * N_ * D_;
    const __nv_bfloat16* BLb = g_BL + (size_t)b * N_ * D_;

    int a_row = (lane & 15), a_colh = (lane >> 4) * 8;
    int b_tile = lane >> 3, b_r8 = lane & 7;
    int b_n = ((b_tile >> 1) * 8) + b_r8;
    int b_k = (b_tile & 1) * 8;

    auto load_chunk = [&](int cc) {
        int nt = cc >> 3, c = cc & 7;
        uint32_t base = smb + B_OFF + (uint32_t)(cc & 1) * B_STAGE_BYTES;
        const __nv_bfloat16* Bh = BHb + (size_t)(nt * 128) * D_ + c * 32;
        const __nv_bfloat16* Bl = BLb + (size_t)(nt * 128) * D_ + c * 32;
        size_t g00 = (size_t)r0_ * D_ + s0_ * 8;
        size_t g01 = (size_t)r1_ * D_ + s1_ * 8;
        CP_ASYNC16(base + d00, Bh + g00);
        CP_ASYNC16(base + d01, Bh + g01);
        CP_ASYNC16(base + B_MAT_BYTES + d00, Bl + g00);
        CP_ASYNC16(base + B_MAT_BYTES + d01, Bl + g01);
        asm volatile("cp.async.commit_group;" ::: "memory");
    };

    load_chunk(0);
    float* Ob = OUT + (size_t)b * M_ * N_;
    __nv_bfloat16* Kbb = g_Kb + (size_t)b * M_ * N_;

    for (int cc = 0; cc < 128; cc++) {
        if (cc < 127) load_chunk(cc + 1);
        if (cc < 127)
            asm volatile("cp.async.wait_group 1;" ::: "memory");
        else
            asm volatile("cp.async.wait_group 0;" ::: "memory");
        __syncthreads();

        int c = cc & 7;
        uint32_t bbase = smb + B_OFF + (uint32_t)(cc & 1) * B_STAGE_BYTES;
        uint32_t sBh_u = bbase, sBl_u = bbase + B_MAT_BYTES;
        uint32_t aH_u = smb + A_H_OFF;
        uint32_t aL_u = smb + A_L_OFF;

#pragma unroll
        for (int ks = 0; ks < 2; ks++) {
            uint32_t bh[4][2], bl[4][2];
#pragma unroll
            for (int np = 0; np < 2; np++) {
                uint32_t off = (uint32_t)((wc * 32 + np * 16 + b_n) * SMS_ + ks * 16 + b_k) * 2;
                LDSM_X4(bh[np * 2][0], bh[np * 2][1], bh[np * 2 + 1][0], bh[np * 2 + 1][1],
                        sBh_u + off);
                LDSM_X4(bl[np * 2][0], bl[np * 2][1], bl[np * 2 + 1][0], bl[np * 2 + 1][1],
                        sBl_u + off);
            }
#pragma unroll
            for (int mi = 0; mi < 2; mi++) {
                uint32_t ah[4], al[4];
                uint32_t aoff = (uint32_t)((wr * 32 + mi * 16 + a_row) * ASTR_ +
                                           c * 32 + ks * 16 + a_colh) * 2;
                LDSM_X4(ah[0], ah[1], ah[2], ah[3], aH_u + aoff);
                LDSM_X4(al[0], al[1], al[2], al[3], aL_u + aoff);
#pragma unroll
                for (int ni = 0; ni < 4; ni++) {
                    MMA16816(acc[mi][ni], ah, bh[ni]);
                    MMA16816(acc[mi][ni], ah, bl[ni]);
                    MMA16816(acc[mi][ni], al, bh[ni]);
                }
            }
        }

        if ((cc & 7) == 7) {
            int nt = cc >> 3;
            int n_base = nt * 128 + wc * 32 + tig * 2;
#pragma unroll
            for (int mi = 0; mi < 2; mi++) {
                int row0 = m0 + wr * 32 + mi * 16 + gid;
#pragma unroll
                for (int ni = 0; ni < 4; ni++) {
                    float v00 = acc[mi][ni][0] * 0.0625f;
                    float v01 = acc[mi][ni][1] * 0.0625f;
                    float v10 = acc[mi][ni][2] * 0.0625f;
                    float v11 = acc[mi][ni][3] * 0.0625f;
                    float e00 = __expf(fminf(fmaxf(v00 * invr, -60.f), 60.f));
                    float e01 = __expf(fminf(fmaxf(v01 * invr, -60.f), 60.f));
                    float e10 = __expf(fminf(fmaxf(v10 * invr, -60.f), 60.f));
                    float e11 = __expf(fminf(fmaxf(v11 * invr, -60.f), 60.f));
                    float z00 = __expf(fminf(fmaxf(v00, -60.f), 60.f));
                    float z01 = __expf(fminf(fmaxf(v01, -60.f), 60.f));
                    float z10 = __expf(fminf(fmaxf(v10, -60.f), 60.f));
                    float z11 = __expf(fminf(fmaxf(v11, -60.f), 60.f));
                    int col = n_base + ni * 8;
                    float2 w0 = {e00, e01}, w1 = {e10, e11};
                    *(float2*)(Ob + (size_t)row0 * N_ + col) = w0;
                    *(float2*)(Ob + (size_t)(row0 + 8) * N_ + col) = w1;
                    uint32_t p0, p1;
                    PACK_BF16X2(p0, e00, e01);
                    PACK_BF16X2(p1, e10, e11);
                    *(uint32_t*)(Kbb + (size_t)row0 * N_ + col) = p0;
                    *(uint32_t*)(Kbb + (size_t)(row0 + 8) * N_ + col) = p1;
                    s_part[mi][0] += e00 + e01;
                    s_part[mi][1] += e10 + e11;
                    z_part[mi][0] += z00 + z01;
                    z_part[mi][1] += z10 + z11;
                    acc[mi][ni][0] = 0.f; acc[mi][ni][1] = 0.f;
                    acc[mi][ni][2] = 0.f; acc[mi][ni][3] = 0.f;
                }
            }
        }
        __syncthreads();
    }

    float* sred = (float*)(smem + B_OFF);
    float* zred = sred + 4 * 64;
#pragma unroll
    for (int mi = 0; mi < 2; mi++)
#pragma unroll
        for (int h = 0; h < 2; h++) {
            float s = s_part[mi][h];
            float z = z_part[mi][h];
            s += __shfl_down_sync(0xffffffffu, s, 1);
            s += __shfl_down_sync(0xffffffffu, s, 2);
            z += __shfl_down_sync(0xffffffffu, z, 1);
            z += __shfl_down_sync(0xffffffffu, z, 2);
            if (tig == 0) {
                int rl = wr * 32 + mi * 16 + h * 8 + gid;
                sred[wc * 64 + rl] = s;
                zred[wc * 64 + rl] = z;
            }
        }
    __syncthreads();
    if (tid < 64) {
        float s = sred[tid] + sred[64 + tid] + sred[128 + tid] + sred[192 + tid];
        float z = zred[tid] + zred[64 + tid] + zred[128 + tid] + zred[192 + tid];
        float cr = __expf(-invr * __logf(fmaxf(z, 1e-30f)));
        int grow = b * M_ + m0 + tid;
        g_R[grow] = cr;
        g_rowtmp[grow] = cr * s;
    }
}

// ---------------- initial global normalization ----------------
__global__ __launch_bounds__(256) void initg_kernel() {
    int b = blockIdx.x;
    float s = 0.f;
    for (int i = threadIdx.x; i < M_; i += 256) s += g_rowtmp[b * M_ + i];
    s = blockReduceSum(s);
    if (threadIdx.x == 0) g_g[b] = 1.0f / fmaxf(s, 1e-8f);
}

// ---------------- iteration 1 row scaling ----------------
__global__ void initR_kernel() {
    int i = blockIdx.x * blockDim.x + threadIdx.x;
    if (i < B_ * M_) {
        int b = i >> 11;
        float rowsum = g_g[b] * g_rowtmp[i];
        g_R[i] *= fminf((1.0f / 2048.0f) / fmaxf(rowsum, 1e-8f), 1.0f);
    }
}

// ---------------- iteration 1 column partial sums (bf16 reads) ----------------
__global__ __launch_bounds__(256) void colsum_kernel() {
    int b = blockIdx.x >> 6;
    int slice = blockIdx.x & 63;
    int i0 = slice * ROWS_PER_SLICE_;
    int tid = threadIdx.x;
    const uint32_t* base = (const uint32_t*)(g_Kb + ((size_t)(b << 11) + i0) * N_);
    float acc[8] = {0, 0, 0, 0, 0, 0, 0, 0};
    for (int r = 0; r < ROWS_PER_SLICE_; r++) {
        float Rv = g_R[(b << 11) + i0 + r];
        const uint32_t* P = base + (size_t)r * (N_ / 2);
#pragma unroll
        for (int q = 0; q < 4; q++) {
            uint32_t x = P[tid + q * 256];
            acc[2 * q] += bf_lo(x) * Rv;
            acc[2 * q + 1] += bf_hi(x) * Rv;
        }
    }
    float* outp = g_colpart + (size_t)blockIdx.x * N_;
#pragma unroll
    for (int q = 0; q < 4; q++) {
        float2 v = {acc[2 * q], acc[2 * q + 1]};
        *(float2*)(outp + 2 * (tid + q * 256)) = v;
    }
}

// ---------------- iterations 2-5: fused rowscale + colsum, bf16, row in registers ----------------
#define FUSED_SMEM_BYTES (8 * N_ * 4)
__global__ __launch_bounds__(256) void fused_iter_kernel() {
    extern __shared__ float ssum[];
    int b = blockIdx.x >> 6;
    int slice = blockIdx.x & 63;
    int i0 = slice * ROWS_PER_SLICE_;
    int wid = threadIdx.x >> 5, lane = threadIdx.x & 31;
    const float* Cp = g_C + (b << 11);
    float g = g_g[b];
    float acc[64];
#pragma unroll
    for (int q = 0; q < 64; q++) acc[q] = 0.f;

    const uint32_t* Kb32 = (const uint32_t*)(g_Kb + (size_t)(b << 11) * N_);

    for (int r = 0; r < 4; r++) {
        int rowl = i0 + wid * 4 + r;
        int row = (b << 11) + rowl;
        const uint32_t* P = Kb32 + (size_t)rowl * (N_ / 2);
        uint32_t x[32];
#pragma unroll
        for (int q = 0; q < 32; q++) x[q] = P[lane + 32 * q];
        float d = 0.f;
#pragma unroll
        for (int q = 0; q < 32; q++) {
            float2 cv = *(const float2*)(Cp + 2 * (lane + 32 * q));
            d += bf_lo(x[q]) * cv.x + bf_hi(x[q]) * cv.y;
        }
#pragma unroll
        for (int o = 16; o; o >>= 1) d += __shfl_xor_sync(0xffffffffu, d, o);
        float Rold = g_R[row];
        float rowsum = g * Rold * d;
        float Rnew = Rold * fminf((1.0f / 2048.0f) / fmaxf(rowsum, 1e-8f), 1.0f);
        if (lane == 0) g_R[row] = Rnew;
#pragma unroll
        for (int q = 0; q < 32; q++) {
            acc[2 * q] += bf_lo(x[q]) * Rnew;
            acc[2 * q + 1] += bf_hi(x[q]) * Rnew;
        }
    }
    float* myrow = ssum + wid * N_;
#pragma unroll
    for (int q = 0; q < 32; q++) {
        float2 v = {acc[2 * q], acc[2 * q + 1]};
        *(float2*)(myrow + 2 * (lane + 32 * q)) = v;
    }
    __syncthreads();
    float* outp = g_colpart + (size_t)blockIdx.x * N_;
    for (int j = threadIdx.x; j < N_; j += 256) {
        float t = 0.f;
#pragma unroll
        for (int w = 0; w < 8; w++) t += ssum[w * N_ + j];
        outp[j] = t;
    }
}

// ---------------- col scaling (parallel) + g update ----------------
__global__ __launch_bounds__(256) void colscale_part_kernel() {
    int b = blockIdx.x >> 3;
    int part = blockIdx.x & 7;
    int j = part * 256 + threadIdx.x;
    float g = g_g[b];
    float acc = 0.f;
    const float* cp = g_colpart + (size_t)(b << 6) * N_ + j;
#pragma unroll 8
    for (int s = 0; s < SLICES_; s++) acc += cp[(size_t)s * N_];
    int cj = (b << 11) + j;
    float colsum = g * g_C[cj] * acc;
    float cc = fminf((1.0f / 2048.0f) / fmaxf(colsum, 1e-8f), 1.0f);
    g_C[cj] *= cc;
    float tp = blockReduceSum(colsum * cc);
    if (threadIdx.x == 0) g_tppart[blockIdx.x] = tp;
}

__global__ void gfix_kernel() {
    int b = threadIdx.x;
    if (b < B_) {
        float tp = 0.f;
#pragma unroll
        for (int p = 0; p < 8; p++) tp += g_tppart[b * 8 + p];
        g_g[b] *= 1.0f / fmaxf(tp, 1e-8f);
    }
}

// ---------------- final: fp32 K0 read, matches written in place ----------------
__global__ __launch_bounds__(256) void final_kernel(float* __restrict__ K,
                                                    const float* __restrict__ tgt) {
    int row = blockIdx.x;
    int b = row >> 11;
    int tid = threadIdx.x;
    float* P = K + (size_t)row * N_;
    const float* C = g_C + (b << 11);
    const float* t0 = tgt + (size_t)b * 3 * N_;
    const float* t1 = t0 + N_;
    const float* t2 = t0 + 2 * N_;
    float gR = g_g[b] * g_R[row];
    float s = 0.f, sx = 0.f, sy = 0.f, sz = 0.f;
#pragma unroll
    for (int k = 0; k < 8; k++) {
        int j = tid + k * 256;
        float val = P[j] * gR * C[j];
        P[j] = val;
        s += val;
        sx += val * t0[j];
        sy += val * t1[j];
        sz += val * t2[j];
    }
    s = blockReduceSum(s);
    sx = blockReduceSum(sx);
    sy = blockReduceSum(sy);
    sz = blockReduceSum(sz);
    if (tid == 0) {
        g_w[row] = s;
        g_numer[row * 3 + 0] = sx;
        g_numer[row * 3 + 1] = sy;
        g_numer[row * 3 + 2] = sz;
    }
}

// ---------------- rigid transform (fp64 Kabsch + Jacobi SVD) ----------------
__global__ __launch_bounds__(256) void rigid_kernel(const float* __restrict__ src,
                                                    float* __restrict__ out) {
    int b = blockIdx.x;
    int tid = threadIdx.x;
    const float* s0 = src + (size_t)b * 3 * M_;
    const float* s1 = s0 + M_;
    const float* s2 = s0 + 2 * M_;
    double acc[16];
#pragma unroll
    for (int q = 0; q < 16; q++) acc[q] = 0.0;
    for (int i = tid; i < M_; i += 256) {
        int row = (b << 11) + i;
        double w = (double)g_w[row];
        double dn = w + 1e-6;
        double bx = (double)g_numer[row * 3 + 0] / dn;
        double by = (double)g_numer[row * 3 + 1] / dn;
        double bz = (double)g_numer[row * 3 + 2] / dn;
        double ax = (double)s0[i], ay = (double)s1[i], az = (double)s2[i];
        acc[0] += w;
        acc[1] += w * ax; acc[2] += w * ay; acc[3] += w * az;
        acc[4] += w * bx; acc[5] += w * by; acc[6] += w * bz;
        acc[7]  += w * ax * bx; acc[8]  += w * ax * by; acc[9]  += w * ax * bz;
        acc[10] += w * ay * bx; acc[11] += w * ay * by; acc[12] += w * ay * bz;
        acc[13] += w * az * bx; acc[14] += w * az * by; acc[15] += w * az * bz;
    }
    __shared__ double sh[256];
    __shared__ double res[16];
    for (int q = 0; q < 16; q++) {
        sh[tid] = acc[q];
        __syncthreads();
        for (int off = 128; off > 0; off >>= 1) {
            if (tid < off) sh[tid] += sh[tid + off];
            __syncthreads();
        }
        if (tid == 0) res[q] = sh[0];
        __syncthreads();
    }
    if (tid != 0) return;

    double W2 = res[0] + 1e-6;
    double ca[3], cb[3];
#pragma unroll
    for (int i = 0; i < 3; i++) {
        ca[i] = res[1 + i] / W2;
        cb[i] = res[4 + i] / W2;
    }
    double sfac = 2.0 - res[0] / W2;
    double Cv[3][3];
#pragma unroll
    for (int i = 0; i < 3; i++)
#pragma unroll
        for (int j = 0; j < 3; j++)
            Cv[i][j] = res[7 + i * 3 + j] / W2 - sfac * ca[i] * cb[j];

    double A[3][3];
#pragma unroll
    for (int i = 0; i < 3; i++)
#pragma unroll
        for (int j = 0; j < 3; j++)
            A[i][j] = Cv[0][i] * Cv[0][j] + Cv[1][i] * Cv[1][j] + Cv[2][i] * Cv[2][j];
    double V[3][3] = {{1, 0, 0}, {0, 1, 0}, {0, 0, 1}};
    const int PP[3] = {0, 0, 1}, QQ[3] = {1, 2, 2};
    for (int sweep = 0; sweep < 30; sweep++) {
        double off = fabs(A[0][1]) + fabs(A[0][2]) + fabs(A[1][2]);
        if (off < 1e-28) break;
        for (int r = 0; r < 3; r++) {
            int p = PP[r], q = QQ[r];
            double apq = A[p][q];
            if (apq == 0.0) continue;
            double theta = (A[q][q] - A[p][p]) / (2.0 * apq);
            double t = ((theta >= 0.0) ? 1.0 : -1.0) / (fabs(theta) + sqrt(1.0 + theta * theta));
            double c = 1.0 / sqrt(1.0 + t * t);
            double s = t * c;
            for (int k = 0; k < 3; k++) {
                double akp = A[k][p], akq = A[k][q];
                A[k][p] = c * akp - s * akq;
                A[k][q] = s * akp + c * akq;
            }
            for (int k = 0; k < 3; k++) {
                double apk = A[p][k], aqk = A[q][k];
                A[p][k] = c * apk - s * aqk;
                A[q][k] = s * apk + c * aqk;
            }
            for (int k = 0; k < 3; k++) {
                double vkp = V[k][p], vkq = V[k][q];
                V[k][p] = c * vkp - s * vkq;
                V[k][q] = s * vkp + c * vkq;
            }
        }
    }
    double d[3] = {A[0][0], A[1][1], A[2][2]};
    for (int i = 0; i < 2; i++)
        for (int j = i + 1; j < 3; j++)
            if (d[j] > d[i]) {
                double tmp = d[i]; d[i] = d[j]; d[j] = tmp;
                for (int k = 0; k < 3; k++) {
                    double tv = V[k][i]; V[k][i] = V[k][j]; V[k][j] = tv;
                }
            }
    double U[3][3];
    double nrm[3];
#pragma unroll
    for (int k = 0; k < 3; k++) {
        double u0 = Cv[0][0] * V[0][k] + Cv[0][1] * V[1][k] + Cv[0][2] * V[2][k];
        double u1 = Cv[1][0] * V[0][k] + Cv[1][1] * V[1][k] + Cv[1][2] * V[2][k];
        double u2 = Cv[2][0] * V[0][k] + Cv[2][1] * V[1][k] + Cv[2][2] * V[2][k];
        double n = sqrt(u0 * u0 + u1 * u1 + u2 * u2);
        nrm[k] = n;
        if (n > 1e-30) {
            U[0][k] = u0 / n; U[1][k] = u1 / n; U[2][k] = u2 / n;
        } else {
            U[0][k] = 0.0; U[1][k] = 0.0; U[2][k] = 0.0;
        }
    }
    if (nrm[2] <= 1e-12 * fmax(nrm[0], 1e-30)) {
        double cx = U[1][0] * U[2][1] - U[2][0] * U[1][1];
        double cy = U[2][0] * U[0][1] - U[0][0] * U[2][1];
        double cz = U[0][0] * U[1][1] - U[1][0] * U[0][1];
        double n = sqrt(cx * cx + cy * cy + cz * cz);
        if (n > 1e-30) { U[0][2] = cx / n; U[1][2] = cy / n; U[2][2] = cz / n; }
    }
    double R[3][3];
#pragma unroll
    for (int i = 0; i < 3; i++)
#pragma unroll
        for (int j = 0; j < 3; j++)
            R[i][j] = V[i][0] * U[j][0] + V[i][1] * U[j][1] + V[i][2] * U[j][2];
    double det = R[0][0] * (R[1][1] * R[2][2] - R[1][2] * R[2][1])
               - R[0][1] * (R[1][0] * R[2][2] - R[1][2] * R[2][0])
               + R[0][2] * (R[1][0] * R[2][1] - R[1][1] * R[2][0]);
    if (!(det > 0.0)) {
#pragma unroll
        for (int i = 0; i < 3; i++)
#pragma unroll
            for (int j = 0; j < 3; j++)
                R[i][j] -= 2.0 * V[i][2] * U[j][2];
    }
    double tr[3];
#pragma unroll
    for (int i = 0; i < 3; i++)
        tr[i] = cb[i] - (R[i][0] * ca[0] + R[i][1] * ca[1] + R[i][2] * ca[2]);

#pragma unroll
    for (int i = 0; i < 3; i++)
#pragma unroll
        for (int j = 0; j < 3; j++)
            out[b * 9 + i * 3 + j] = (float)R[i][j];
#pragma unroll
    for (int i = 0; i < 3; i++) out[144 + b * 3 + i] = (float)tr[i];
}

// ---------------- launch ----------------
extern "C" void kernel_launch(void* const* d_in, const int* in_sizes, int n_in,
                              void* d_out, int out_size) {
    (void)in_sizes; (void)n_in; (void)out_size;
    const float* se  = (const float*)d_in[0];
    const float* te  = (const float*)d_in[1];
    const float* src = (const float*)d_in[2];
    const float* tgt = (const float*)d_in[3];
    const float* rho = (const float*)d_in[4];
    float* out = (float*)d_out;
    float* Kmat = out + 192;

    static int attr_done = 0;
    if (!attr_done) {
        cudaFuncSetAttribute(gemm_fused_kernel, cudaFuncAttributeMaxDynamicSharedMemorySize,
                             GEMM_SMEM_BYTES);
        cudaFuncSetAttribute(fused_iter_kernel, cudaFuncAttributeMaxDynamicSharedMemorySize,
                             FUSED_SMEM_BYTES);
        attr_done = 1;
    }

    init_kernel<<<(B_ * N_ + 255) / 256, 256>>>();
    __nv_bfloat16 *bh, *bl;
    cudaGetSymbolAddress((void**)&bh, g_BH);
    cudaGetSymbolAddress((void**)&bl, g_BL);
    split_transpose_kernel<<<dim3(N_ / 32, D_ / 32, B_), 256>>>(te, bh, bl);
    gemm_fused_kernel<<<dim3(M_ / 64, B_), 256, GEMM_SMEM_BYTES>>>(Kmat, se, rho);
    initg_kernel<<<B_, 256>>>();
    initR_kernel<<<(B_ * M_ + 255) / 256, 256>>>();
    colsum_kernel<<<B_ * SLICES_, 256>>>();
    colscale_part_kernel<<<B_ * 8, 256>>>();
    gfix_kernel<<<1, 32>>>();
    for (int it = 0; it < 4; it++) {
        fused_iter_kernel<<<B_ * SLICES_, 256, FUSED_SMEM_BYTES>>>();
        colscale_part_kernel<<<B_ * 8, 256>>>();
        gfix_kernel<<<1, 32>>>();
    }
    final_kernel<<<B_ * M_, 256>>>(Kmat, tgt);
    rigid_kernel<<<B_, 256>>>(src, out);
}

// round 11
// speedup vs baseline: 1.8191x; 1.0676x over previous
#include <cuda_runtime.h>
#include <cuda_bf16.h>
#include <math.h>
#include <stdint.h>

#define B_ 16
#define D_ 256
#define M_ 2048
#define N_ 2048
#define SLICES_ 64
#define ROWS_PER_SLICE_ 32

// ---------------- scratch (static device arrays; no allocation) ----------------
__device__ float g_R[B_ * M_];
__device__ float g_C[B_ * N_];
__device__ float g_rowtmp[B_ * M_];
__device__ float g_colpart[B_ * SLICES_ * N_];
__device__ float g_g[B_];
__device__ float g_tppart[B_ * 8];
__device__ float g_w[B_ * M_];
__device__ float g_numer[B_ * M_ * 3];
__device__ __nv_bfloat16 g_BH[B_ * N_ * D_];
__device__ __nv_bfloat16 g_BL[B_ * N_ * D_];
__device__ __nv_bfloat16 g_KbH[(size_t)B_ * M_ * N_];  // bf16 hi of K0' (128 MB)
__device__ __nv_bfloat16 g_KbL[(size_t)B_ * M_ * N_];  // bf16 lo of K0' (128 MB)

// ---------------- helpers ----------------
__device__ __forceinline__ uint32_t smem_u32(const void* p) {
    uint32_t a;
    asm("{ .reg .u64 t; cvta.to.shared.u64 t, %1; cvt.u32.u64 %0, t; }" : "=r"(a) : "l"(p));
    return a;
}

#define LDSM_X4(r0, r1, r2, r3, addr) \
    asm volatile("ldmatrix.sync.aligned.m8n8.x4.shared.b16 {%0,%1,%2,%3}, [%4];" \
                 : "=r"(r0), "=r"(r1), "=r"(r2), "=r"(r3) : "r"(addr))

#define MMA16816(d, a, bq) \
    asm volatile( \
        "mma.sync.aligned.m16n8k16.row.col.f32.bf16.bf16.f32 " \
        "{%0,%1,%2,%3}, {%4,%5,%6,%7}, {%8,%9}, {%0,%1,%2,%3};" \
        : "+f"((d)[0]), "+f"((d)[1]), "+f"((d)[2]), "+f"((d)[3]) \
        : "r"((a)[0]), "r"((a)[1]), "r"((a)[2]), "r"((a)[3]), \
          "r"((bq)[0]), "r"((bq)[1]))

#define CP_ASYNC16(sa, ga) \
    asm volatile("cp.async.cg.shared.global [%0], [%1], 16;" :: "r"(sa), "l"(ga))

#define PACK_BF16X2(r, lo, hi) \
    asm("cvt.rn.bf16x2.f32 %0, %1, %2;" : "=r"(r) : "f"(hi), "f"(lo))

__device__ __forceinline__ float bf_lo(uint32_t x) { return __uint_as_float(x << 16); }
__device__ __forceinline__ float bf_hi(uint32_t x) { return __uint_as_float(x & 0xffff0000u); }

// ---------------- block reductions ----------------
__device__ __forceinline__ float blockReduceSum(float v) {
    __shared__ float sh[33];
    int lane = threadIdx.x & 31, w = threadIdx.x >> 5;
#pragma unroll
    for (int o = 16; o; o >>= 1) v += __shfl_down_sync(0xffffffffu, v, o);
    if (lane == 0) sh[w] = v;
    __syncthreads();
    if (w == 0) {
        v = (lane < (int)(blockDim.x >> 5)) ? sh[lane] : 0.f;
#pragma unroll
        for (int o = 16; o; o >>= 1) v += __shfl_down_sync(0xffffffffu, v, o);
        if (lane == 0) sh[32] = v;
    }
    __syncthreads();
    float r = sh[32];
    __syncthreads();
    return r;
}

// ---------------- init: C = 1 ----------------
__global__ void init_kernel() {
    int i = blockIdx.x * blockDim.x + threadIdx.x;
    if (i < B_ * N_) g_C[i] = 1.0f;
}

// ---------------- transpose + bf16 hi/lo split for B (te) ----------------
__global__ __launch_bounds__(256) void split_transpose_kernel(const float* __restrict__ X,
                                                              __nv_bfloat16* __restrict__ H,
                                                              __nv_bfloat16* __restrict__ L) {
    __shared__ float t[32][33];
    int b = blockIdx.z;
    int m0 = blockIdx.x * 32, d0 = blockIdx.y * 32;
    const float* Xb = X + (size_t)b * D_ * M_;
    int tx = threadIdx.x & 31, ty = threadIdx.x >> 5;
#pragma unroll
    for (int i = 0; i < 4; i++) {
        int d = d0 + ty + i * 8;
        t[ty + i * 8][tx] = Xb[(size_t)d * M_ + m0 + tx];
    }
    __syncthreads();
#pragma unroll
    for (int i = 0; i < 4; i++) {
        int m = m0 + ty + i * 8;
        float v = t[tx][ty + i * 8];
        __nv_bfloat16 h = __float2bfloat16(v);
        __nv_bfloat16 l = __float2bfloat16(v - __bfloat162float(h));
        size_t o = ((size_t)b * M_ + m) * D_ + d0 + tx;
        H[o] = h;
        L[o] = l;
    }
}

// ---------------- fused GEMM + exp + row stats (bf16 hi/lo K0 writes) ----------------
#define ASTR_ 264
#define SMS_ 40
#define A_H_OFF 0
#define A_L_OFF (64 * ASTR_ * 2)
#define B_OFF (2 * 64 * ASTR_ * 2)
#define B_MAT_BYTES (128 * SMS_ * 2)
#define B_STAGE_BYTES (2 * B_MAT_BYTES)
#define GEMM_SMEM_BYTES (B_OFF + 2 * B_STAGE_BYTES)

__global__ __launch_bounds__(256, 2) void gemm_fused_kernel(const float* __restrict__ SE,
                                                            const float* __restrict__ rho_p) {
    extern __shared__ __align__(16) char smem[];
    uint32_t smb = smem_u32(smem);
    int tid = threadIdx.x, wid = tid >> 5, lane = tid & 31;
    int mt = blockIdx.x, b = blockIdx.y;
    int m0 = mt * 64;
    int wr = wid >> 2, wc = wid & 3;
    int gid = lane >> 2, tig = lane & 3;

    float rho = fmaxf(rho_p[0], 1e-8f);
    float invr = 1.0f / rho;
    bool rho1 = (rho == 1.0f);

    {
        const float* Ab = SE + (size_t)b * D_ * M_ + m0;
        int dd = tid >> 6, j = tid & 63;
        __nv_bfloat16* aH = (__nv_bfloat16*)(smem + A_H_OFF);
        __nv_bfloat16* aL = (__nv_bfloat16*)(smem + A_L_OFF);
        for (int d0 = 0; d0 < D_; d0 += 4) {
            int d = d0 + dd;
            float v = Ab[(size_t)d * M_ + j];
            __nv_bfloat16 h = __float2bfloat16(v);
            __nv_bfloat16 l = __float2bfloat16(v - __bfloat162float(h));
            int off = j * ASTR_ + d;
            aH[off] = h;
            aL[off] = l;
        }
    }
    __syncthreads();

    float acc[2][4][4];
#pragma unroll
    for (int mi = 0; mi < 2; mi++)
#pragma unroll
        for (int ni = 0; ni < 4; ni++)
#pragma unroll
            for (int r = 0; r < 4; r++) acc[mi][ni][r] = 0.f;

    float s_part[2][2] = {{0, 0}, {0, 0}};
    float z_part[2][2] = {{0, 0}, {0, 0}};

    int i0 = tid * 2, i1 = tid * 2 + 1;
    int r0_ = i0 >> 2, s0_ = i0 & 3;
    int r1_ = i1 >> 2, s1_ = i1 & 3;
    uint32_t d00 = (uint32_t)(r0_ * SMS_ + s0_ * 8) * 2;
    uint32_t d01 = (uint32_t)(r1_ * SMS_ + s1_ * 8) * 2;

    const __nv_bfloat16* BHb = g_BH + (size_t)b * N_ * D_;
    const __nv_bfloat16* BLb = g_BL + (size_t)b * N_ * D_;

    int a_row = (lane & 15), a_colh = (lane >> 4) * 8;
    int b_tile = lane >> 3, b_r8 = lane & 7;
    int b_n = ((b_tile >> 1) * 8) + b_r8;
    int b_k = (b_tile & 1) * 8;

    auto load_chunk = [&](int cc) {
        int nt = cc >> 3, c = cc & 7;
        uint32_t base = smb + B_OFF + (uint32_t)(cc & 1) * B_STAGE_BYTES;
        const __nv_bfloat16* Bh = BHb + (size_t)(nt * 128) * D_ + c * 32;
        const __nv_bfloat16* Bl = BLb + (size_t)(nt * 128) * D_ + c * 32;
        size_t g00 = (size_t)r0_ * D_ + s0_ * 8;
        size_t g01 = (size_t)r1_ * D_ + s1_ * 8;
        CP_ASYNC16(base + d00, Bh + g00);
        CP_ASYNC16(base + d01, Bh + g01);
        CP_ASYNC16(base + B_MAT_BYTES + d00, Bl + g00);
        CP_ASYNC16(base + B_MAT_BYTES + d01, Bl + g01);
        asm volatile("cp.async.commit_group;" ::: "memory");
    };

    load_chunk(0);
    __nv_bfloat16* KHb = g_KbH + (size_t)b * M_ * N_;
    __nv_bfloat16* KLb = g_KbL + (size_t)b * M_ * N_;

    for (int cc = 0; cc < 128; cc++) {
        if (cc < 127) load_chunk(cc + 1);
        if (cc < 127)
            asm volatile("cp.async.wait_group 1;" ::: "memory");
        else
            asm volatile("cp.async.wait_group 0;" ::: "memory");
        __syncthreads();

        int c = cc & 7;
        uint32_t bbase = smb + B_OFF + (uint32_t)(cc & 1) * B_STAGE_BYTES;
        uint32_t sBh_u = bbase, sBl_u = bbase + B_MAT_BYTES;
        uint32_t aH_u = smb + A_H_OFF;
        uint32_t aL_u = smb + A_L_OFF;

#pragma unroll
        for (int ks = 0; ks < 2; ks++) {
            uint32_t bh[4][2], bl[4][2];
#pragma unroll
            for (int np = 0; np < 2; np++) {
                uint32_t off = (uint32_t)((wc * 32 + np * 16 + b_n) * SMS_ + ks * 16 + b_k) * 2;
                LDSM_X4(bh[np * 2][0], bh[np * 2][1], bh[np * 2 + 1][0], bh[np * 2 + 1][1],
                        sBh_u + off);
                LDSM_X4(bl[np * 2][0], bl[np * 2][1], bl[np * 2 + 1][0], bl[np * 2 + 1][1],
                        sBl_u + off);
            }
#pragma unroll
            for (int mi = 0; mi < 2; mi++) {
                uint32_t ah[4], al[4];
                uint32_t aoff = (uint32_t)((wr * 32 + mi * 16 + a_row) * ASTR_ +
                                           c * 32 + ks * 16 + a_colh) * 2;
                LDSM_X4(ah[0], ah[1], ah[2], ah[3], aH_u + aoff);
                LDSM_X4(al[0], al[1], al[2], al[3], aL_u + aoff);
#pragma unroll
                for (int ni = 0; ni < 4; ni++) {
                    MMA16816(acc[mi][ni], ah, bh[ni]);
                    MMA16816(acc[mi][ni], ah, bl[ni]);
                    MMA16816(acc[mi][ni], al, bh[ni]);
                }
            }
        }

        if ((cc & 7) == 7) {
            int nt = cc >> 3;
            int n_base = nt * 128 + wc * 32 + tig * 2;
#pragma unroll
            for (int mi = 0; mi < 2; mi++) {
                int row0 = m0 + wr * 32 + mi * 16 + gid;
#pragma unroll
                for (int ni = 0; ni < 4; ni++) {
                    float v00 = acc[mi][ni][0] * 0.0625f;
                    float v01 = acc[mi][ni][1] * 0.0625f;
                    float v10 = acc[mi][ni][2] * 0.0625f;
                    float v11 = acc[mi][ni][3] * 0.0625f;
                    float e00 = __expf(fminf(fmaxf(v00 * invr, -60.f), 60.f));
                    float e01 = __expf(fminf(fmaxf(v01 * invr, -60.f), 60.f));
                    float e10 = __expf(fminf(fmaxf(v10 * invr, -60.f), 60.f));
                    float e11 = __expf(fminf(fmaxf(v11 * invr, -60.f), 60.f));
                    float z00, z01, z10, z11;
                    if (rho1) {
                        z00 = e00; z01 = e01; z10 = e10; z11 = e11;
                    } else {
                        z00 = __expf(fminf(fmaxf(v00, -60.f), 60.f));
                        z01 = __expf(fminf(fmaxf(v01, -60.f), 60.f));
                        z10 = __expf(fminf(fmaxf(v10, -60.f), 60.f));
                        z11 = __expf(fminf(fmaxf(v11, -60.f), 60.f));
                    }
                    int col = n_base + ni * 8;
                    uint32_t ph0, ph1;
                    PACK_BF16X2(ph0, e00, e01);
                    PACK_BF16X2(ph1, e10, e11);
                    float l00 = e00 - bf_lo(ph0), l01 = e01 - bf_hi(ph0);
                    float l10 = e10 - bf_lo(ph1), l11 = e11 - bf_hi(ph1);
                    uint32_t pl0, pl1;
                    PACK_BF16X2(pl0, l00, l01);
                    PACK_BF16X2(pl1, l10, l11);
                    *(uint32_t*)(KHb + (size_t)row0 * N_ + col) = ph0;
                    *(uint32_t*)(KHb + (size_t)(row0 + 8) * N_ + col) = ph1;
                    *(uint32_t*)(KLb + (size_t)row0 * N_ + col) = pl0;
                    *(uint32_t*)(KLb + (size_t)(row0 + 8) * N_ + col) = pl1;
                    s_part[mi][0] += e00 + e01;
                    s_part[mi][1] += e10 + e11;
                    z_part[mi][0] += z00 + z01;
                    z_part[mi][1] += z10 + z11;
                    acc[mi][ni][0] = 0.f; acc[mi][ni][1] = 0.f;
                    acc[mi][ni][2] = 0.f; acc[mi][ni][3] = 0.f;
                }
            }
        }
        __syncthreads();
    }

    float* sred = (float*)(smem + B_OFF);
    float* zred = sred + 4 * 64;
#pragma unroll
    for (int mi = 0; mi < 2; mi++)
#pragma unroll
        for (int h = 0; h < 2; h++) {
            float s = s_part[mi][h];
            float z = z_part[mi][h];
            s += __shfl_down_sync(0xffffffffu, s, 1);
            s += __shfl_down_sync(0xffffffffu, s, 2);
            z += __shfl_down_sync(0xffffffffu, z, 1);
            z += __shfl_down_sync(0xffffffffu, z, 2);
            if (tig == 0) {
                int rl = wr * 32 + mi * 16 + h * 8 + gid;
                sred[wc * 64 + rl] = s;
                zred[wc * 64 + rl] = z;
            }
        }
    __syncthreads();
    if (tid < 64) {
        float s = sred[tid] + sred[64 + tid] + sred[128 + tid] + sred[192 + tid];
        float z = zred[tid] + zred[64 + tid] + zred[128 + tid] + zred[192 + tid];
        float cr = __expf(-invr * __logf(fmaxf(z, 1e-30f)));
        int grow = b * M_ + m0 + tid;
        g_R[grow] = cr;
        g_rowtmp[grow] = cr * s;
    }
}

// ---------------- initial global normalization ----------------
__global__ __launch_bounds__(256) void initg_kernel() {
    int b = blockIdx.x;
    float s = 0.f;
    for (int i = threadIdx.x; i < M_; i += 256) s += g_rowtmp[b * M_ + i];
    s = blockReduceSum(s);
    if (threadIdx.x == 0) g_g[b] = 1.0f / fmaxf(s, 1e-8f);
}

// ---------------- iteration 1 row scaling ----------------
__global__ void initR_kernel() {
    int i = blockIdx.x * blockDim.x + threadIdx.x;
    if (i < B_ * M_) {
        int b = i >> 11;
        float rowsum = g_g[b] * g_rowtmp[i];
        g_R[i] *= fminf((1.0f / 2048.0f) / fmaxf(rowsum, 1e-8f), 1.0f);
    }
}

// ---------------- iteration 1 column partial sums (bf16-hi reads) ----------------
__global__ __launch_bounds__(256) void colsum_kernel() {
    int b = blockIdx.x >> 6;
    int slice = blockIdx.x & 63;
    int i0 = slice * ROWS_PER_SLICE_;
    int tid = threadIdx.x;
    const uint32_t* base = (const uint32_t*)(g_KbH + ((size_t)(b << 11) + i0) * N_);
    float acc[8] = {0, 0, 0, 0, 0, 0, 0, 0};
    for (int r = 0; r < ROWS_PER_SLICE_; r++) {
        float Rv = g_R[(b << 11) + i0 + r];
        const uint32_t* P = base + (size_t)r * (N_ / 2);
#pragma unroll
        for (int q = 0; q < 4; q++) {
            uint32_t x = P[tid + q * 256];
            acc[2 * q] += bf_lo(x) * Rv;
            acc[2 * q + 1] += bf_hi(x) * Rv;
        }
    }
    float* outp = g_colpart + (size_t)blockIdx.x * N_;
#pragma unroll
    for (int q = 0; q < 4; q++) {
        float2 v = {acc[2 * q], acc[2 * q + 1]};
        *(float2*)(outp + 2 * (tid + q * 256)) = v;
    }
}

// ---------------- iterations 2-5: fused rowscale + colsum ----------------
#define FUSED_SMEM_BYTES (8 * N_ * 4)
__global__ __launch_bounds__(256) void fused_iter_kernel() {
    extern __shared__ float ssum[];
    int b = blockIdx.x >> 6;
    int slice = blockIdx.x & 63;
    int i0 = slice * ROWS_PER_SLICE_;
    int wid = threadIdx.x >> 5, lane = threadIdx.x & 31;
    const float* Cp = g_C + (b << 11);
    float g = g_g[b];
    float acc[64];
#pragma unroll
    for (int q = 0; q < 64; q++) acc[q] = 0.f;

    const uint32_t* Kb32 = (const uint32_t*)(g_KbH + (size_t)(b << 11) * N_);

    for (int r = 0; r < 4; r++) {
        int rowl = i0 + wid * 4 + r;
        int row = (b << 11) + rowl;
        const uint32_t* P = Kb32 + (size_t)rowl * (N_ / 2);
        uint32_t x[32];
#pragma unroll
        for (int q = 0; q < 32; q++) x[q] = P[lane + 32 * q];
        float d = 0.f;
#pragma unroll
        for (int q = 0; q < 32; q++) {
            float2 cv = *(const float2*)(Cp + 2 * (lane + 32 * q));
            d += bf_lo(x[q]) * cv.x + bf_hi(x[q]) * cv.y;
        }
#pragma unroll
        for (int o = 16; o; o >>= 1) d += __shfl_xor_sync(0xffffffffu, d, o);
        float Rold = g_R[row];
        float rowsum = g * Rold * d;
        float Rnew = Rold * fminf((1.0f / 2048.0f) / fmaxf(rowsum, 1e-8f), 1.0f);
        if (lane == 0) g_R[row] = Rnew;
#pragma unroll
        for (int q = 0; q < 32; q++) {
            acc[2 * q] += bf_lo(x[q]) * Rnew;
            acc[2 * q + 1] += bf_hi(x[q]) * Rnew;
        }
    }
    float* myrow = ssum + wid * N_;
#pragma unroll
    for (int q = 0; q < 32; q++) {
        float2 v = {acc[2 * q], acc[2 * q + 1]};
        *(float2*)(myrow + 2 * (lane + 32 * q)) = v;
    }
    __syncthreads();
    float* outp = g_colpart + (size_t)blockIdx.x * N_;
    for (int j = threadIdx.x; j < N_; j += 256) {
        float t = 0.f;
#pragma unroll
        for (int w = 0; w < 8; w++) t += ssum[w * N_ + j];
        outp[j] = t;
    }
}

// ---------------- col scaling (parallel) + g update ----------------
__global__ __launch_bounds__(256) void colscale_part_kernel() {
    int b = blockIdx.x >> 3;
    int part = blockIdx.x & 7;
    int j = part * 256 + threadIdx.x;
    float g = g_g[b];
    float acc = 0.f;
    const float* cp = g_colpart + (size_t)(b << 6) * N_ + j;
#pragma unroll 8
    for (int s = 0; s < SLICES_; s++) acc += cp[(size_t)s * N_];
    int cj = (b << 11) + j;
    float colsum = g * g_C[cj] * acc;
    float cc = fminf((1.0f / 2048.0f) / fmaxf(colsum, 1e-8f), 1.0f);
    g_C[cj] *= cc;
    float tp = blockReduceSum(colsum * cc);
    if (threadIdx.x == 0) g_tppart[blockIdx.x] = tp;
}

__global__ void gfix_kernel() {
    int b = threadIdx.x;
    if (b < B_) {
        float tp = 0.f;
#pragma unroll
        for (int p = 0; p < 8; p++) tp += g_tppart[b * 8 + p];
        g_g[b] *= 1.0f / fmaxf(tp, 1e-8f);
    }
}

// ---------------- final: warp-per-row, hi+lo reconstruction, no block syncs ----------------
__global__ __launch_bounds__(256) void final_kernel(float* __restrict__ K,
                                                    const float* __restrict__ tgt) {
    int blk = blockIdx.x;                 // 4096 blocks, 8 rows each
    int b = blk >> 8;
    int rowl = ((blk & 255) << 3) + (threadIdx.x >> 5);
    int lane = threadIdx.x & 31;
    int row = (b << 11) + rowl;
    const uint2* H = (const uint2*)(g_KbH + (size_t)row * N_);
    const uint2* L = (const uint2*)(g_KbL + (size_t)row * N_);
    const float4* C4 = (const float4*)(g_C + (b << 11));
    const float4* t04 = (const float4*)(tgt + (size_t)b * 3 * N_);
    const float4* t14 = t04 + N_ / 4;
    const float4* t24 = t04 + 2 * (N_ / 4);
    float* P = K + (size_t)row * N_;
    float gR = g_g[b] * g_R[row];
    float s = 0.f, sx = 0.f, sy = 0.f, sz = 0.f;
#pragma unroll
    for (int q = 0; q < 16; q++) {
        int i2 = lane + 32 * q;           // uint2 index (4 elements)
        uint2 h = H[i2];
        uint2 l = L[i2];
        float4 c = C4[i2];
        float v0 = (bf_lo(h.x) + bf_lo(l.x)) * gR * c.x;
        float v1 = (bf_hi(h.x) + bf_hi(l.x)) * gR * c.y;
        float v2 = (bf_lo(h.y) + bf_lo(l.y)) * gR * c.z;
        float v3 = (bf_hi(h.y) + bf_hi(l.y)) * gR * c.w;
        float4 o = {v0, v1, v2, v3};
        *(float4*)(P + i2 * 4) = o;
        float4 a0 = t04[i2], a1 = t14[i2], a2 = t24[i2];
        s += v0 + v1 + v2 + v3;
        sx += v0 * a0.x + v1 * a0.y + v2 * a0.z + v3 * a0.w;
        sy += v0 * a1.x + v1 * a1.y + v2 * a1.z + v3 * a1.w;
        sz += v0 * a2.x + v1 * a2.y + v2 * a2.z + v3 * a2.w;
    }
#pragma unroll
    for (int o = 16; o; o >>= 1) {
        s += __shfl_xor_sync(0xffffffffu, s, o);
        sx += __shfl_xor_sync(0xffffffffu, sx, o);
        sy += __shfl_xor_sync(0xffffffffu, sy, o);
        sz += __shfl_xor_sync(0xffffffffu, sz, o);
    }
    if (lane == 0) {
        g_w[row] = s;
        g_numer[row * 3 + 0] = sx;
        g_numer[row * 3 + 1] = sy;
        g_numer[row * 3 + 2] = sz;
    }
}

// ---------------- rigid transform (fp64 Kabsch + Jacobi SVD) ----------------
__global__ __launch_bounds__(256) void rigid_kernel(const float* __restrict__ src,
                                                    float* __restrict__ out) {
    int b = blockIdx.x;
    int tid = threadIdx.x;
    const float* s0 = src + (size_t)b * 3 * M_;
    const float* s1 = s0 + M_;
    const float* s2 = s0 + 2 * M_;
    double acc[16];
#pragma unroll
    for (int q = 0; q < 16; q++) acc[q] = 0.0;
    for (int i = tid; i < M_; i += 256) {
        int row = (b << 11) + i;
        double w = (double)g_w[row];
        double dn = w + 1e-6;
        double bx = (double)g_numer[row * 3 + 0] / dn;
        double by = (double)g_numer[row * 3 + 1] / dn;
        double bz = (double)g_numer[row * 3 + 2] / dn;
        double ax = (double)s0[i], ay = (double)s1[i], az = (double)s2[i];
        acc[0] += w;
        acc[1] += w * ax; acc[2] += w * ay; acc[3] += w * az;
        acc[4] += w * bx; acc[5] += w * by; acc[6] += w * bz;
        acc[7]  += w * ax * bx; acc[8]  += w * ax * by; acc[9]  += w * ax * bz;
        acc[10] += w * ay * bx; acc[11] += w * ay * by; acc[12] += w * ay * bz;
        acc[13] += w * az * bx; acc[14] += w * az * by; acc[15] += w * az * bz;
    }
    __shared__ double sh[256];
    __shared__ double res[16];
    for (int q = 0; q < 16; q++) {
        sh[tid] = acc[q];
        __syncthreads();
        for (int off = 128; off > 0; off >>= 1) {
            if (tid < off) sh[tid] += sh[tid + off];
            __syncthreads();
        }
        if (tid == 0) res[q] = sh[0];
        __syncthreads();
    }
    if (tid != 0) return;

    double W2 = res[0] + 1e-6;
    double ca[3], cb[3];
#pragma unroll
    for (int i = 0; i < 3; i++) {
        ca[i] = res[1 + i] / W2;
        cb[i] = res[4 + i] / W2;
    }
    double sfac = 2.0 - res[0] / W2;
    double Cv[3][3];
#pragma unroll
    for (int i = 0; i < 3; i++)
#pragma unroll
        for (int j = 0; j < 3; j++)
            Cv[i][j] = res[7 + i * 3 + j] / W2 - sfac * ca[i] * cb[j];

    double A[3][3];
#pragma unroll
    for (int i = 0; i < 3; i++)
#pragma unroll
        for (int j = 0; j < 3; j++)
            A[i][j] = Cv[0][i] * Cv[0][j] + Cv[1][i] * Cv[1][j] + Cv[2][i] * Cv[2][j];
    double V[3][3] = {{1, 0, 0}, {0, 1, 0}, {0, 0, 1}};
    const int PP[3] = {0, 0, 1}, QQ[3] = {1, 2, 2};
    for (int sweep = 0; sweep < 30; sweep++) {
        double off = fabs(A[0][1]) + fabs(A[0][2]) + fabs(A[1][2]);
        if (off < 1e-28) break;
        for (int r = 0; r < 3; r++) {
            int p = PP[r], q = QQ[r];
            double apq = A[p][q];
            if (apq == 0.0) continue;
            double theta = (A[q][q] - A[p][p]) / (2.0 * apq);
            double t = ((theta >= 0.0) ? 1.0 : -1.0) / (fabs(theta) + sqrt(1.0 + theta * theta));
            double c = 1.0 / sqrt(1.0 + t * t);
            double s = t * c;
            for (int k = 0; k < 3; k++) {
                double akp = A[k][p], akq = A[k][q];
                A[k][p] = c * akp - s * akq;
                A[k][q] = s * akp + c * akq;
            }
            for (int k = 0; k < 3; k++) {
                double apk = A[p][k], aqk = A[q][k];
                A[p][k] = c * apk - s * aqk;
                A[q][k] = s * apk + c * aqk;
            }
            for (int k = 0; k < 3; k++) {
                double vkp = V[k][p], vkq = V[k][q];
                V[k][p] = c * vkp - s * vkq;
                V[k][q] = s * vkp + c * vkq;
            }
        }
    }
    double d[3] = {A[0][0], A[1][1], A[2][2]};
    for (int i = 0; i < 2; i++)
        for (int j = i + 1; j < 3; j++)
            if (d[j] > d[i]) {
                double tmp = d[i]; d[i] = d[j]; d[j] = tmp;
                for (int k = 0; k < 3; k++) {
                    double tv = V[k][i]; V[k][i] = V[k][j]; V[k][j] = tv;
                }
            }
    double U[3][3];
    double nrm[3];
#pragma unroll
    for (int k = 0; k < 3; k++) {
        double u0 = Cv[0][0] * V[0][k] + Cv[0][1] * V[1][k] + Cv[0][2] * V[2][k];
        double u1 = Cv[1][0] * V[0][k] + Cv[1][1] * V[1][k] + Cv[1][2] * V[2][k];
        double u2 = Cv[2][0] * V[0][k] + Cv[2][1] * V[1][k] + Cv[2][2] * V[2][k];
        double n = sqrt(u0 * u0 + u1 * u1 + u2 * u2);
        nrm[k] = n;
        if (n > 1e-30) {
            U[0][k] = u0 / n; U[1][k] = u1 / n; U[2][k] = u2 / n;
        } else {
            U[0][k] = 0.0; U[1][k] = 0.0; U[2][k] = 0.0;
        }
    }
    if (nrm[2] <= 1e-12 * fmax(nrm[0], 1e-30)) {
        double cx = U[1][0] * U[2][1] - U[2][0] * U[1][1];
        double cy = U[2][0] * U[0][1] - U[0][0] * U[2][1];
        double cz = U[0][0] * U[1][1] - U[1][0] * U[0][1];
        double n = sqrt(cx * cx + cy * cy + cz * cz);
        if (n > 1e-30) { U[0][2] = cx / n; U[1][2] = cy / n; U[2][2] = cz / n; }
    }
    double R[3][3];
#pragma unroll
    for (int i = 0; i < 3; i++)
#pragma unroll
        for (int j = 0; j < 3; j++)
            R[i][j] = V[i][0] * U[j][0] + V[i][1] * U[j][1] + V[i][2] * U[j][2];
    double det = R[0][0] * (R[1][1] * R[2][2] - R[1][2] * R[2][1])
               - R[0][1] * (R[1][0] * R[2][2] - R[1][2] * R[2][0])
               + R[0][2] * (R[1][0] * R[2][1] - R[1][1] * R[2][0]);
    if (!(det > 0.0)) {
#pragma unroll
        for (int i = 0; i < 3; i++)
#pragma unroll
            for (int j = 0; j < 3; j++)
                R[i][j] -= 2.0 * V[i][2] * U[j][2];
    }
    double tr[3];
#pragma unroll
    for (int i = 0; i < 3; i++)
        tr[i] = cb[i] - (R[i][0] * ca[0] + R[i][1] * ca[1] + R[i][2] * ca[2]);

#pragma unroll
    for (int i = 0; i < 3; i++)
#pragma unroll
        for (int j = 0; j < 3; j++)
            out[b * 9 + i * 3 + j] = (float)R[i][j];
#pragma unroll
    for (int i = 0; i < 3; i++) out[144 + b * 3 + i] = (float)tr[i];
}

// ---------------- launch ----------------
extern "C" void kernel_launch(void* const* d_in, const int* in_sizes, int n_in,
                              void* d_out, int out_size) {
    (void)in_sizes; (void)n_in; (void)out_size;
    const float* se  = (const float*)d_in[0];
    const float* te  = (const float*)d_in[1];
    const float* src = (const float*)d_in[2];
    const float* tgt = (const float*)d_in[3];
    const float* rho = (const float*)d_in[4];
    float* out = (float*)d_out;
    float* Kmat = out + 192;

    static int attr_done = 0;
    if (!attr_done) {
        cudaFuncSetAttribute(gemm_fused_kernel, cudaFuncAttributeMaxDynamicSharedMemorySize,
                             GEMM_SMEM_BYTES);
        cudaFuncSetAttribute(fused_iter_kernel, cudaFuncAttributeMaxDynamicSharedMemorySize,
                             FUSED_SMEM_BYTES);
        attr_done = 1;
    }

    init_kernel<<<(B_ * N_ + 255) / 256, 256>>>();
    __nv_bfloat16 *bh, *bl;
    cudaGetSymbolAddress((void**)&bh, g_BH);
    cudaGetSymbolAddress((void**)&bl, g_BL);
    split_transpose_kernel<<<dim3(N_ / 32, D_ / 32, B_), 256>>>(te, bh, bl);
    gemm_fused_kernel<<<dim3(M_ / 64, B_), 256, GEMM_SMEM_BYTES>>>(se, rho);
    initg_kernel<<<B_, 256>>>();
    initR_kernel<<<(B_ * M_ + 255) / 256, 256>>>();
    colsum_kernel<<<B_ * SLICES_, 256>>>();
    colscale_part_kernel<<<B_ * 8, 256>>>();
    gfix_kernel<<<1, 32>>>();
    for (int it = 0; it < 4; it++) {
        fused_iter_kernel<<<B_ * SLICES_, 256, FUSED_SMEM_BYTES>>>();
        colscale_part_kernel<<<B_ * 8, 256>>>();
        gfix_kernel<<<1, 32>>>();
    }
    final_kernel<<<B_ * M_ / 8, 256>>>(Kmat, tgt);
    rigid_kernel<<<B_, 256>>>(src, out);
}

// round 13
// speedup vs baseline: 1.8427x; 1.0130x over previous
#include <cuda_runtime.h>
#include <cuda_bf16.h>
#include <math.h>
#include <stdint.h>

#define B_ 16
#define D_ 256
#define M_ 2048
#define N_ 2048
#define SLICES_ 64
#define ROWS_PER_SLICE_ 32

// ---------------- scratch (static device arrays; no allocation) ----------------
__device__ float g_R[B_ * M_];
__device__ float g_C[B_ * N_];
__device__ float g_rowtmp[B_ * M_];
__device__ float g_colpart[B_ * SLICES_ * N_];
__device__ float g_g[B_];
__device__ float g_tppart[B_ * 8];
__device__ unsigned g_cnt[B_];  // zero-initialized; colscale fold resets to 0 each use
__device__ float g_w[B_ * M_];
__device__ float g_numer[B_ * M_ * 3];
__device__ __nv_bfloat16 g_BH[B_ * N_ * D_];
__device__ __nv_bfloat16 g_BL[B_ * N_ * D_];
__device__ __nv_bfloat16 g_KbH[(size_t)B_ * M_ * N_];
__device__ __nv_bfloat16 g_KbL[(size_t)B_ * M_ * N_];

// ---------------- helpers ----------------
__device__ __forceinline__ uint32_t smem_u32(const void* p) {
    uint32_t a;
    asm("{ .reg .u64 t; cvta.to.shared.u64 t, %1; cvt.u32.u64 %0, t; }" : "=r"(a) : "l"(p));
    return a;
}

#define LDSM_X4(r0, r1, r2, r3, addr) \
    asm volatile("ldmatrix.sync.aligned.m8n8.x4.shared.b16 {%0,%1,%2,%3}, [%4];" \
                 : "=r"(r0), "=r"(r1), "=r"(r2), "=r"(r3) : "r"(addr))

#define MMA16816(d, a, bq) \
    asm volatile( \
        "mma.sync.aligned.m16n8k16.row.col.f32.bf16.bf16.f32 " \
        "{%0,%1,%2,%3}, {%4,%5,%6,%7}, {%8,%9}, {%0,%1,%2,%3};" \
        : "+f"((d)[0]), "+f"((d)[1]), "+f"((d)[2]), "+f"((d)[3]) \
        : "r"((a)[0]), "r"((a)[1]), "r"((a)[2]), "r"((a)[3]), \
          "r"((bq)[0]), "r"((bq)[1]))

#define CP_ASYNC16(sa, ga) \
    asm volatile("cp.async.cg.shared.global [%0], [%1], 16;" :: "r"(sa), "l"(ga))

#define PACK_BF16X2(r, lo, hi) \
    asm("cvt.rn.bf16x2.f32 %0, %1, %2;" : "=r"(r) : "f"(hi), "f"(lo))

__device__ __forceinline__ float bf_lo(uint32_t x) { return __uint_as_float(x << 16); }
__device__ __forceinline__ float bf_hi(uint32_t x) { return __uint_as_float(x & 0xffff0000u); }

// ---------------- block reductions ----------------
__device__ __forceinline__ float blockReduceSum(float v) {
    __shared__ float sh[33];
    int lane = threadIdx.x & 31, w = threadIdx.x >> 5;
#pragma unroll
    for (int o = 16; o; o >>= 1) v += __shfl_down_sync(0xffffffffu, v, o);
    if (lane == 0) sh[w] = v;
    __syncthreads();
    if (w == 0) {
        v = (lane < (int)(blockDim.x >> 5)) ? sh[lane] : 0.f;
#pragma unroll
        for (int o = 16; o; o >>= 1) v += __shfl_down_sync(0xffffffffu, v, o);
        if (lane == 0) sh[32] = v;
    }
    __syncthreads();
    float r = sh[32];
    __syncthreads();
    return r;
}

// ---------------- transpose + bf16 hi/lo split for B (te) ----------------
__global__ __launch_bounds__(256) void split_transpose_kernel(const float* __restrict__ X,
                                                              __nv_bfloat16* __restrict__ H,
                                                              __nv_bfloat16* __restrict__ L) {
    __shared__ float t[32][33];
    int b = blockIdx.z;
    int m0 = blockIdx.x * 32, d0 = blockIdx.y * 32;
    const float* Xb = X + (size_t)b * D_ * M_;
    int tx = threadIdx.x & 31, ty = threadIdx.x >> 5;
#pragma unroll
    for (int i = 0; i < 4; i++) {
        int d = d0 + ty + i * 8;
        t[ty + i * 8][tx] = Xb[(size_t)d * M_ + m0 + tx];
    }
    __syncthreads();
#pragma unroll
    for (int i = 0; i < 4; i++) {
        int m = m0 + ty + i * 8;
        float v = t[tx][ty + i * 8];
        __nv_bfloat16 h = __float2bfloat16(v);
        __nv_bfloat16 l = __float2bfloat16(v - __bfloat162float(h));
        size_t o = ((size_t)b * M_ + m) * D_ + d0 + tx;
        H[o] = h;
        L[o] = l;
    }
}

// ---------------- fused GEMM + exp + row stats (single-sync pipeline) ----------------
#define ASTR_ 264
#define SMS_ 40
#define A_H_OFF 0
#define A_L_OFF (64 * ASTR_ * 2)
#define B_OFF (2 * 64 * ASTR_ * 2)
#define B_MAT_BYTES (128 * SMS_ * 2)
#define B_STAGE_BYTES (2 * B_MAT_BYTES)
#define GEMM_SMEM_BYTES (B_OFF + 2 * B_STAGE_BYTES)

__global__ __launch_bounds__(256, 2) void gemm_fused_kernel(const float* __restrict__ SE,
                                                            const float* __restrict__ rho_p) {
    extern __shared__ __align__(16) char smem[];
    uint32_t smb = smem_u32(smem);
    int tid = threadIdx.x, wid = tid >> 5, lane = tid & 31;
    int mt = blockIdx.x, b = blockIdx.y;
    int m0 = mt * 64;
    int wr = wid >> 2, wc = wid & 3;
    int gid = lane >> 2, tig = lane & 3;

    float rho = fmaxf(rho_p[0], 1e-8f);
    float invr = 1.0f / rho;
    bool rho1 = (rho == 1.0f);

    {
        const float* Ab = SE + (size_t)b * D_ * M_ + m0;
        int dd = tid >> 6, j = tid & 63;
        __nv_bfloat16* aH = (__nv_bfloat16*)(smem + A_H_OFF);
        __nv_bfloat16* aL = (__nv_bfloat16*)(smem + A_L_OFF);
        for (int d0 = 0; d0 < D_; d0 += 4) {
            int d = d0 + dd;
            float v = Ab[(size_t)d * M_ + j];
            __nv_bfloat16 h = __float2bfloat16(v);
            __nv_bfloat16 l = __float2bfloat16(v - __bfloat162float(h));
            int off = j * ASTR_ + d;
            aH[off] = h;
            aL[off] = l;
        }
    }
    __syncthreads();

    float acc[2][4][4];
#pragma unroll
    for (int mi = 0; mi < 2; mi++)
#pragma unroll
        for (int ni = 0; ni < 4; ni++)
#pragma unroll
            for (int r = 0; r < 4; r++) acc[mi][ni][r] = 0.f;

    float s_part[2][2] = {{0, 0}, {0, 0}};
    float z_part[2][2] = {{0, 0}, {0, 0}};

    int i0 = tid * 2, i1 = tid * 2 + 1;
    int r0_ = i0 >> 2, s0_ = i0 & 3;
    int r1_ = i1 >> 2, s1_ = i1 & 3;
    uint32_t d00 = (uint32_t)(r0_ * SMS_ + s0_ * 8) * 2;
    uint32_t d01 = (uint32_t)(r1_ * SMS_ + s1_ * 8) * 2;

    const __nv_bfloat16* BHb = g_BH + (size_t)b * N_ * D_;
    const __nv_bfloat16* BLb = g_BL + (size_t)b * N_ * D_;

    int a_row = (lane & 15), a_colh = (lane >> 4) * 8;
    int b_tile = lane >> 3, b_r8 = lane & 7;
    int b_n = ((b_tile >> 1) * 8) + b_r8;
    int b_k = (b_tile & 1) * 8;

    auto load_chunk = [&](int cc) {
        int nt = cc >> 3, c = cc & 7;
        uint32_t base = smb + B_OFF + (uint32_t)(cc & 1) * B_STAGE_BYTES;
        const __nv_bfloat16* Bh = BHb + (size_t)(nt * 128) * D_ + c * 32;
        const __nv_bfloat16* Bl = BLb + (size_t)(nt * 128) * D_ + c * 32;
        size_t g00 = (size_t)r0_ * D_ + s0_ * 8;
        size_t g01 = (size_t)r1_ * D_ + s1_ * 8;
        CP_ASYNC16(base + d00, Bh + g00);
        CP_ASYNC16(base + d01, Bh + g01);
        CP_ASYNC16(base + B_MAT_BYTES + d00, Bl + g00);
        CP_ASYNC16(base + B_MAT_BYTES + d01, Bl + g01);
        asm volatile("cp.async.commit_group;" ::: "memory");
    };

    load_chunk(0);
    __nv_bfloat16* KHb = g_KbH + (size_t)b * M_ * N_;
    __nv_bfloat16* KLb = g_KbL + (size_t)b * M_ * N_;

    for (int cc = 0; cc < 128; cc++) {
        // stage cc is the only pending group; wait for it, barrier, then prefetch cc+1
        asm volatile("cp.async.wait_group 0;" ::: "memory");
        __syncthreads();
        if (cc < 127) load_chunk(cc + 1);

        int c = cc & 7;
        uint32_t bbase = smb + B_OFF + (uint32_t)(cc & 1) * B_STAGE_BYTES;
        uint32_t sBh_u = bbase, sBl_u = bbase + B_MAT_BYTES;
        uint32_t aH_u = smb + A_H_OFF;
        uint32_t aL_u = smb + A_L_OFF;

#pragma unroll
        for (int ks = 0; ks < 2; ks++) {
            uint32_t bh[4][2], bl[4][2];
#pragma unroll
            for (int np = 0; np < 2; np++) {
                uint32_t off = (uint32_t)((wc * 32 + np * 16 + b_n) * SMS_ + ks * 16 + b_k) * 2;
                LDSM_X4(bh[np * 2][0], bh[np * 2][1], bh[np * 2 + 1][0], bh[np * 2 + 1][1],
                        sBh_u + off);
                LDSM_X4(bl[np * 2][0], bl[np * 2][1], bl[np * 2 + 1][0], bl[np * 2 + 1][1],
                        sBl_u + off);
            }
#pragma unroll
            for (int mi = 0; mi < 2; mi++) {
                uint32_t ah[4], al[4];
                uint32_t aoff = (uint32_t)((wr * 32 + mi * 16 + a_row) * ASTR_ +
                                           c * 32 + ks * 16 + a_colh) * 2;
                LDSM_X4(ah[0], ah[1], ah[2], ah[3], aH_u + aoff);
                LDSM_X4(al[0], al[1], al[2], al[3], aL_u + aoff);
#pragma unroll
                for (int ni = 0; ni < 4; ni++) {
                    MMA16816(acc[mi][ni], ah, bh[ni]);
                    MMA16816(acc[mi][ni], ah, bl[ni]);
                    MMA16816(acc[mi][ni], al, bh[ni]);
                }
            }
        }

        if ((cc & 7) == 7) {
            int nt = cc >> 3;
            int n_base = nt * 128 + wc * 32 + tig * 2;
#pragma unroll
            for (int mi = 0; mi < 2; mi++) {
                int row0 = m0 + wr * 32 + mi * 16 + gid;
#pragma unroll
                for (int ni = 0; ni < 4; ni++) {
                    float v00 = acc[mi][ni][0] * 0.0625f;
                    float v01 = acc[mi][ni][1] * 0.0625f;
                    float v10 = acc[mi][ni][2] * 0.0625f;
                    float v11 = acc[mi][ni][3] * 0.0625f;
                    float e00 = __expf(fminf(fmaxf(v00 * invr, -60.f), 60.f));
                    float e01 = __expf(fminf(fmaxf(v01 * invr, -60.f), 60.f));
                    float e10 = __expf(fminf(fmaxf(v10 * invr, -60.f), 60.f));
                    float e11 = __expf(fminf(fmaxf(v11 * invr, -60.f), 60.f));
                    float z00, z01, z10, z11;
                    if (rho1) {
                        z00 = e00; z01 = e01; z10 = e10; z11 = e11;
                    } else {
                        z00 = __expf(fminf(fmaxf(v00, -60.f), 60.f));
                        z01 = __expf(fminf(fmaxf(v01, -60.f), 60.f));
                        z10 = __expf(fminf(fmaxf(v10, -60.f), 60.f));
                        z11 = __expf(fminf(fmaxf(v11, -60.f), 60.f));
                    }
                    int col = n_base + ni * 8;
                    uint32_t ph0, ph1;
                    PACK_BF16X2(ph0, e00, e01);
                    PACK_BF16X2(ph1, e10, e11);
                    float l00 = e00 - bf_lo(ph0), l01 = e01 - bf_hi(ph0);
                    float l10 = e10 - bf_lo(ph1), l11 = e11 - bf_hi(ph1);
                    uint32_t pl0, pl1;
                    PACK_BF16X2(pl0, l00, l01);
                    PACK_BF16X2(pl1, l10, l11);
                    *(uint32_t*)(KHb + (size_t)row0 * N_ + col) = ph0;
                    *(uint32_t*)(KHb + (size_t)(row0 + 8) * N_ + col) = ph1;
                    *(uint32_t*)(KLb + (size_t)row0 * N_ + col) = pl0;
                    *(uint32_t*)(KLb + (size_t)(row0 + 8) * N_ + col) = pl1;
                    s_part[mi][0] += e00 + e01;
                    s_part[mi][1] += e10 + e11;
                    z_part[mi][0] += z00 + z01;
                    z_part[mi][1] += z10 + z11;
                    acc[mi][ni][0] = 0.f; acc[mi][ni][1] = 0.f;
                    acc[mi][ni][2] = 0.f; acc[mi][ni][3] = 0.f;
                }
            }
        }
    }

    float* sred = (float*)(smem + B_OFF);
    float* zred = sred + 4 * 64;
#pragma unroll
    for (int mi = 0; mi < 2; mi++)
#pragma unroll
        for (int h = 0; h < 2; h++) {
            float s = s_part[mi][h];
            float z = z_part[mi][h];
            s += __shfl_down_sync(0xffffffffu, s, 1);
            s += __shfl_down_sync(0xffffffffu, s, 2);
            z += __shfl_down_sync(0xffffffffu, z, 1);
            z += __shfl_down_sync(0xffffffffu, z, 2);
            if (tig == 0) {
                int rl = wr * 32 + mi * 16 + h * 8 + gid;
                sred[wc * 64 + rl] = s;
                zred[wc * 64 + rl] = z;
            }
        }
    __syncthreads();
    if (tid < 64) {
        float s = sred[tid] + sred[64 + tid] + sred[128 + tid] + sred[192 + tid];
        float z = zred[tid] + zred[64 + tid] + zred[128 + tid] + zred[192 + tid];
        float cr = __expf(-invr * __logf(fmaxf(z, 1e-30f)));
        int grow = b * M_ + m0 + tid;
        g_R[grow] = cr;
        g_rowtmp[grow] = cr * s;
    }
}

// ---------------- merged: initial g + iteration-1 row scaling ----------------
__global__ __launch_bounds__(256) void initgR_kernel() {
    int b = blockIdx.x;
    float s = 0.f;
    for (int i = threadIdx.x; i < M_; i += 256) s += g_rowtmp[b * M_ + i];
    s = blockReduceSum(s);
    float g = 1.0f / fmaxf(s, 1e-8f);
    if (threadIdx.x == 0) g_g[b] = g;
    for (int i = threadIdx.x; i < M_; i += 256) {
        int gi = b * M_ + i;
        float rowsum = g * g_rowtmp[gi];
        g_R[gi] *= fminf((1.0f / 2048.0f) / fmaxf(rowsum, 1e-8f), 1.0f);
    }
}

// ---------------- iteration 1 column partial sums (bf16-hi reads) ----------------
__global__ __launch_bounds__(256) void colsum_kernel() {
    int b = blockIdx.x >> 6;
    int slice = blockIdx.x & 63;
    int i0 = slice * ROWS_PER_SLICE_;
    int tid = threadIdx.x;
    const uint32_t* base = (const uint32_t*)(g_KbH + ((size_t)(b << 11) + i0) * N_);
    float acc[8] = {0, 0, 0, 0, 0, 0, 0, 0};
    for (int r = 0; r < ROWS_PER_SLICE_; r++) {
        float Rv = g_R[(b << 11) + i0 + r];
        const uint32_t* P = base + (size_t)r * (N_ / 2);
#pragma unroll
        for (int q = 0; q < 4; q++) {
            uint32_t x = P[tid + q * 256];
            acc[2 * q] += bf_lo(x) * Rv;
            acc[2 * q + 1] += bf_hi(x) * Rv;
        }
    }
    float* outp = g_colpart + (size_t)blockIdx.x * N_;
#pragma unroll
    for (int q = 0; q < 4; q++) {
        float2 v = {acc[2 * q], acc[2 * q + 1]};
        *(float2*)(outp + 2 * (tid + q * 256)) = v;
    }
}

// ---------------- iterations 2-5: fused rowscale + colsum ----------------
#define FUSED_SMEM_BYTES (8 * N_ * 4)
__global__ __launch_bounds__(256) void fused_iter_kernel() {
    extern __shared__ float ssum[];
    int b = blockIdx.x >> 6;
    int slice = blockIdx.x & 63;
    int i0 = slice * ROWS_PER_SLICE_;
    int wid = threadIdx.x >> 5, lane = threadIdx.x & 31;
    const float* Cp = g_C + (b << 11);
    float g = g_g[b];
    float acc[64];
#pragma unroll
    for (int q = 0; q < 64; q++) acc[q] = 0.f;

    const uint32_t* Kb32 = (const uint32_t*)(g_KbH + (size_t)(b << 11) * N_);

    for (int r = 0; r < 4; r++) {
        int rowl = i0 + wid * 4 + r;
        int row = (b << 11) + rowl;
        const uint32_t* P = Kb32 + (size_t)rowl * (N_ / 2);
        uint32_t x[32];
#pragma unroll
        for (int q = 0; q < 32; q++) x[q] = P[lane + 32 * q];
        float d = 0.f;
#pragma unroll
        for (int q = 0; q < 32; q++) {
            float2 cv = *(const float2*)(Cp + 2 * (lane + 32 * q));
            d += bf_lo(x[q]) * cv.x + bf_hi(x[q]) * cv.y;
        }
#pragma unroll
        for (int o = 16; o; o >>= 1) d += __shfl_xor_sync(0xffffffffu, d, o);
        float Rold = g_R[row];
        float rowsum = g * Rold * d;
        float Rnew = Rold * fminf((1.0f / 2048.0f) / fmaxf(rowsum, 1e-8f), 1.0f);
        if (lane == 0) g_R[row] = Rnew;
#pragma unroll
        for (int q = 0; q < 32; q++) {
            acc[2 * q] += bf_lo(x[q]) * Rnew;
            acc[2 * q + 1] += bf_hi(x[q]) * Rnew;
        }
    }
    float* myrow = ssum + wid * N_;
#pragma unroll
    for (int q = 0; q < 32; q++) {
        float2 v = {acc[2 * q], acc[2 * q + 1]};
        *(float2*)(myrow + 2 * (lane + 32 * q)) = v;
    }
    __syncthreads();
    float* outp = g_colpart + (size_t)blockIdx.x * N_;
    for (int j = threadIdx.x; j < N_; j += 256) {
        float t = 0.f;
#pragma unroll
        for (int w = 0; w < 8; w++) t += ssum[w * N_ + j];
        outp[j] = t;
    }
}

// ---------------- col scaling (parallel) + folded g update ----------------
__global__ __launch_bounds__(256) void colscale_part_kernel(int first) {
    int b = blockIdx.x >> 3;
    int part = blockIdx.x & 7;
    int j = part * 256 + threadIdx.x;
    float g = g_g[b];
    float acc = 0.f;
    const float* cp = g_colpart + (size_t)(b << 6) * N_ + j;
#pragma unroll 8
    for (int s = 0; s < SLICES_; s++) acc += cp[(size_t)s * N_];
    int cj = (b << 11) + j;
    float base = first ? 1.0f : g_C[cj];
    float colsum = g * base * acc;
    float cc = fminf((1.0f / 2048.0f) / fmaxf(colsum, 1e-8f), 1.0f);
    g_C[cj] = base * cc;
    float tp = blockReduceSum(colsum * cc);
    if (threadIdx.x == 0) {
        g_tppart[blockIdx.x] = tp;
        __threadfence();
        unsigned old = atomicAdd(&g_cnt[b], 1u);
        if (old == 7u) {
            float t = 0.f;
#pragma unroll
            for (int p = 0; p < 8; p++) t += g_tppart[b * 8 + p];
            g_g[b] = g * (1.0f / fmaxf(t, 1e-8f));
            g_cnt[b] = 0u;
        }
    }
}

// ---------------- final: warp-per-row, hi+lo reconstruction ----------------
__global__ __launch_bounds__(256) void final_kernel(float* __restrict__ K,
                                                    const float* __restrict__ tgt) {
    int blk = blockIdx.x;
    int b = blk >> 8;
    int rowl = ((blk & 255) << 3) + (threadIdx.x >> 5);
    int lane = threadIdx.x & 31;
    int row = (b << 11) + rowl;
    const uint2* H = (const uint2*)(g_KbH + (size_t)row * N_);
    const uint2* L = (const uint2*)(g_KbL + (size_t)row * N_);
    const float4* C4 = (const float4*)(g_C + (b << 11));
    const float4* t04 = (const float4*)(tgt + (size_t)b * 3 * N_);
    const float4* t14 = t04 + N_ / 4;
    const float4* t24 = t04 + 2 * (N_ / 4);
    float* P = K + (size_t)row * N_;
    float gR = g_g[b] * g_R[row];
    float s = 0.f, sx = 0.f, sy = 0.f, sz = 0.f;
#pragma unroll
    for (int q = 0; q < 16; q++) {
        int i2 = lane + 32 * q;
        uint2 h = H[i2];
        uint2 l = L[i2];
        float4 c = C4[i2];
        float v0 = (bf_lo(h.x) + bf_lo(l.x)) * gR * c.x;
        float v1 = (bf_hi(h.x) + bf_hi(l.x)) * gR * c.y;
        float v2 = (bf_lo(h.y) + bf_lo(l.y)) * gR * c.z;
        float v3 = (bf_hi(h.y) + bf_hi(l.y)) * gR * c.w;
        float4 o = {v0, v1, v2, v3};
        *(float4*)(P + i2 * 4) = o;
        float4 a0 = t04[i2], a1 = t14[i2], a2 = t24[i2];
        s += v0 + v1 + v2 + v3;
        sx += v0 * a0.x + v1 * a0.y + v2 * a0.z + v3 * a0.w;
        sy += v0 * a1.x + v1 * a1.y + v2 * a1.z + v3 * a1.w;
        sz += v0 * a2.x + v1 * a2.y + v2 * a2.z + v3 * a2.w;
    }
#pragma unroll
    for (int o = 16; o; o >>= 1) {
        s += __shfl_xor_sync(0xffffffffu, s, o);
        sx += __shfl_xor_sync(0xffffffffu, sx, o);
        sy += __shfl_xor_sync(0xffffffffu, sy, o);
        sz += __shfl_xor_sync(0xffffffffu, sz, o);
    }
    if (lane == 0) {
        g_w[row] = s;
        g_numer[row * 3 + 0] = sx;
        g_numer[row * 3 + 1] = sy;
        g_numer[row * 3 + 2] = sz;
    }
}

// ---------------- rigid transform (fp64 Kabsch + Jacobi SVD) ----------------
__global__ __launch_bounds__(256) void rigid_kernel(const float* __restrict__ src,
                                                    float* __restrict__ out) {
    int b = blockIdx.x;
    int tid = threadIdx.x;
    const float* s0 = src + (size_t)b * 3 * M_;
    const float* s1 = s0 + M_;
    const float* s2 = s0 + 2 * M_;
    double acc[16];
#pragma unroll
    for (int q = 0; q < 16; q++) acc[q] = 0.0;
    for (int i = tid; i < M_; i += 256) {
        int row = (b << 11) + i;
        double w = (double)g_w[row];
        double dn = w + 1e-6;
        double bx = (double)g_numer[row * 3 + 0] / dn;
        double by = (double)g_numer[row * 3 + 1] / dn;
        double bz = (double)g_numer[row * 3 + 2] / dn;
        double ax = (double)s0[i], ay = (double)s1[i], az = (double)s2[i];
        acc[0] += w;
        acc[1] += w * ax; acc[2] += w * ay; acc[3] += w * az;
        acc[4] += w * bx; acc[5] += w * by; acc[6] += w * bz;
        acc[7]  += w * ax * bx; acc[8]  += w * ax * by; acc[9]  += w * ax * bz;
        acc[10] += w * ay * bx; acc[11] += w * ay * by; acc[12] += w * ay * bz;
        acc[13] += w * az * bx; acc[14] += w * az * by; acc[15] += w * az * bz;
    }
    __shared__ double sh[256];
    __shared__ double res[16];
    for (int q = 0; q < 16; q++) {
        sh[tid] = acc[q];
        __syncthreads();
        for (int off = 128; off > 0; off >>= 1) {
            if (tid < off) sh[tid] += sh[tid + off];
            __syncthreads();
        }
        if (tid == 0) res[q] = sh[0];
        __syncthreads();
    }
    if (tid != 0) return;

    double W2 = res[0] + 1e-6;
    double ca[3], cb[3];
#pragma unroll
    for (int i = 0; i < 3; i++) {
        ca[i] = res[1 + i] / W2;
        cb[i] = res[4 + i] / W2;
    }
    double sfac = 2.0 - res[0] / W2;
    double Cv[3][3];
#pragma unroll
    for (int i = 0; i < 3; i++)
#pragma unroll
        for (int j = 0; j < 3; j++)
            Cv[i][j] = res[7 + i * 3 + j] / W2 - sfac * ca[i] * cb[j];

    double A[3][3];
#pragma unroll
    for (int i = 0; i < 3; i++)
#pragma unroll
        for (int j = 0; j < 3; j++)
            A[i][j] = Cv[0][i] * Cv[0][j] + Cv[1][i] * Cv[1][j] + Cv[2][i] * Cv[2][j];
    double V[3][3] = {{1, 0, 0}, {0, 1, 0}, {0, 0, 1}};
    const int PP[3] = {0, 0, 1}, QQ[3] = {1, 2, 2};
    for (int sweep = 0; sweep < 30; sweep++) {
        double off = fabs(A[0][1]) + fabs(A[0][2]) + fabs(A[1][2]);
        if (off < 1e-28) break;
        for (int r = 0; r < 3; r++) {
            int p = PP[r], q = QQ[r];
            double apq = A[p][q];
            if (apq == 0.0) continue;
            double theta = (A[q][q] - A[p][p]) / (2.0 * apq);
            double t = ((theta >= 0.0) ? 1.0 : -1.0) / (fabs(theta) + sqrt(1.0 + theta * theta));
            double c = 1.0 / sqrt(1.0 + t * t);
            double s = t * c;
            for (int k = 0; k < 3; k++) {
                double akp = A[k][p], akq = A[k][q];
                A[k][p] = c * akp - s * akq;
                A[k][q] = s * akp + c * akq;
            }
            for (int k = 0; k < 3; k++) {
                double apk = A[p][k], aqk = A[q][k];
                A[p][k] = c * apk - s * aqk;
                A[q][k] = s * apk + c * aqk;
            }
            for (int k = 0; k < 3; k++) {
                double vkp = V[k][p], vkq = V[k][q];
                V[k][p] = c * vkp - s * vkq;
                V[k][q] = s * vkp + c * vkq;
            }
        }
    }
    double d[3] = {A[0][0], A[1][1], A[2][2]};
    for (int i = 0; i < 2; i++)
        for (int j = i + 1; j < 3; j++)
            if (d[j] > d[i]) {
                double tmp = d[i]; d[i] = d[j]; d[j] = tmp;
                for (int k = 0; k < 3; k++) {
                    double tv = V[k][i]; V[k][i] = V[k][j]; V[k][j] = tv;
                }
            }
    double U[3][3];
    double nrm[3];
#pragma unroll
    for (int k = 0; k < 3; k++) {
        double u0 = Cv[0][0] * V[0][k] + Cv[0][1] * V[1][k] + Cv[0][2] * V[2][k];
        double u1 = Cv[1][0] * V[0][k] + Cv[1][1] * V[1][k] + Cv[1][2] * V[2][k];
        double u2 = Cv[2][0] * V[0][k] + Cv[2][1] * V[1][k] + Cv[2][2] * V[2][k];
        double n = sqrt(u0 * u0 + u1 * u1 + u2 * u2);
        nrm[k] = n;
        if (n > 1e-30) {
            U[0][k] = u0 / n; U[1][k] = u1 / n; U[2][k] = u2 / n;
        } else {
            U[0][k] = 0.0; U[1][k] = 0.0; U[2][k] = 0.0;
        }
    }
    if (nrm[2] <= 1e-12 * fmax(nrm[0], 1e-30)) {
        double cx = U[1][0] * U[2][1] - U[2][0] * U[1][1];
        double cy = U[2][0] * U[0][1] - U[0][0] * U[2][1];
        double cz = U[0][0] * U[1][1] - U[1][0] * U[0][1];
        double n = sqrt(cx * cx + cy * cy + cz * cz);
        if (n > 1e-30) { U[0][2] = cx / n; U[1][2] = cy / n; U[2][2] = cz / n; }
    }
    double R[3][3];
#pragma unroll
    for (int i = 0; i < 3; i++)
#pragma unroll
        for (int j = 0; j < 3; j++)
            R[i][j] = V[i][0] * U[j][0] + V[i][1] * U[j][1] + V[i][2] * U[j][2];
    double det = R[0][0] * (R[1][1] * R[2][2] - R[1][2] * R[2][1])
               - R[0][1] * (R[1][0] * R[2][2] - R[1][2] * R[2][0])
               + R[0][2] * (R[1][0] * R[2][1] - R[1][1] * R[2][0]);
    if (!(det > 0.0)) {
#pragma unroll
        for (int i = 0; i < 3; i++)
#pragma unroll
            for (int j = 0; j < 3; j++)
                R[i][j] -= 2.0 * V[i][2] * U[j][2];
    }
    double tr[3];
#pragma unroll
    for (int i = 0; i < 3; i++)
        tr[i] = cb[i] - (R[i][0] * ca[0] + R[i][1] * ca[1] + R[i][2] * ca[2]);

#pragma unroll
    for (int i = 0; i < 3; i++)
#pragma unroll
        for (int j = 0; j < 3; j++)
            out[b * 9 + i * 3 + j] = (float)R[i][j];
#pragma unroll
    for (int i = 0; i < 3; i++) out[144 + b * 3 + i] = (float)tr[i];
}

// ---------------- launch ----------------
extern "C" void kernel_launch(void* const* d_in, const int* in_sizes, int n_in,
                              void* d_out, int out_size) {
    (void)in_sizes; (void)n_in; (void)out_size;
    const float* se  = (const float*)d_in[0];
    const float* te  = (const float*)d_in[1];
    const float* src = (const float*)d_in[2];
    const float* tgt = (const float*)d_in[3];
    const float* rho = (const float*)d_in[4];
    float* out = (float*)d_out;
    float* Kmat = out + 192;

    static int attr_done = 0;
    if (!attr_done) {
        cudaFuncSetAttribute(gemm_fused_kernel, cudaFuncAttributeMaxDynamicSharedMemorySize,
                             GEMM_SMEM_BYTES);
        cudaFuncSetAttribute(fused_iter_kernel, cudaFuncAttributeMaxDynamicSharedMemorySize,
                             FUSED_SMEM_BYTES);
        attr_done = 1;
    }

    __nv_bfloat16 *bh, *bl;
    cudaGetSymbolAddress((void**)&bh, g_BH);
    cudaGetSymbolAddress((void**)&bl, g_BL);
    split_transpose_kernel<<<dim3(N_ / 32, D_ / 32, B_), 256>>>(te, bh, bl);
    gemm_fused_kernel<<<dim3(M_ / 64, B_), 256, GEMM_SMEM_BYTES>>>(se, rho);
    initgR_kernel<<<B_, 256>>>();
    colsum_kernel<<<B_ * SLICES_, 256>>>();
    colscale_part_kernel<<<B_ * 8, 256>>>(1);
    for (int it = 0; it < 4; it++) {
        fused_iter_kernel<<<B_ * SLICES_, 256, FUSED_SMEM_BYTES>>>();
        colscale_part_kernel<<<B_ * 8, 256>>>(0);
    }
    final_kernel<<<B_ * M_ / 8, 256>>>(Kmat, tgt);
    rigid_kernel<<<B_, 256>>>(src, out);
}

// round 14
// speedup vs baseline: 1.9759x; 1.0723x over previous
#include <cuda_runtime.h>
#include <cuda_bf16.h>
#include <math.h>
#include <stdint.h>

#define B_ 16
#define D_ 256
#define M_ 2048
#define N_ 2048
#define SLICES_ 64
#define ROWS_PER_SLICE_ 32

// ---------------- scratch (static device arrays; no allocation) ----------------
__device__ float g_R[B_ * M_];
__device__ float g_C[B_ * N_];
__device__ float g_rowtmp[B_ * M_];
__device__ float g_srow[B_ * M_];
__device__ float g_zrow[B_ * M_];
__device__ float g_colpart[B_ * SLICES_ * N_];
__device__ float g_g[B_];
__device__ float g_tppart[B_ * 8];
__device__ unsigned g_cnt[B_];
__device__ float g_w[B_ * M_];
__device__ float g_numer[B_ * M_ * 3];
__device__ __nv_bfloat16 g_AH[B_ * M_ * D_];
__device__ __nv_bfloat16 g_AL[B_ * M_ * D_];
__device__ __nv_bfloat16 g_BH[B_ * N_ * D_];
__device__ __nv_bfloat16 g_BL[B_ * N_ * D_];
__device__ __nv_bfloat16 g_KbH[(size_t)B_ * M_ * N_];
__device__ __nv_bfloat16 g_KbL[(size_t)B_ * M_ * N_];

// ---------------- helpers ----------------
__device__ __forceinline__ uint32_t smem_u32(const void* p) {
    uint32_t a;
    asm("{ .reg .u64 t; cvta.to.shared.u64 t, %1; cvt.u32.u64 %0, t; }" : "=r"(a) : "l"(p));
    return a;
}

#define LDSM_X4(r0, r1, r2, r3, addr) \
    asm volatile("ldmatrix.sync.aligned.m8n8.x4.shared.b16 {%0,%1,%2,%3}, [%4];" \
                 : "=r"(r0), "=r"(r1), "=r"(r2), "=r"(r3) : "r"(addr))

#define MMA16816(d, a, bq) \
    asm volatile( \
        "mma.sync.aligned.m16n8k16.row.col.f32.bf16.bf16.f32 " \
        "{%0,%1,%2,%3}, {%4,%5,%6,%7}, {%8,%9}, {%0,%1,%2,%3};" \
        : "+f"((d)[0]), "+f"((d)[1]), "+f"((d)[2]), "+f"((d)[3]) \
        : "r"((a)[0]), "r"((a)[1]), "r"((a)[2]), "r"((a)[3]), \
          "r"((bq)[0]), "r"((bq)[1]))

#define CP_ASYNC16(sa, ga) \
    asm volatile("cp.async.cg.shared.global [%0], [%1], 16;" :: "r"(sa), "l"(ga))

#define PACK_BF16X2(r, lo, hi) \
    asm("cvt.rn.bf16x2.f32 %0, %1, %2;" : "=r"(r) : "f"(hi), "f"(lo))

__device__ __forceinline__ float bf_lo(uint32_t x) { return __uint_as_float(x << 16); }
__device__ __forceinline__ float bf_hi(uint32_t x) { return __uint_as_float(x & 0xffff0000u); }

// ---------------- block reductions ----------------
__device__ __forceinline__ float blockReduceSum(float v) {
    __shared__ float sh[33];
    int lane = threadIdx.x & 31, w = threadIdx.x >> 5;
#pragma unroll
    for (int o = 16; o; o >>= 1) v += __shfl_down_sync(0xffffffffu, v, o);
    if (lane == 0) sh[w] = v;
    __syncthreads();
    if (w == 0) {
        v = (lane < (int)(blockDim.x >> 5)) ? sh[lane] : 0.f;
#pragma unroll
        for (int o = 16; o; o >>= 1) v += __shfl_down_sync(0xffffffffu, v, o);
        if (lane == 0) sh[32] = v;
    }
    __syncthreads();
    float r = sh[32];
    __syncthreads();
    return r;
}

// ---------------- transpose + bf16 hi/lo split (optionally zero row stats) ----------------
__global__ __launch_bounds__(256) void split_transpose_kernel(const float* __restrict__ X,
                                                              __nv_bfloat16* __restrict__ H,
                                                              __nv_bfloat16* __restrict__ L,
                                                              int zero_stats) {
    __shared__ float t[32][33];
    int b = blockIdx.z;
    int m0 = blockIdx.x * 32, d0 = blockIdx.y * 32;
    if (zero_stats && blockIdx.y == 0 && threadIdx.x < 32) {
        g_srow[b * M_ + m0 + threadIdx.x] = 0.f;
        g_zrow[b * M_ + m0 + threadIdx.x] = 0.f;
    }
    const float* Xb = X + (size_t)b * D_ * M_;
    int tx = threadIdx.x & 31, ty = threadIdx.x >> 5;
#pragma unroll
    for (int i = 0; i < 4; i++) {
        int d = d0 + ty + i * 8;
        t[ty + i * 8][tx] = Xb[(size_t)d * M_ + m0 + tx];
    }
    __syncthreads();
#pragma unroll
    for (int i = 0; i < 4; i++) {
        int m = m0 + ty + i * 8;
        float v = t[tx][ty + i * 8];
        __nv_bfloat16 h = __float2bfloat16(v);
        __nv_bfloat16 l = __float2bfloat16(v - __bfloat162float(h));
        size_t o = ((size_t)b * M_ + m) * D_ + d0 + tx;
        H[o] = h;
        L[o] = l;
    }
}

// ---------------- tile GEMM (128x128, grid 4096) + fused exp/bf16 epilogue ----------------
#define SMS_ 40
#define MAT_B (128 * SMS_ * 2)       // 10240 bytes per matrix per stage
#define STAGE_B (4 * MAT_B)          // 40960 (Ah, Al, Bh, Bl)
#define GEMM_SMEM_BYTES (2 * STAGE_B)

__global__ __launch_bounds__(256, 2) void gemm_tile_kernel(const float* __restrict__ rho_p) {
    extern __shared__ __align__(16) char smem[];
    uint32_t smb = smem_u32(smem);
    int tid = threadIdx.x, wid = tid >> 5, lane = tid & 31;
    int b = blockIdx.z, m0 = blockIdx.y * 128, n0 = blockIdx.x * 128;
    int wr = wid >> 2, wc = wid & 3;
    int gid = lane >> 2, tig = lane & 3;

    float rho = fmaxf(rho_p[0], 1e-8f);
    float invr = 1.0f / rho;
    bool rho1 = (rho == 1.0f);

    const __nv_bfloat16* Ah = g_AH + ((size_t)b * M_ + m0) * D_;
    const __nv_bfloat16* Al = g_AL + ((size_t)b * M_ + m0) * D_;
    const __nv_bfloat16* Bh = g_BH + ((size_t)b * N_ + n0) * D_;
    const __nv_bfloat16* Bl = g_BL + ((size_t)b * N_ + n0) * D_;

    float acc[4][4][4];
#pragma unroll
    for (int mi = 0; mi < 4; mi++)
#pragma unroll
        for (int ni = 0; ni < 4; ni++)
#pragma unroll
            for (int r = 0; r < 4; r++) acc[mi][ni][r] = 0.f;

    // cp.async mapping: 512 16B vectors per matrix, 2 per thread
    int i0 = tid * 2, i1 = tid * 2 + 1;
    int r0_ = i0 >> 2, s0_ = i0 & 3;
    int r1_ = i1 >> 2, s1_ = i1 & 3;
    uint32_t d00 = (uint32_t)(r0_ * SMS_ + s0_ * 8) * 2;
    uint32_t d01 = (uint32_t)(r1_ * SMS_ + s1_ * 8) * 2;

    int a_row = (lane & 15), a_colh = (lane >> 4) * 8;
    int b_tile = lane >> 3, b_r8 = lane & 7;
    int b_n = ((b_tile >> 1) * 8) + b_r8;
    int b_k = (b_tile & 1) * 8;

    auto load_chunk = [&](int c) {
        uint32_t base = smb + (uint32_t)(c & 1) * STAGE_B;
        size_t g00 = (size_t)r0_ * D_ + c * 32 + s0_ * 8;
        size_t g01 = (size_t)r1_ * D_ + c * 32 + s1_ * 8;
        CP_ASYNC16(base + d00, Ah + g00);
        CP_ASYNC16(base + d01, Ah + g01);
        CP_ASYNC16(base + MAT_B + d00, Al + g00);
        CP_ASYNC16(base + MAT_B + d01, Al + g01);
        CP_ASYNC16(base + 2 * MAT_B + d00, Bh + g00);
        CP_ASYNC16(base + 2 * MAT_B + d01, Bh + g01);
        CP_ASYNC16(base + 3 * MAT_B + d00, Bl + g00);
        CP_ASYNC16(base + 3 * MAT_B + d01, Bl + g01);
        asm volatile("cp.async.commit_group;" ::: "memory");
    };

    load_chunk(0);

    for (int c = 0; c < 8; c++) {
        asm volatile("cp.async.wait_group 0;" ::: "memory");
        __syncthreads();
        if (c < 7) load_chunk(c + 1);

        uint32_t base = smb + (uint32_t)(c & 1) * STAGE_B;
        uint32_t sAh_u = base, sAl_u = base + MAT_B;
        uint32_t sBh_u = base + 2 * MAT_B, sBl_u = base + 3 * MAT_B;

#pragma unroll
        for (int ks = 0; ks < 2; ks++) {
            uint32_t bh[4][2], bl[4][2];
#pragma unroll
            for (int np = 0; np < 2; np++) {
                uint32_t off = (uint32_t)((wc * 32 + np * 16 + b_n) * SMS_ + ks * 16 + b_k) * 2;
                LDSM_X4(bh[np * 2][0], bh[np * 2][1], bh[np * 2 + 1][0], bh[np * 2 + 1][1],
                        sBh_u + off);
                LDSM_X4(bl[np * 2][0], bl[np * 2][1], bl[np * 2 + 1][0], bl[np * 2 + 1][1],
                        sBl_u + off);
            }
#pragma unroll
            for (int mi = 0; mi < 4; mi++) {
                uint32_t ah[4], al[4];
                uint32_t aoff = (uint32_t)((wr * 64 + mi * 16 + a_row) * SMS_ + ks * 16 + a_colh) * 2;
                LDSM_X4(ah[0], ah[1], ah[2], ah[3], sAh_u + aoff);
                LDSM_X4(al[0], al[1], al[2], al[3], sAl_u + aoff);
#pragma unroll
                for (int ni = 0; ni < 4; ni++) {
                    MMA16816(acc[mi][ni], ah, bh[ni]);
                    MMA16816(acc[mi][ni], ah, bl[ni]);
                    MMA16816(acc[mi][ni], al, bh[ni]);
                }
            }
        }
        __syncthreads();
    }

    // ---- fused epilogue: e = exp(v/rho), bf16 hi/lo stores, row-stat atomics ----
    __nv_bfloat16* KHb = g_KbH + (size_t)b * M_ * N_;
    __nv_bfloat16* KLb = g_KbL + (size_t)b * M_ * N_;
    float s_part[4][2], z_part[4][2];
#pragma unroll
    for (int mi = 0; mi < 4; mi++) {
        s_part[mi][0] = s_part[mi][1] = 0.f;
        z_part[mi][0] = z_part[mi][1] = 0.f;
    }
#pragma unroll
    for (int mi = 0; mi < 4; mi++) {
        int row0 = m0 + wr * 64 + mi * 16 + gid;
#pragma unroll
        for (int ni = 0; ni < 4; ni++) {
            float v00 = acc[mi][ni][0] * 0.0625f;
            float v01 = acc[mi][ni][1] * 0.0625f;
            float v10 = acc[mi][ni][2] * 0.0625f;
            float v11 = acc[mi][ni][3] * 0.0625f;
            float e00 = __expf(fminf(fmaxf(v00 * invr, -60.f), 60.f));
            float e01 = __expf(fminf(fmaxf(v01 * invr, -60.f), 60.f));
            float e10 = __expf(fminf(fmaxf(v10 * invr, -60.f), 60.f));
            float e11 = __expf(fminf(fmaxf(v11 * invr, -60.f), 60.f));
            float z00, z01, z10, z11;
            if (rho1) {
                z00 = e00; z01 = e01; z10 = e10; z11 = e11;
            } else {
                z00 = __expf(fminf(fmaxf(v00, -60.f), 60.f));
                z01 = __expf(fminf(fmaxf(v01, -60.f), 60.f));
                z10 = __expf(fminf(fmaxf(v10, -60.f), 60.f));
                z11 = __expf(fminf(fmaxf(v11, -60.f), 60.f));
            }
            int col = n0 + wc * 32 + ni * 8 + tig * 2;
            uint32_t ph0, ph1;
            PACK_BF16X2(ph0, e00, e01);
            PACK_BF16X2(ph1, e10, e11);
            float l00 = e00 - bf_lo(ph0), l01 = e01 - bf_hi(ph0);
            float l10 = e10 - bf_lo(ph1), l11 = e11 - bf_hi(ph1);
            uint32_t pl0, pl1;
            PACK_BF16X2(pl0, l00, l01);
            PACK_BF16X2(pl1, l10, l11);
            *(uint32_t*)(KHb + (size_t)row0 * N_ + col) = ph0;
            *(uint32_t*)(KHb + (size_t)(row0 + 8) * N_ + col) = ph1;
            *(uint32_t*)(KLb + (size_t)row0 * N_ + col) = pl0;
            *(uint32_t*)(KLb + (size_t)(row0 + 8) * N_ + col) = pl1;
            s_part[mi][0] += e00 + e01;
            s_part[mi][1] += e10 + e11;
            z_part[mi][0] += z00 + z01;
            z_part[mi][1] += z10 + z11;
        }
    }
#pragma unroll
    for (int mi = 0; mi < 4; mi++)
#pragma unroll
        for (int h = 0; h < 2; h++) {
            float s = s_part[mi][h];
            float z = z_part[mi][h];
            s += __shfl_down_sync(0xffffffffu, s, 1);
            s += __shfl_down_sync(0xffffffffu, s, 2);
            z += __shfl_down_sync(0xffffffffu, z, 1);
            z += __shfl_down_sync(0xffffffffu, z, 2);
            if (tig == 0) {
                int row = m0 + wr * 64 + mi * 16 + h * 8 + gid;
                atomicAdd(&g_srow[b * M_ + row], s);
                atomicAdd(&g_zrow[b * M_ + row], z);
            }
        }
}

// ---------------- merged: cr from z, initial g, iteration-1 row scaling ----------------
__global__ __launch_bounds__(256) void initgR_kernel(const float* __restrict__ rho_p) {
    int b = blockIdx.x;
    float rho = fmaxf(rho_p[0], 1e-8f);
    float invr = 1.0f / rho;
    float part = 0.f;
    for (int i = threadIdx.x; i < M_; i += 256) {
        int gi = b * M_ + i;
        float s = g_srow[gi];
        float z = g_zrow[gi];
        float cr = __expf(-invr * __logf(fmaxf(z, 1e-30f)));
        float w = cr * s;
        g_R[gi] = cr;
        g_rowtmp[gi] = w;
        part += w;
    }
    part = blockReduceSum(part);
    float g = 1.0f / fmaxf(part, 1e-8f);
    if (threadIdx.x == 0) g_g[b] = g;
    for (int i = threadIdx.x; i < M_; i += 256) {
        int gi = b * M_ + i;
        float rowsum = g * g_rowtmp[gi];
        g_R[gi] *= fminf((1.0f / 2048.0f) / fmaxf(rowsum, 1e-8f), 1.0f);
    }
}

// ---------------- iteration 1 column partial sums (bf16-hi reads) ----------------
__global__ __launch_bounds__(256) void colsum_kernel() {
    int b = blockIdx.x >> 6;
    int slice = blockIdx.x & 63;
    int i0 = slice * ROWS_PER_SLICE_;
    int tid = threadIdx.x;
    const uint32_t* base = (const uint32_t*)(g_KbH + ((size_t)(b << 11) + i0) * N_);
    float acc[8] = {0, 0, 0, 0, 0, 0, 0, 0};
    for (int r = 0; r < ROWS_PER_SLICE_; r++) {
        float Rv = g_R[(b << 11) + i0 + r];
        const uint32_t* P = base + (size_t)r * (N_ / 2);
#pragma unroll
        for (int q = 0; q < 4; q++) {
            uint32_t x = P[tid + q * 256];
            acc[2 * q] += bf_lo(x) * Rv;
            acc[2 * q + 1] += bf_hi(x) * Rv;
        }
    }
    float* outp = g_colpart + (size_t)blockIdx.x * N_;
#pragma unroll
    for (int q = 0; q < 4; q++) {
        float2 v = {acc[2 * q], acc[2 * q + 1]};
        *(float2*)(outp + 2 * (tid + q * 256)) = v;
    }
}

// ---------------- iterations 2-5: fused rowscale + colsum ----------------
#define FUSED_SMEM_BYTES (8 * N_ * 4)
__global__ __launch_bounds__(256) void fused_iter_kernel() {
    extern __shared__ float ssum[];
    int b = blockIdx.x >> 6;
    int slice = blockIdx.x & 63;
    int i0 = slice * ROWS_PER_SLICE_;
    int wid = threadIdx.x >> 5, lane = threadIdx.x & 31;
    const float* Cp = g_C + (b << 11);
    float g = g_g[b];
    float acc[64];
#pragma unroll
    for (int q = 0; q < 64; q++) acc[q] = 0.f;

    const uint32_t* Kb32 = (const uint32_t*)(g_KbH + (size_t)(b << 11) * N_);

    for (int r = 0; r < 4; r++) {
        int rowl = i0 + wid * 4 + r;
        int row = (b << 11) + rowl;
        const uint32_t* P = Kb32 + (size_t)rowl * (N_ / 2);
        uint32_t x[32];
#pragma unroll
        for (int q = 0; q < 32; q++) x[q] = P[lane + 32 * q];
        float d = 0.f;
#pragma unroll
        for (int q = 0; q < 32; q++) {
            float2 cv = *(const float2*)(Cp + 2 * (lane + 32 * q));
            d += bf_lo(x[q]) * cv.x + bf_hi(x[q]) * cv.y;
        }
#pragma unroll
        for (int o = 16; o; o >>= 1) d += __shfl_xor_sync(0xffffffffu, d, o);
        float Rold = g_R[row];
        float rowsum = g * Rold * d;
        float Rnew = Rold * fminf((1.0f / 2048.0f) / fmaxf(rowsum, 1e-8f), 1.0f);
        if (lane == 0) g_R[row] = Rnew;
#pragma unroll
        for (int q = 0; q < 32; q++) {
            acc[2 * q] += bf_lo(x[q]) * Rnew;
            acc[2 * q + 1] += bf_hi(x[q]) * Rnew;
        }
    }
    float* myrow = ssum + wid * N_;
#pragma unroll
    for (int q = 0; q < 32; q++) {
        float2 v = {acc[2 * q], acc[2 * q + 1]};
        *(float2*)(myrow + 2 * (lane + 32 * q)) = v;
    }
    __syncthreads();
    float* outp = g_colpart + (size_t)blockIdx.x * N_;
    for (int j = threadIdx.x; j < N_; j += 256) {
        float t = 0.f;
#pragma unroll
        for (int w = 0; w < 8; w++) t += ssum[w * N_ + j];
        outp[j] = t;
    }
}

// ---------------- col scaling (parallel) + folded g update ----------------
__global__ __launch_bounds__(256) void colscale_part_kernel(int first) {
    int b = blockIdx.x >> 3;
    int part = blockIdx.x & 7;
    int j = part * 256 + threadIdx.x;
    float g = g_g[b];
    float acc = 0.f;
    const float* cp = g_colpart + (size_t)(b << 6) * N_ + j;
#pragma unroll 8
    for (int s = 0; s < SLICES_; s++) acc += cp[(size_t)s * N_];
    int cj = (b << 11) + j;
    float base = first ? 1.0f : g_C[cj];
    float colsum = g * base * acc;
    float cc = fminf((1.0f / 2048.0f) / fmaxf(colsum, 1e-8f), 1.0f);
    g_C[cj] = base * cc;
    float tp = blockReduceSum(colsum * cc);
    if (threadIdx.x == 0) {
        g_tppart[blockIdx.x] = tp;
        __threadfence();
        unsigned old = atomicAdd(&g_cnt[b], 1u);
        if (old == 7u) {
            float t = 0.f;
#pragma unroll
            for (int p = 0; p < 8; p++) t += g_tppart[b * 8 + p];
            g_g[b] = g * (1.0f / fmaxf(t, 1e-8f));
            g_cnt[b] = 0u;
        }
    }
}

// ---------------- final: warp-per-row, hi+lo reconstruction ----------------
__global__ __launch_bounds__(256) void final_kernel(float* __restrict__ K,
                                                    const float* __restrict__ tgt) {
    int blk = blockIdx.x;
    int b = blk >> 8;
    int rowl = ((blk & 255) << 3) + (threadIdx.x >> 5);
    int lane = threadIdx.x & 31;
    int row = (b << 11) + rowl;
    const uint2* H = (const uint2*)(g_KbH + (size_t)row * N_);
    const uint2* L = (const uint2*)(g_KbL + (size_t)row * N_);
    const float4* C4 = (const float4*)(g_C + (b << 11));
    const float4* t04 = (const float4*)(tgt + (size_t)b * 3 * N_);
    const float4* t14 = t04 + N_ / 4;
    const float4* t24 = t04 + 2 * (N_ / 4);
    float* P = K + (size_t)row * N_;
    float gR = g_g[b] * g_R[row];
    float s = 0.f, sx = 0.f, sy = 0.f, sz = 0.f;
#pragma unroll
    for (int q = 0; q < 16; q++) {
        int i2 = lane + 32 * q;
        uint2 h = H[i2];
        uint2 l = L[i2];
        float4 c = C4[i2];
        float v0 = (bf_lo(h.x) + bf_lo(l.x)) * gR * c.x;
        float v1 = (bf_hi(h.x) + bf_hi(l.x)) * gR * c.y;
        float v2 = (bf_lo(h.y) + bf_lo(l.y)) * gR * c.z;
        float v3 = (bf_hi(h.y) + bf_hi(l.y)) * gR * c.w;
        float4 o = {v0, v1, v2, v3};
        *(float4*)(P + i2 * 4) = o;
        float4 a0 = t04[i2], a1 = t14[i2], a2 = t24[i2];
        s += v0 + v1 + v2 + v3;
        sx += v0 * a0.x + v1 * a0.y + v2 * a0.z + v3 * a0.w;
        sy += v0 * a1.x + v1 * a1.y + v2 * a1.z + v3 * a1.w;
        sz += v0 * a2.x + v1 * a2.y + v2 * a2.z + v3 * a2.w;
    }
#pragma unroll
    for (int o = 16; o; o >>= 1) {
        s += __shfl_xor_sync(0xffffffffu, s, o);
        sx += __shfl_xor_sync(0xffffffffu, sx, o);
        sy += __shfl_xor_sync(0xffffffffu, sy, o);
        sz += __shfl_xor_sync(0xffffffffu, sz, o);
    }
    if (lane == 0) {
        g_w[row] = s;
        g_numer[row * 3 + 0] = sx;
        g_numer[row * 3 + 1] = sy;
        g_numer[row * 3 + 2] = sz;
    }
}

// ---------------- rigid transform (fp64 Kabsch + Jacobi SVD) ----------------
__global__ __launch_bounds__(256) void rigid_kernel(const float* __restrict__ src,
                                                    float* __restrict__ out) {
    int b = blockIdx.x;
    int tid = threadIdx.x;
    const float* s0 = src + (size_t)b * 3 * M_;
    const float* s1 = s0 + M_;
    const float* s2 = s0 + 2 * M_;
    double acc[16];
#pragma unroll
    for (int q = 0; q < 16; q++) acc[q] = 0.0;
    for (int i = tid; i < M_; i += 256) {
        int row = (b << 11) + i;
        double w = (double)g_w[row];
        double dn = w + 1e-6;
        double bx = (double)g_numer[row * 3 + 0] / dn;
        double by = (double)g_numer[row * 3 + 1] / dn;
        double bz = (double)g_numer[row * 3 + 2] / dn;
        double ax = (double)s0[i], ay = (double)s1[i], az = (double)s2[i];
        acc[0] += w;
        acc[1] += w * ax; acc[2] += w * ay; acc[3] += w * az;
        acc[4] += w * bx; acc[5] += w * by; acc[6] += w * bz;
        acc[7]  += w * ax * bx; acc[8]  += w * ax * by; acc[9]  += w * ax * bz;
        acc[10] += w * ay * bx; acc[11] += w * ay * by; acc[12] += w * ay * bz;
        acc[13] += w * az * bx; acc[14] += w * az * by; acc[15] += w * az * bz;
    }
    __shared__ double sh[256];
    __shared__ double res[16];
    for (int q = 0; q < 16; q++) {
        sh[tid] = acc[q];
        __syncthreads();
        for (int off = 128; off > 0; off >>= 1) {
            if (tid < off) sh[tid] += sh[tid + off];
            __syncthreads();
        }
        if (tid == 0) res[q] = sh[0];
        __syncthreads();
    }
    if (tid != 0) return;

    double W2 = res[0] + 1e-6;
    double ca[3], cb[3];
#pragma unroll
    for (int i = 0; i < 3; i++) {
        ca[i] = res[1 + i] / W2;
        cb[i] = res[4 + i] / W2;
    }
    double sfac = 2.0 - res[0] / W2;
    double Cv[3][3];
#pragma unroll
    for (int i = 0; i < 3; i++)
#pragma unroll
        for (int j = 0; j < 3; j++)
            Cv[i][j] = res[7 + i * 3 + j] / W2 - sfac * ca[i] * cb[j];

    double A[3][3];
#pragma unroll
    for (int i = 0; i < 3; i++)
#pragma unroll
        for (int j = 0; j < 3; j++)
            A[i][j] = Cv[0][i] * Cv[0][j] + Cv[1][i] * Cv[1][j] + Cv[2][i] * Cv[2][j];
    double V[3][3] = {{1, 0, 0}, {0, 1, 0}, {0, 0, 1}};
    const int PP[3] = {0, 0, 1}, QQ[3] = {1, 2, 2};
    for (int sweep = 0; sweep < 30; sweep++) {
        double off = fabs(A[0][1]) + fabs(A[0][2]) + fabs(A[1][2]);
        if (off < 1e-28) break;
        for (int r = 0; r < 3; r++) {
            int p = PP[r], q = QQ[r];
            double apq = A[p][q];
            if (apq == 0.0) continue;
            double theta = (A[q][q] - A[p][p]) / (2.0 * apq);
            double t = ((theta >= 0.0) ? 1.0 : -1.0) / (fabs(theta) + sqrt(1.0 + theta * theta));
            double c = 1.0 / sqrt(1.0 + t * t);
            double s = t * c;
            for (int k = 0; k < 3; k++) {
                double akp = A[k][p], akq = A[k][q];
                A[k][p] = c * akp - s * akq;
                A[k][q] = s * akp + c * akq;
            }
            for (int k = 0; k < 3; k++) {
                double apk = A[p][k], aqk = A[q][k];
                A[p][k] = c * apk - s * aqk;
                A[q][k] = s * apk + c * aqk;
            }
            for (int k = 0; k < 3; k++) {
                double vkp = V[k][p], vkq = V[k][q];
                V[k][p] = c * vkp - s * vkq;
                V[k][q] = s * vkp + c * vkq;
            }
        }
    }
    double d[3] = {A[0][0], A[1][1], A[2][2]};
    for (int i = 0; i < 2; i++)
        for (int j = i + 1; j < 3; j++)
            if (d[j] > d[i]) {
                double tmp = d[i]; d[i] = d[j]; d[j] = tmp;
                for (int k = 0; k < 3; k++) {
                    double tv = V[k][i]; V[k][i] = V[k][j]; V[k][j] = tv;
                }
            }
    double U[3][3];
    double nrm[3];
#pragma unroll
    for (int k = 0; k < 3; k++) {
        double u0 = Cv[0][0] * V[0][k] + Cv[0][1] * V[1][k] + Cv[0][2] * V[2][k];
        double u1 = Cv[1][0] * V[0][k] + Cv[1][1] * V[1][k] + Cv[1][2] * V[2][k];
        double u2 = Cv[2][0] * V[0][k] + Cv[2][1] * V[1][k] + Cv[2][2] * V[2][k];
        double n = sqrt(u0 * u0 + u1 * u1 + u2 * u2);
        nrm[k] = n;
        if (n > 1e-30) {
            U[0][k] = u0 / n; U[1][k] = u1 / n; U[2][k] = u2 / n;
        } else {
            U[0][k] = 0.0; U[1][k] = 0.0; U[2][k] = 0.0;
        }
    }
    if (nrm[2] <= 1e-12 * fmax(nrm[0], 1e-30)) {
        double cx = U[1][0] * U[2][1] - U[2][0] * U[1][1];
        double cy = U[2][0] * U[0][1] - U[0][0] * U[2][1];
        double cz = U[0][0] * U[1][1] - U[1][0] * U[0][1];
        double n = sqrt(cx * cx + cy * cy + cz * cz);
        if (n > 1e-30) { U[0][2] = cx / n; U[1][2] = cy / n; U[2][2] = cz / n; }
    }
    double R[3][3];
#pragma unroll
    for (int i = 0; i < 3; i++)
#pragma unroll
        for (int j = 0; j < 3; j++)
            R[i][j] = V[i][0] * U[j][0] + V[i][1] * U[j][1] + V[i][2] * U[j][2];
    double det = R[0][0] * (R[1][1] * R[2][2] - R[1][2] * R[2][1])
               - R[0][1] * (R[1][0] * R[2][2] - R[1][2] * R[2][0])
               + R[0][2] * (R[1][0] * R[2][1] - R[1][1] * R[2][0]);
    if (!(det > 0.0)) {
#pragma unroll
        for (int i = 0; i < 3; i++)
#pragma unroll
            for (int j = 0; j < 3; j++)
                R[i][j] -= 2.0 * V[i][2] * U[j][2];
    }
    double tr[3];
#pragma unroll
    for (int i = 0; i < 3; i++)
        tr[i] = cb[i] - (R[i][0] * ca[0] + R[i][1] * ca[1] + R[i][2] * ca[2]);

#pragma unroll
    for (int i = 0; i < 3; i++)
#pragma unroll
        for (int j = 0; j < 3; j++)
            out[b * 9 + i * 3 + j] = (float)R[i][j];
#pragma unroll
    for (int i = 0; i < 3; i++) out[144 + b * 3 + i] = (float)tr[i];
}

// ---------------- launch ----------------
extern "C" void kernel_launch(void* const* d_in, const int* in_sizes, int n_in,
                              void* d_out, int out_size) {
    (void)in_sizes; (void)n_in; (void)out_size;
    const float* se  = (const float*)d_in[0];
    const float* te  = (const float*)d_in[1];
    const float* src = (const float*)d_in[2];
    const float* tgt = (const float*)d_in[3];
    const float* rho = (const float*)d_in[4];
    float* out = (float*)d_out;
    float* Kmat = out + 192;

    static int attr_done = 0;
    if (!attr_done) {
        cudaFuncSetAttribute(gemm_tile_kernel, cudaFuncAttributeMaxDynamicSharedMemorySize,
                             GEMM_SMEM_BYTES);
        cudaFuncSetAttribute(fused_iter_kernel, cudaFuncAttributeMaxDynamicSharedMemorySize,
                             FUSED_SMEM_BYTES);
        attr_done = 1;
    }

    __nv_bfloat16 *ah, *al, *bh, *bl;
    cudaGetSymbolAddress((void**)&ah, g_AH);
    cudaGetSymbolAddress((void**)&al, g_AL);
    cudaGetSymbolAddress((void**)&bh, g_BH);
    cudaGetSymbolAddress((void**)&bl, g_BL);
    split_transpose_kernel<<<dim3(M_ / 32, D_ / 32, B_), 256>>>(se, ah, al, 1);
    split_transpose_kernel<<<dim3(N_ / 32, D_ / 32, B_), 256>>>(te, bh, bl, 0);
    gemm_tile_kernel<<<dim3(N_ / 128, M_ / 128, B_), 256, GEMM_SMEM_BYTES>>>(rho);
    initgR_kernel<<<B_, 256>>>(rho);
    colsum_kernel<<<B_ * SLICES_, 256>>>();
    colscale_part_kernel<<<B_ * 8, 256>>>(1);
    for (int it = 0; it < 4; it++) {
        fused_iter_kernel<<<B_ * SLICES_, 256, FUSED_SMEM_BYTES>>>();
        colscale_part_kernel<<<B_ * 8, 256>>>(0);
    }
    final_kernel<<<B_ * M_ / 8, 256>>>(Kmat, tgt);
    rigid_kernel<<<B_, 256>>>(src, out);
}